// round 5
// baseline (speedup 1.0000x reference)
#include <cuda_runtime.h>
#include <math.h>
#include <stdint.h>

#define NF 3000
#define NB 1500
#define KNB 64

// -------------------- global scratch (no runtime allocation allowed) ----------
__device__ float g_p1[NF * 3];
__device__ float g_ff[NF * 9];

__device__ int   g_idxF[NF * KNB];
__device__ int   g_cbF [NF * KNB];
__device__ float g_w8F [NF * KNB * 8];
__device__ int   g_cntF[NF];

__device__ int   g_idxB[NF * KNB];
__device__ int   g_cbB [NF * KNB];
__device__ float g_w8B [NF * KNB * 8];
__device__ int   g_cntB[NF];

__device__ float g_out0[NF * 3 * 96];
__device__ float g_out1[NF * 3 * 64];
__device__ float g_out2[NF * 3 * 64];
__device__ float g_out3[NF * 3 * 64];
__device__ float g_out4[NF * 3 * 3];

__device__ float g_A[(size_t)NF * 3 * 64 * 96];   // GEMM input scratch (max layer1)

// -------------------- helpers -------------------------------------------------
__device__ __forceinline__ float sgnf(float v) {
    return (v > 0.f) ? 1.f : ((v < 0.f) ? -1.f : 0.f);
}

__device__ __forceinline__ uint32_t f2tf32(float f) {
    uint32_t r;
    asm("cvt.rna.tf32.f32 %0, %1;" : "=r"(r) : "f"(f));
    return r;
}

// Per-edge weight computation: offset (dx,dy,dz) = p_in[j] - p_out[n]
__device__ void edge_weights(float dx, float dy, float dz, float* w8, int* cbase)
{
    const float inv_r = 1.f / 3.f;     // radius = EXTENT*0.5 = 3.0
    float x = dx * inv_r, y = dy * inv_r, z = dz * inv_r;
    float sq = (x * x + y * y) + z * z;

    float win = 1.f - sq;
    win = win * win * win;
    win = fminf(fmaxf(win, 0.f), 1.f);

    // _ball_to_cube
    float norm  = sqrtf(fmaxf(sq, 1e-8f));
    float xy_sq = x * x + y * y;
    bool  polar = (1.25f * z * z > xy_sq);
    float s_p = sqrtf(3.f * norm / (norm + fabsf(z) + 1e-8f));
    float s_e = norm / sqrtf(fmaxf(xy_sq, 1e-8f));
    float cx = polar ? x * s_p : x * s_e;
    float cy = polar ? y * s_p : y * s_e;
    float cz = polar ? sgnf(z) * norm : 1.5f * z;

    float nxy = sqrtf(fmaxf(cx * cx + cy * cy, 1e-8f));
    bool  xdom = (fabsf(cy) <= fabsf(cx));
    float sx = (fabsf(cx) > 1e-8f) ? cx : 1.f;
    float sy = (fabsf(cy) > 1e-8f) ? cy : 1.f;
    const float FOPI = 1.27323954473516268615f;  // 4/pi
    float bx1 = sgnf(cx) * nxy;
    float by1 = bx1 * FOPI * atanf(cy / sx);
    float by2 = sgnf(cy) * nxy;
    float bx2 = by2 * FOPI * atanf(cx / sy);
    float bx = xdom ? bx1 : bx2;
    float by = xdom ? by1 : by2;
    if (cx * cx + cy * cy < 1e-8f) { bx = 0.f; by = 0.f; }
    float bz = cz;
    if (sq < 1e-8f) { bx = 0.f; by = 0.f; bz = 0.f; }

    float bb[3] = {bx, by, bz};
    float f[3];
    int   c0[3];
#pragma unroll
    for (int ax = 0; ax < 3; ax++) {
        float co = (bb[ax] * 0.5f + 0.5f) * 3.f;       // (KS-1)=3
        co = fminf(fmaxf(co, 0.f), 3.f);
        int ci = (int)floorf(co);
        ci = min(max(ci, 0), 2);
        c0[ax] = ci;
        f[ax] = co - (float)ci;
    }
    *cbase = (c0[0] * 4 + c0[1]) * 4 + c0[2];
#pragma unroll
    for (int r = 0; r < 8; r++) {
        int i = (r >> 2) & 1, j = (r >> 1) & 1, l = r & 1;
        float w = (i ? f[0] : 1.f - f[0]) * (j ? f[1] : 1.f - f[1]) * (l ? f[2] : 1.f - f[2]);
        w8[r] = w * win;
    }
}

__device__ __forceinline__ int corner_cell(int cb, int r) {
    return cb + ((r >> 2) & 1) * 16 + ((r >> 1) & 1) * 4 + (r & 1);
}

// -------------------- kernel 1: prep -----------------------------------------
__global__ void prep_kernel(const float* __restrict__ p0, const float* __restrict__ v0,
                            const float* __restrict__ a, const float* __restrict__ other,
                            const float* __restrict__ v0e)
{
    int n = blockIdx.x * blockDim.x + threadIdx.x;
    if (n >= NF) return;
#pragma unroll
    for (int j = 0; j < 3; j++) {
        float v0v = v0[n * 3 + j], av = a[n * 3 + j];
        float v1 = v0v + 0.1f * av;
        float p1 = p0[n * 3 + j] + 0.1f * (v0v + v1) * 0.5f;
        g_p1[n * 3 + j] = p1;
        g_ff[n * 9 + 0 + j] = v1;                // s=0 : v1
        g_ff[n * 9 + 3 + j] = other[n * 3 + j];  // s=1 : other_feats
        g_ff[n * 9 + 6 + j] = v0e[n * 3 + j];    // s=2 : v0_enc
    }
}

// -------------------- kernel 2: neighbor build (fluid or box) -----------------
__global__ void nbr_kernel(const float* __restrict__ pts, int npts,
                           const float* __restrict__ mask, int self_exclude,
                           int* __restrict__ idx_out, int* __restrict__ cb_out,
                           float* __restrict__ w8_out, int* __restrict__ cnt_out)
{
    int n = blockIdx.x;
    __shared__ float sd2[512];
    __shared__ int   sidx[512];
    __shared__ int   scnt;
    float qx = g_p1[n * 3], qy = g_p1[n * 3 + 1], qz = g_p1[n * 3 + 2];
    if (threadIdx.x == 0) scnt = 0;
    __syncthreads();

    for (int j = threadIdx.x; j < npts; j += blockDim.x) {
        if (self_exclude && j == n) continue;
        if (mask && mask[j] <= 0.f) continue;
        float dx = pts[j * 3] - qx, dy = pts[j * 3 + 1] - qy, dz = pts[j * 3 + 2] - qz;
        float d2 = (dx * dx + dy * dy) + dz * dz;
        if (d2 < 9.0f) {
            int p = atomicAdd(&scnt, 1);
            if (p < 512) { sd2[p] = d2; sidx[p] = j; }
        }
    }
    __syncthreads();
    int cnt = min(scnt, 512);

    // Sort ONLY if more than KNB candidates (set membership is order-free).
    if (cnt > KNB) {
        int P = 1;
        while (P < cnt) P <<= 1;
        for (int i = cnt + threadIdx.x; i < P; i += blockDim.x) { sd2[i] = 3.0e38f; sidx[i] = 0x7fffffff; }
        __syncthreads();
        for (int k = 2; k <= P; k <<= 1) {
            for (int j2 = k >> 1; j2 > 0; j2 >>= 1) {
                for (int i = threadIdx.x; i < P; i += blockDim.x) {
                    int ixj = i ^ j2;
                    if (ixj > i) {
                        float a = sd2[i], b = sd2[ixj];
                        int ia = sidx[i], ib = sidx[ixj];
                        bool agtb = (a > b) || ((a == b) && (ia > ib));
                        bool up = ((i & k) == 0);
                        if (agtb == up) { sd2[i] = b; sd2[ixj] = a; sidx[i] = ib; sidx[ixj] = ia; }
                    }
                }
                __syncthreads();
            }
        }
        cnt = KNB;
    }

    if (threadIdx.x == 0) cnt_out[n] = cnt;
    if ((int)threadIdx.x < cnt) {
        int j = sidx[threadIdx.x];
        float dx = pts[j * 3] - qx, dy = pts[j * 3 + 1] - qy, dz = pts[j * 3 + 2] - qz;
        float w8[8];
        int cb;
        edge_weights(dx, dy, dz, w8, &cb);
        int e = n * KNB + threadIdx.x;
        idx_out[e] = j;
        cb_out[e] = cb;
#pragma unroll
        for (int r = 0; r < 8; r++) w8_out[e * 8 + r] = w8[r];
    }
}

// -------------------- kernel 3: phase-2 (cf + co + df -> out0), CSR gather ----
__global__ void __launch_bounds__(128) phase2_kernel(
    const float* __restrict__ box_feats,
    const float* __restrict__ k0f, const float* __restrict__ b0f,
    const float* __restrict__ k0o, const float* __restrict__ b0o,
    const float* __restrict__ wdf, const float* __restrict__ bdf)
{
    int n = blockIdx.x, tid = threadIdx.x;
    __shared__ float  F[64 * 12];       // fluid neighbor feats, stride 12
    __shared__ float  bfv[64];
    __shared__ float2 entF[512];
    __shared__ float2 entB[512];
    __shared__ int scF[64], scB[64];
    __shared__ int startF[65], startB[65];
    __shared__ int fillF[64], fillB[64];
    __shared__ int ejF[64], ecbF[64];
    __shared__ int ejB[64], ecbB[64];
    __shared__ float ewF[512], ewB[512];
    __shared__ float cF[576];   // 64 cells x 9
    __shared__ float cB[64];

    int cntF = g_cntF[n];
    int cntB = g_cntB[n];

    if (tid < 64) { scF[tid] = 0; scB[tid] = 0; }
    if (tid < cntF) { ejF[tid] = g_idxF[n * KNB + tid]; ecbF[tid] = g_cbF[n * KNB + tid]; }
    {
        int t = tid - 64;
        if (t >= 0 && t < cntB) { ejB[t] = g_idxB[n * KNB + t]; ecbB[t] = g_cbB[n * KNB + t]; }
    }
    for (int i = tid; i < cntF * 8; i += 128) ewF[i] = g_w8F[n * KNB * 8 + i];
    for (int i = tid; i < cntB * 8; i += 128) ewB[i] = g_w8B[n * KNB * 8 + i];
    __syncthreads();

    // count
    if (tid < cntF) {
        int cb = ecbF[tid];
#pragma unroll
        for (int r = 0; r < 8; r++) atomicAdd(&scF[corner_cell(cb, r)], 1);
    } else if (tid >= 64 && tid - 64 < cntB) {
        int cb = ecbB[tid - 64];
#pragma unroll
        for (int r = 0; r < 8; r++) atomicAdd(&scB[corner_cell(cb, r)], 1);
    }
    __syncthreads();
    // inclusive scan of both count arrays
    for (int d = 1; d < 64; d <<= 1) {
        int v = 0;
        if (tid < 64) { if (tid >= d) v = scF[tid - d]; }
        else { int t = tid - 64; if (t >= d) v = scB[t - d]; }
        __syncthreads();
        if (tid < 64) { if (tid >= d) scF[tid] += v; }
        else { int t = tid - 64; if (t >= d) scB[t] += v; }
        __syncthreads();
    }
    if (tid < 64) {
        startF[tid + 1] = scF[tid];
        fillF[tid] = (tid == 0) ? 0 : scF[tid - 1];
        if (tid == 0) startF[0] = 0;
    } else {
        int t = tid - 64;
        startB[t + 1] = scB[t];
        fillB[t] = (t == 0) ? 0 : scB[t - 1];
        if (t == 0) startB[0] = 0;
    }
    __syncthreads();
    // fill
    if (tid < cntF) {
        int cb = ecbF[tid];
#pragma unroll
        for (int r = 0; r < 8; r++) {
            int l = corner_cell(cb, r);
            int pos = atomicAdd(&fillF[l], 1);
            entF[pos] = make_float2(ewF[tid * 8 + r], __int_as_float(tid));
        }
    } else if (tid >= 64 && tid - 64 < cntB) {
        int e = tid - 64;
        int cb = ecbB[e];
#pragma unroll
        for (int r = 0; r < 8; r++) {
            int l = corner_cell(cb, r);
            int pos = atomicAdd(&fillB[l], 1);
            entB[pos] = make_float2(ewB[e * 8 + r], __int_as_float(e));
        }
    }
    // gather features
    for (int i = tid; i < cntF * 9; i += 128) {
        int e = i / 9, c = i % 9;
        F[e * 12 + c] = g_ff[ejF[e] * 9 + c];
    }
    for (int i = tid; i < cntB; i += 128) bfv[i] = box_feats[ejB[i]];
    __syncthreads();

    // accumulate: thread < 64 owns one cell
    if (tid < 64) {
        int l = tid;
        float acc[9];
#pragma unroll
        for (int c = 0; c < 9; c++) acc[c] = 0.f;
        for (int k = startF[l]; k < startF[l + 1]; k++) {
            float2 we = entF[k];
            float w = we.x;
            int e = __float_as_int(we.y);
#pragma unroll
            for (int c = 0; c < 9; c++) acc[c] += w * F[e * 12 + c];
        }
#pragma unroll
        for (int c = 0; c < 9; c++) cF[l * 9 + c] = acc[c];
        float ab = 0.f;
        for (int k = startB[l]; k < startB[l + 1]; k++) {
            float2 we = entB[k];
            ab += we.x * bfv[__float_as_int(we.y)];
        }
        cB[l] = ab;
    }
    __syncthreads();

    if (tid < 96) {
        int s = tid / 32, o = tid % 32;
        float co = b0o[o];
        for (int l = 0; l < 64; l++) co += cB[l] * k0o[l * 32 + o];
        float cf = b0f[o];
        for (int l = 0; l < 64; l++) {
#pragma unroll
            for (int c = 0; c < 3; c++) cf += cF[l * 9 + s * 3 + c] * k0f[(l * 3 + c) * 32 + o];
        }
        float df = bdf[o];
#pragma unroll
        for (int c = 0; c < 3; c++) df += g_ff[n * 9 + s * 3 + c] * wdf[c * 32 + o];
        int base = n * 288 + s * 96;
        g_out0[base + o]      = co;   // concat order: [co, cf, df]
        g_out0[base + 32 + o] = cf;
        g_out0[base + 64 + o] = df;
    }
}

// -------------------- kernel 4: CSR-gather scatter ----------------------------
// prev: 3000 rows of (3*C) pre-relu features. Writes A (9000 x 64C), row = n*3+s.
// One CTA per point, 256 threads. Per-thread register accumulation: thread owns
// (cell, channel-chunk); entries gathered via per-cell CSR built in smem.
template <int C>
__global__ void __launch_bounds__(256) scatter_csr_kernel(
    const float* __restrict__ prev, float* __restrict__ Aout)
{
    constexpr int SC  = 3 * C;
    constexpr int SCP = SC + 8;       // padded stride: 16B-aligned, bank-rotating
    constexpr int CH  = SC / 8;       // channels per thread (24 or 36)
    int n = blockIdx.x;
    int tid = threadIdx.x;

    extern __shared__ float H[];      // [64][SCP] relu'd neighbor features
    __shared__ float2 ent[512];
    __shared__ int   scc[64];
    __shared__ int   cellStart[65];
    __shared__ int   fillPos[64];
    __shared__ int   ej[64];
    __shared__ int   ecb[64];
    __shared__ float ew[512];

    int cnt = g_cntF[n];
    if (tid < 64) scc[tid] = 0;
    if (tid < cnt) { ej[tid] = g_idxF[n * KNB + tid]; ecb[tid] = g_cbF[n * KNB + tid]; }
    for (int i = tid; i < cnt * 8; i += 256) ew[i] = g_w8F[n * KNB * 8 + i];
    __syncthreads();

    // count
    if (tid < cnt) {
        int cb = ecb[tid];
#pragma unroll
        for (int r = 0; r < 8; r++) atomicAdd(&scc[corner_cell(cb, r)], 1);
    }
    __syncthreads();
    // inclusive scan
    for (int d = 1; d < 64; d <<= 1) {
        int v = 0;
        if (tid < 64 && tid >= d) v = scc[tid - d];
        __syncthreads();
        if (tid < 64 && tid >= d) scc[tid] += v;
        __syncthreads();
    }
    if (tid < 64) {
        cellStart[tid + 1] = scc[tid];
        fillPos[tid] = (tid == 0) ? 0 : scc[tid - 1];
        if (tid == 0) cellStart[0] = 0;
    }
    __syncthreads();
    // fill CSR entries
    if (tid < cnt) {
        int cb = ecb[tid];
#pragma unroll
        for (int r = 0; r < 8; r++) {
            int l = corner_cell(cb, r);
            int pos = atomicAdd(&fillPos[l], 1);
            ent[pos] = make_float2(ew[tid * 8 + r], __int_as_float(tid));
        }
    }
    // gather H (relu'd neighbor rows), float4
    for (int i = tid; i < cnt * (SC / 4); i += 256) {
        int e = i / (SC / 4), q = i % (SC / 4);
        float4 v = *(const float4*)(prev + (size_t)ej[e] * SC + q * 4);
        v.x = fmaxf(v.x, 0.f); v.y = fmaxf(v.y, 0.f);
        v.z = fmaxf(v.z, 0.f); v.w = fmaxf(v.w, 0.f);
        *(float4*)&H[e * SCP + q * 4] = v;
    }
    __syncthreads();

    // accumulate in registers: 2 passes x (32 cells x 8 channel-groups)
#pragma unroll
    for (int pass = 0; pass < 2; pass++) {
        int l = pass * 32 + (tid >> 3);
        int c0 = (tid & 7) * CH;
        float acc[CH];
#pragma unroll
        for (int i = 0; i < CH; i++) acc[i] = 0.f;
        int k1 = cellStart[l + 1];
        for (int k = cellStart[l]; k < k1; k++) {
            float2 we = ent[k];
            float w = we.x;
            const float* hr = &H[__float_as_int(we.y) * SCP + c0];
#pragma unroll
            for (int q4 = 0; q4 < CH / 4; q4++) {
                float4 h = *(const float4*)(hr + q4 * 4);
                acc[q4 * 4 + 0] += w * h.x;
                acc[q4 * 4 + 1] += w * h.y;
                acc[q4 * 4 + 2] += w * h.z;
                acc[q4 * 4 + 3] += w * h.w;
            }
        }
#pragma unroll
        for (int cc = 0; cc < CH; cc++) {
            int ch = c0 + cc;
            int s = ch / C, c = ch % C;
            Aout[(size_t)(n * 3 + s) * (64 * C) + l * C + c] = acc[cc];
        }
    }
}

// -------------------- kernel 5: TF32 tensor-core GEMM -------------------------
#define AS_STRIDE 36
#define BS_STRIDE 72
__global__ void __launch_bounds__(128) gemm_tf32_kernel(
    const float* __restrict__ A, const float* __restrict__ Bk,
    const float* __restrict__ prev, const float* __restrict__ wd,
    const float* __restrict__ bc, const float* __restrict__ bd,
    float* __restrict__ Out, int M, int K, int C, int res)
{
    __shared__ uint32_t As[64 * AS_STRIDE];
    __shared__ uint32_t Bs[32 * BS_STRIDE];

    int tid = threadIdx.x;
    int warp = tid >> 5, lane = tid & 31;
    int warp_m = warp >> 1, warp_n = warp & 1;
    int g = lane >> 2, tg = lane & 3;
    int rowBase = blockIdx.x * 64;

    float acc[2][4][4];
#pragma unroll
    for (int i = 0; i < 2; i++)
#pragma unroll
        for (int j = 0; j < 4; j++)
#pragma unroll
            for (int q = 0; q < 4; q++) acc[i][j][q] = 0.f;

    const int stages0 = K / 32, stages1 = C / 32;
    const int S = stages0 + stages1;

    float4 pa[4], pb[4];

    auto load_stage = [&](int s) {
        int seg = (s >= stages0);
        const float* Ag = seg ? prev : A;
        const float* Bg = seg ? wd : Bk;
        int Ks = seg ? C : K;
        int k0 = seg ? (s - stages0) * 32 : s * 32;
#pragma unroll
        for (int q = 0; q < 4; q++) {
            int f = tid + q * 128;
            int r = rowBase + (f >> 3);
            if (r >= M) r = M - 1;
            int kc = k0 + ((f & 7) << 2);
            pa[q] = *(const float4*)(Ag + (size_t)r * Ks + kc);
            if (seg) {
                pa[q].x = fmaxf(pa[q].x, 0.f); pa[q].y = fmaxf(pa[q].y, 0.f);
                pa[q].z = fmaxf(pa[q].z, 0.f); pa[q].w = fmaxf(pa[q].w, 0.f);
            }
            int kr = k0 + (f >> 4);
            int cc = (f & 15) << 2;
            pb[q] = *(const float4*)(Bg + (size_t)kr * 64 + cc);
        }
    };

    auto store_stage = [&]() {
#pragma unroll
        for (int q = 0; q < 4; q++) {
            int f = tid + q * 128;
            uint32_t* ad = &As[(f >> 3) * AS_STRIDE + ((f & 7) << 2)];
            ad[0] = f2tf32(pa[q].x); ad[1] = f2tf32(pa[q].y);
            ad[2] = f2tf32(pa[q].z); ad[3] = f2tf32(pa[q].w);
            uint32_t* bdst = &Bs[(f >> 4) * BS_STRIDE + ((f & 15) << 2)];
            bdst[0] = f2tf32(pb[q].x); bdst[1] = f2tf32(pb[q].y);
            bdst[2] = f2tf32(pb[q].z); bdst[3] = f2tf32(pb[q].w);
        }
    };

    load_stage(0);
    for (int s = 0; s < S; s++) {
        store_stage();
        __syncthreads();
        if (s + 1 < S) load_stage(s + 1);

#pragma unroll
        for (int k8 = 0; k8 < 32; k8 += 8) {
            uint32_t af[2][4];
#pragma unroll
            for (int i2 = 0; i2 < 2; i2++) {
                int r0 = warp_m * 32 + i2 * 16 + g;
                af[i2][0] = As[r0 * AS_STRIDE + k8 + tg];
                af[i2][1] = As[(r0 + 8) * AS_STRIDE + k8 + tg];
                af[i2][2] = As[r0 * AS_STRIDE + k8 + tg + 4];
                af[i2][3] = As[(r0 + 8) * AS_STRIDE + k8 + tg + 4];
            }
#pragma unroll
            for (int j = 0; j < 4; j++) {
                int n0 = warp_n * 32 + j * 8;
                uint32_t b0 = Bs[(k8 + tg) * BS_STRIDE + n0 + g];
                uint32_t b1 = Bs[(k8 + tg + 4) * BS_STRIDE + n0 + g];
#pragma unroll
                for (int i2 = 0; i2 < 2; i2++) {
                    asm volatile(
                        "mma.sync.aligned.m16n8k8.row.col.f32.tf32.tf32.f32 "
                        "{%0,%1,%2,%3}, {%4,%5,%6,%7}, {%8,%9}, {%0,%1,%2,%3};\n"
                        : "+f"(acc[i2][j][0]), "+f"(acc[i2][j][1]),
                          "+f"(acc[i2][j][2]), "+f"(acc[i2][j][3])
                        : "r"(af[i2][0]), "r"(af[i2][1]), "r"(af[i2][2]), "r"(af[i2][3]),
                          "r"(b0), "r"(b1));
                }
            }
        }
        __syncthreads();
    }

#pragma unroll
    for (int i2 = 0; i2 < 2; i2++) {
#pragma unroll
        for (int j = 0; j < 4; j++) {
            int col = warp_n * 32 + j * 8 + tg * 2;
#pragma unroll
            for (int q = 0; q < 4; q++) {
                int row = rowBase + warp_m * 32 + i2 * 16 + g + ((q >= 2) ? 8 : 0);
                int c = col + (q & 1);
                if (row < M) {
                    float v = acc[i2][j][q] + bc[c] + bd[c];
                    if (res) v += prev[(size_t)row * C + c];
                    Out[(size_t)row * 64 + c] = v;
                }
            }
        }
    }
}

// -------------------- kernel 6: last layer (64C -> 3) -------------------------
__global__ void out4_kernel(const float* __restrict__ A, const float* __restrict__ kern,
                            const float* __restrict__ prev, const float* __restrict__ wd,
                            const float* __restrict__ bc, const float* __restrict__ bd,
                            float* __restrict__ out4, int M, int K)
{
    int warp = (blockIdx.x * blockDim.x + threadIdx.x) >> 5;
    int lane = threadIdx.x & 31;
    if (warp >= M) return;
    float a0 = 0.f, a1 = 0.f, a2 = 0.f;
    const float* Ar = A + (size_t)warp * K;
    for (int k = lane; k < K; k += 32) {
        float av = Ar[k];
        a0 += av * kern[k * 3 + 0];
        a1 += av * kern[k * 3 + 1];
        a2 += av * kern[k * 3 + 2];
    }
    const float* pr = prev + (size_t)warp * 64;
    for (int c = lane; c < 64; c += 32) {
        float h = fmaxf(pr[c], 0.f);
        a0 += h * wd[c * 3 + 0];
        a1 += h * wd[c * 3 + 1];
        a2 += h * wd[c * 3 + 2];
    }
#pragma unroll
    for (int off = 16; off > 0; off >>= 1) {
        a0 += __shfl_down_sync(0xffffffffu, a0, off);
        a1 += __shfl_down_sync(0xffffffffu, a1, off);
        a2 += __shfl_down_sync(0xffffffffu, a2, off);
    }
    if (lane == 0) {
        out4[warp * 3 + 0] = a0 + bc[0] + bd[0];
        out4[warp * 3 + 1] = a1 + bc[1] + bd[1];
        out4[warp * 3 + 2] = a2 + bc[2] + bd[2];
    }
}

// -------------------- kernel 7: final outputs ---------------------------------
__global__ void final_kernel(const float* __restrict__ p0, const float* __restrict__ v0e,
                             float* __restrict__ outp)
{
    int n = blockIdx.x * blockDim.x + threadIdx.x;
    if (n >= NF) return;
#pragma unroll
    for (int j = 0; j < 3; j++) {
        float o0 = g_out4[n * 9 + j];                 // s=0 row
        float corr = o0 * 0.25f * (1.f / 16.f);
        float pc = g_p1[n * 3 + j] + corr;
        outp[n * 3 + j] = pc;                          // p_c
        outp[9000 + n * 3 + j] = (pc - p0[n * 3 + j]) / 0.1f;  // v_c
        outp[18000 + n * 6 + 0 + j] = g_out4[n * 9 + 3 + j] * 0.25f;  // m_matrix s=1
        outp[18000 + n * 6 + 3 + j] = g_out4[n * 9 + 6 + j] * 0.25f;  // m_matrix s=2
        outp[36000 + n * 3 + j] = v0e[n * 3 + j];      // state_feats
    }
}

// -------------------- launch --------------------------------------------------
template <typename T>
static T* sym_addr(const void* sym)
{
    void* p = nullptr;
    cudaGetSymbolAddress(&p, sym);
    return (T*)p;
}

extern "C" void kernel_launch(void* const* d_in, const int* in_sizes, int n_in,
                              void* d_out, int out_size)
{
    (void)n_in; (void)out_size;
    const float* v0e       = (const float*)d_in[1];
    const float* p0        = (const float*)d_in[2];
    const float* v0        = (const float*)d_in[3];
    const float* a         = (const float*)d_in[4];
    const float* other     = (const float*)d_in[5];
    const float* box       = (const float*)d_in[6];
    const float* box_feats = (const float*)d_in[7];
    const float* box_mask  = (const float*)d_in[9];
    const float* k0f = (const float*)d_in[10];
    const float* b0f = (const float*)d_in[11];
    const float* k0o = (const float*)d_in[12];
    const float* b0o = (const float*)d_in[13];
    const float* wdf = (const float*)d_in[14];
    const float* bdf = (const float*)d_in[15];

    // Resolve deep-layer weights 16..31 BY SIZE (robust to metadata ordering).
    const float* kcA[5] = {0, 0, 0, 0, 0};
    const float* wdA[5] = {0, 0, 0, 0, 0};
    const float* b64[6] = {0, 0, 0, 0, 0, 0};
    const float* b3[2]  = {0, 0};
    int n262 = 0, n4096 = 0, nb64 = 0, nb3 = 0;
    for (int i = 16; i < 32; i++) {
        const float* p = (const float*)d_in[i];
        switch (in_sizes[i]) {
            case 393216: kcA[1] = p; break;
            case 262144: if (n262++ == 0) kcA[2] = p; else kcA[3] = p; break;
            case 12288:  kcA[4] = p; break;
            case 6144:   wdA[1] = p; break;
            case 4096:   if (n4096++ == 0) wdA[2] = p; else wdA[3] = p; break;
            case 192:    wdA[4] = p; break;
            case 64:     if (nb64 < 6) b64[nb64++] = p; break;
            case 3:      if (nb3 < 2) b3[nb3++] = p; break;
            default: break;
        }
    }
    const float* bc1 = b64[0]; const float* bd1 = b64[1];
    const float* bc2 = b64[2]; const float* bd2 = b64[3];
    const float* bc3 = b64[4]; const float* bd3 = b64[5];
    const float* bc4 = b3[0];  const float* bd4 = b3[1];

    float* outp = (float*)d_out;

    float* pp1   = sym_addr<float>(g_p1);
    int*   pidxF = sym_addr<int>(g_idxF);
    int*   pcbF  = sym_addr<int>(g_cbF);
    float* pw8F  = sym_addr<float>(g_w8F);
    int*   pcntF = sym_addr<int>(g_cntF);
    int*   pidxB = sym_addr<int>(g_idxB);
    int*   pcbB  = sym_addr<int>(g_cbB);
    float* pw8B  = sym_addr<float>(g_w8B);
    int*   pcntB = sym_addr<int>(g_cntB);
    float* pout0 = sym_addr<float>(g_out0);
    float* pout1 = sym_addr<float>(g_out1);
    float* pout2 = sym_addr<float>(g_out2);
    float* pout3 = sym_addr<float>(g_out3);
    float* pout4 = sym_addr<float>(g_out4);
    float* pA    = sym_addr<float>(g_A);

    const int smem96 = 64 * (3 * 96 + 8) * (int)sizeof(float);  // 75776
    const int smem64 = 64 * (3 * 64 + 8) * (int)sizeof(float);  // 51200
    cudaFuncSetAttribute(scatter_csr_kernel<96>, cudaFuncAttributeMaxDynamicSharedMemorySize, smem96);
    cudaFuncSetAttribute(scatter_csr_kernel<64>, cudaFuncAttributeMaxDynamicSharedMemorySize, smem64);

    prep_kernel<<<(NF + 127) / 128, 128>>>(p0, v0, a, other, v0e);
    nbr_kernel<<<NF, 256>>>(pp1, NF, nullptr, 1, pidxF, pcbF, pw8F, pcntF);
    nbr_kernel<<<NF, 256>>>(box, NB, box_mask, 0, pidxB, pcbB, pw8B, pcntB);
    phase2_kernel<<<NF, 128>>>(box_feats, k0f, b0f, k0o, b0o, wdf, bdf);

    const int Mrows = NF * 3;  // 9000
    const int gemmGrid = (Mrows + 63) / 64;   // 141 CTAs

    // layer 1: C=96, K=6144, no residual
    scatter_csr_kernel<96><<<NF, 256, smem96>>>(pout0, pA);
    gemm_tf32_kernel<<<gemmGrid, 128>>>(pA, kcA[1], pout0, wdA[1], bc1, bd1, pout1, Mrows, 6144, 96, 0);

    // layer 2: C=64, K=4096, residual
    scatter_csr_kernel<64><<<NF, 256, smem64>>>(pout1, pA);
    gemm_tf32_kernel<<<gemmGrid, 128>>>(pA, kcA[2], pout1, wdA[2], bc2, bd2, pout2, Mrows, 4096, 64, 1);

    // layer 3: C=64, K=4096, residual
    scatter_csr_kernel<64><<<NF, 256, smem64>>>(pout2, pA);
    gemm_tf32_kernel<<<gemmGrid, 128>>>(pA, kcA[3], pout2, wdA[3], bc3, bd3, pout3, Mrows, 4096, 64, 1);

    // layer 4: C=64 -> 3 outputs
    scatter_csr_kernel<64><<<NF, 256, smem64>>>(pout3, pA);
    out4_kernel<<<(Mrows * 32 + 255) / 256, 256>>>(pA, kcA[4], pout3, wdA[4], bc4, bd4, pout4, Mrows, 4096);

    final_kernel<<<(NF + 127) / 128, 128>>>(p0, v0e, outp);
}

// round 10
// speedup vs baseline: 1.6130x; 1.6130x over previous
#include <cuda_runtime.h>
#include <math.h>
#include <stdint.h>

#define NF 3000
#define NB 1500
#define KNB 64

// -------------------- global scratch (no runtime allocation allowed) ----------
__device__ float g_p1[NF * 3];
__device__ float g_ff[NF * 9];

__device__ int   g_idxF[NF * KNB];
__device__ int   g_cbF [NF * KNB];
__device__ float g_w8F [NF * KNB * 8];
__device__ int   g_cntF[NF];

__device__ int   g_idxB[NF * KNB];
__device__ int   g_cbB [NF * KNB];
__device__ float g_w8B [NF * KNB * 8];
__device__ int   g_cntB[NF];

__device__ float g_out0[NF * 3 * 96];
__device__ float g_out1[NF * 3 * 64];
__device__ float g_out2[NF * 3 * 64];
__device__ float g_out3[NF * 3 * 64];
__device__ float g_out4[NF * 3 * 3];

__device__ float g_A[(size_t)NF * 3 * 64 * 96];   // GEMM input scratch (max layer1)

// -------------------- helpers -------------------------------------------------
__device__ __forceinline__ float sgnf(float v) {
    return (v > 0.f) ? 1.f : ((v < 0.f) ? -1.f : 0.f);
}

__device__ __forceinline__ uint32_t f2tf32(float f) {
    uint32_t r;
    asm("cvt.rna.tf32.f32 %0, %1;" : "=r"(r) : "f"(f));
    return r;
}

// Per-edge weight computation: offset (dx,dy,dz) = p_in[j] - p_out[n]
__device__ void edge_weights(float dx, float dy, float dz, float* w8, int* cbase)
{
    const float inv_r = 1.f / 3.f;     // radius = EXTENT*0.5 = 3.0
    float x = dx * inv_r, y = dy * inv_r, z = dz * inv_r;
    float sq = (x * x + y * y) + z * z;

    float win = 1.f - sq;
    win = win * win * win;
    win = fminf(fmaxf(win, 0.f), 1.f);

    // _ball_to_cube
    float norm  = sqrtf(fmaxf(sq, 1e-8f));
    float xy_sq = x * x + y * y;
    bool  polar = (1.25f * z * z > xy_sq);
    float s_p = sqrtf(3.f * norm / (norm + fabsf(z) + 1e-8f));
    float s_e = norm / sqrtf(fmaxf(xy_sq, 1e-8f));
    float cx = polar ? x * s_p : x * s_e;
    float cy = polar ? y * s_p : y * s_e;
    float cz = polar ? sgnf(z) * norm : 1.5f * z;

    float nxy = sqrtf(fmaxf(cx * cx + cy * cy, 1e-8f));
    bool  xdom = (fabsf(cy) <= fabsf(cx));
    float sx = (fabsf(cx) > 1e-8f) ? cx : 1.f;
    float sy = (fabsf(cy) > 1e-8f) ? cy : 1.f;
    const float FOPI = 1.27323954473516268615f;  // 4/pi
    float bx1 = sgnf(cx) * nxy;
    float by1 = bx1 * FOPI * atanf(cy / sx);
    float by2 = sgnf(cy) * nxy;
    float bx2 = by2 * FOPI * atanf(cx / sy);
    float bx = xdom ? bx1 : bx2;
    float by = xdom ? by1 : by2;
    if (cx * cx + cy * cy < 1e-8f) { bx = 0.f; by = 0.f; }
    float bz = cz;
    if (sq < 1e-8f) { bx = 0.f; by = 0.f; bz = 0.f; }

    float bb[3] = {bx, by, bz};
    float f[3];
    int   c0[3];
#pragma unroll
    for (int ax = 0; ax < 3; ax++) {
        float co = (bb[ax] * 0.5f + 0.5f) * 3.f;       // (KS-1)=3
        co = fminf(fmaxf(co, 0.f), 3.f);
        int ci = (int)floorf(co);
        ci = min(max(ci, 0), 2);
        c0[ax] = ci;
        f[ax] = co - (float)ci;
    }
    *cbase = (c0[0] * 4 + c0[1]) * 4 + c0[2];
#pragma unroll
    for (int r = 0; r < 8; r++) {
        int i = (r >> 2) & 1, j = (r >> 1) & 1, l = r & 1;
        float w = (i ? f[0] : 1.f - f[0]) * (j ? f[1] : 1.f - f[1]) * (l ? f[2] : 1.f - f[2]);
        w8[r] = w * win;
    }
}

__device__ __forceinline__ int corner_cell(int cb, int r) {
    return cb + ((r >> 2) & 1) * 16 + ((r >> 1) & 1) * 4 + (r & 1);
}

// -------------------- kernel 1: prep -----------------------------------------
__global__ void prep_kernel(const float* __restrict__ p0, const float* __restrict__ v0,
                            const float* __restrict__ a, const float* __restrict__ other,
                            const float* __restrict__ v0e)
{
    int n = blockIdx.x * blockDim.x + threadIdx.x;
    if (n >= NF) return;
#pragma unroll
    for (int j = 0; j < 3; j++) {
        float v0v = v0[n * 3 + j], av = a[n * 3 + j];
        float v1 = v0v + 0.1f * av;
        float p1 = p0[n * 3 + j] + 0.1f * (v0v + v1) * 0.5f;
        g_p1[n * 3 + j] = p1;
        g_ff[n * 9 + 0 + j] = v1;                // s=0 : v1
        g_ff[n * 9 + 3 + j] = other[n * 3 + j];  // s=1 : other_feats
        g_ff[n * 9 + 6 + j] = v0e[n * 3 + j];    // s=2 : v0_enc
    }
}

// -------------------- kernel 2: neighbor build (fluid or box) -----------------
__global__ void nbr_kernel(const float* __restrict__ pts, int npts,
                           const float* __restrict__ mask, int self_exclude,
                           int* __restrict__ idx_out, int* __restrict__ cb_out,
                           float* __restrict__ w8_out, int* __restrict__ cnt_out)
{
    int n = blockIdx.x;
    __shared__ float sd2[512];
    __shared__ int   sidx[512];
    __shared__ int   scnt;
    float qx = g_p1[n * 3], qy = g_p1[n * 3 + 1], qz = g_p1[n * 3 + 2];
    if (threadIdx.x == 0) scnt = 0;
    __syncthreads();

    for (int j = threadIdx.x; j < npts; j += blockDim.x) {
        if (self_exclude && j == n) continue;
        if (mask && mask[j] <= 0.f) continue;
        float dx = pts[j * 3] - qx, dy = pts[j * 3 + 1] - qy, dz = pts[j * 3 + 2] - qz;
        float d2 = (dx * dx + dy * dy) + dz * dz;
        if (d2 < 9.0f) {
            int p = atomicAdd(&scnt, 1);
            if (p < 512) { sd2[p] = d2; sidx[p] = j; }
        }
    }
    __syncthreads();
    int cnt = min(scnt, 512);

    // Sort ONLY if more than KNB candidates (set membership is order-free).
    if (cnt > KNB) {
        int P = 1;
        while (P < cnt) P <<= 1;
        for (int i = cnt + threadIdx.x; i < P; i += blockDim.x) { sd2[i] = 3.0e38f; sidx[i] = 0x7fffffff; }
        __syncthreads();
        for (int k = 2; k <= P; k <<= 1) {
            for (int j2 = k >> 1; j2 > 0; j2 >>= 1) {
                for (int i = threadIdx.x; i < P; i += blockDim.x) {
                    int ixj = i ^ j2;
                    if (ixj > i) {
                        float a = sd2[i], b = sd2[ixj];
                        int ia = sidx[i], ib = sidx[ixj];
                        bool agtb = (a > b) || ((a == b) && (ia > ib));
                        bool up = ((i & k) == 0);
                        if (agtb == up) { sd2[i] = b; sd2[ixj] = a; sidx[i] = ib; sidx[ixj] = ia; }
                    }
                }
                __syncthreads();
            }
        }
        cnt = KNB;
    }

    if (threadIdx.x == 0) cnt_out[n] = cnt;
    if ((int)threadIdx.x < cnt) {
        int j = sidx[threadIdx.x];
        float dx = pts[j * 3] - qx, dy = pts[j * 3 + 1] - qy, dz = pts[j * 3 + 2] - qz;
        float w8[8];
        int cb;
        edge_weights(dx, dy, dz, w8, &cb);
        int e = n * KNB + threadIdx.x;
        idx_out[e] = j;
        cb_out[e] = cb;
#pragma unroll
        for (int r = 0; r < 8; r++) w8_out[e * 8 + r] = w8[r];
    }
}

// -------------------- kernel 3: phase-2 (cf + co + df -> out0), CSR gather ----
__global__ void __launch_bounds__(128) phase2_kernel(
    const float* __restrict__ box_feats,
    const float* __restrict__ k0f, const float* __restrict__ b0f,
    const float* __restrict__ k0o, const float* __restrict__ b0o,
    const float* __restrict__ wdf, const float* __restrict__ bdf)
{
    int n = blockIdx.x, tid = threadIdx.x;
    __shared__ float  F[64 * 12];       // fluid neighbor feats, stride 12
    __shared__ float  bfv[64];
    __shared__ float2 entF[512];
    __shared__ float2 entB[512];
    __shared__ int scF[64], scB[64];
    __shared__ int startF[65], startB[65];
    __shared__ int fillF[64], fillB[64];
    __shared__ int ejF[64], ecbF[64];
    __shared__ int ejB[64], ecbB[64];
    __shared__ float ewF[512], ewB[512];
    __shared__ float cF[576];   // 64 cells x 9
    __shared__ float cB[64];

    int cntF = g_cntF[n];
    int cntB = g_cntB[n];

    if (tid < 64) { scF[tid] = 0; scB[tid] = 0; }
    if (tid < cntF) { ejF[tid] = g_idxF[n * KNB + tid]; ecbF[tid] = g_cbF[n * KNB + tid]; }
    {
        int t = tid - 64;
        if (t >= 0 && t < cntB) { ejB[t] = g_idxB[n * KNB + t]; ecbB[t] = g_cbB[n * KNB + t]; }
    }
    for (int i = tid; i < cntF * 8; i += 128) ewF[i] = g_w8F[n * KNB * 8 + i];
    for (int i = tid; i < cntB * 8; i += 128) ewB[i] = g_w8B[n * KNB * 8 + i];
    __syncthreads();

    // count
    if (tid < cntF) {
        int cb = ecbF[tid];
#pragma unroll
        for (int r = 0; r < 8; r++) atomicAdd(&scF[corner_cell(cb, r)], 1);
    } else if (tid >= 64 && tid - 64 < cntB) {
        int cb = ecbB[tid - 64];
#pragma unroll
        for (int r = 0; r < 8; r++) atomicAdd(&scB[corner_cell(cb, r)], 1);
    }
    __syncthreads();
    // inclusive scan of both count arrays
    for (int d = 1; d < 64; d <<= 1) {
        int v = 0;
        if (tid < 64) { if (tid >= d) v = scF[tid - d]; }
        else { int t = tid - 64; if (t >= d) v = scB[t - d]; }
        __syncthreads();
        if (tid < 64) { if (tid >= d) scF[tid] += v; }
        else { int t = tid - 64; if (t >= d) scB[t] += v; }
        __syncthreads();
    }
    if (tid < 64) {
        startF[tid + 1] = scF[tid];
        fillF[tid] = (tid == 0) ? 0 : scF[tid - 1];
        if (tid == 0) startF[0] = 0;
    } else {
        int t = tid - 64;
        startB[t + 1] = scB[t];
        fillB[t] = (t == 0) ? 0 : scB[t - 1];
        if (t == 0) startB[0] = 0;
    }
    __syncthreads();
    // fill
    if (tid < cntF) {
        int cb = ecbF[tid];
#pragma unroll
        for (int r = 0; r < 8; r++) {
            int l = corner_cell(cb, r);
            int pos = atomicAdd(&fillF[l], 1);
            entF[pos] = make_float2(ewF[tid * 8 + r], __int_as_float(tid));
        }
    } else if (tid >= 64 && tid - 64 < cntB) {
        int e = tid - 64;
        int cb = ecbB[e];
#pragma unroll
        for (int r = 0; r < 8; r++) {
            int l = corner_cell(cb, r);
            int pos = atomicAdd(&fillB[l], 1);
            entB[pos] = make_float2(ewB[e * 8 + r], __int_as_float(e));
        }
    }
    // gather features
    for (int i = tid; i < cntF * 9; i += 128) {
        int e = i / 9, c = i % 9;
        F[e * 12 + c] = g_ff[ejF[e] * 9 + c];
    }
    for (int i = tid; i < cntB; i += 128) bfv[i] = box_feats[ejB[i]];
    __syncthreads();

    // accumulate: thread < 64 owns one cell
    if (tid < 64) {
        int l = tid;
        float acc[9];
#pragma unroll
        for (int c = 0; c < 9; c++) acc[c] = 0.f;
        for (int k = startF[l]; k < startF[l + 1]; k++) {
            float2 we = entF[k];
            float w = we.x;
            int e = __float_as_int(we.y);
#pragma unroll
            for (int c = 0; c < 9; c++) acc[c] += w * F[e * 12 + c];
        }
#pragma unroll
        for (int c = 0; c < 9; c++) cF[l * 9 + c] = acc[c];
        float ab = 0.f;
        for (int k = startB[l]; k < startB[l + 1]; k++) {
            float2 we = entB[k];
            ab += we.x * bfv[__float_as_int(we.y)];
        }
        cB[l] = ab;
    }
    __syncthreads();

    if (tid < 96) {
        int s = tid / 32, o = tid % 32;
        float co = b0o[o];
        for (int l = 0; l < 64; l++) co += cB[l] * k0o[l * 32 + o];
        float cf = b0f[o];
        for (int l = 0; l < 64; l++) {
#pragma unroll
            for (int c = 0; c < 3; c++) cf += cF[l * 9 + s * 3 + c] * k0f[(l * 3 + c) * 32 + o];
        }
        float df = bdf[o];
#pragma unroll
        for (int c = 0; c < 3; c++) df += g_ff[n * 9 + s * 3 + c] * wdf[c * 32 + o];
        int base = n * 288 + s * 96;
        g_out0[base + o]      = co;   // concat order: [co, cf, df]
        g_out0[base + 32 + o] = cf;
        g_out0[base + 64 + o] = df;
    }
}

// -------------------- kernel 4: warp-per-cell CSR gather scatter --------------
// prev: 3000 rows of (3*C) pre-relu features. Writes A (9000 x 64C), row = n*3+s.
// 256 threads = 8 warps; each warp owns cells wid, wid+8, ... All 32 lanes of a
// warp share the same entry list (no divergence); lane owns channels i*32+lane
// (conflict-free H rows since SC % 32 == 0).
template <int C>
__global__ void __launch_bounds__(256) scatter_warp_kernel(
    const float* __restrict__ prev, float* __restrict__ Aout)
{
    constexpr int SC = 3 * C;          // 288 or 192
    constexpr int PF = SC / 32;        // floats per lane: 9 or 6
    int n = blockIdx.x;
    int tid = threadIdx.x, lane = tid & 31, wid = tid >> 5;

    extern __shared__ float H[];       // [64][SC], stride SC (multiple of 32)
    __shared__ float2 ent[512];
    __shared__ int   scc[64];
    __shared__ int   cellStart[65];
    __shared__ int   fillPos[64];
    __shared__ int   ej[64];
    __shared__ int   ecb[64];
    __shared__ float ew[512];

    int cnt = g_cntF[n];
    if (tid < 64) scc[tid] = 0;
    if (tid < cnt) { ej[tid] = g_idxF[n * KNB + tid]; ecb[tid] = g_cbF[n * KNB + tid]; }
    for (int i = tid; i < cnt * 8; i += 256) ew[i] = g_w8F[n * KNB * 8 + i];
    __syncthreads();

    // count
    if (tid < cnt) {
        int cb = ecb[tid];
#pragma unroll
        for (int r = 0; r < 8; r++) atomicAdd(&scc[corner_cell(cb, r)], 1);
    }
    __syncthreads();
    // inclusive scan
    for (int d = 1; d < 64; d <<= 1) {
        int v = 0;
        if (tid < 64 && tid >= d) v = scc[tid - d];
        __syncthreads();
        if (tid < 64 && tid >= d) scc[tid] += v;
        __syncthreads();
    }
    if (tid < 64) {
        cellStart[tid + 1] = scc[tid];
        fillPos[tid] = (tid == 0) ? 0 : scc[tid - 1];
        if (tid == 0) cellStart[0] = 0;
    }
    __syncthreads();
    // fill CSR entries
    if (tid < cnt) {
        int cb = ecb[tid];
#pragma unroll
        for (int r = 0; r < 8; r++) {
            int l = corner_cell(cb, r);
            int pos = atomicAdd(&fillPos[l], 1);
            ent[pos] = make_float2(ew[tid * 8 + r], __int_as_float(tid));
        }
    }
    // gather H rows (relu'd), float4 coalesced
    for (int i = tid; i < cnt * (SC / 4); i += 256) {
        int e = i / (SC / 4), q = i % (SC / 4);
        float4 v = *(const float4*)(prev + (size_t)ej[e] * SC + q * 4);
        v.x = fmaxf(v.x, 0.f); v.y = fmaxf(v.y, 0.f);
        v.z = fmaxf(v.z, 0.f); v.w = fmaxf(v.w, 0.f);
        *(float4*)&H[e * SC + q * 4] = v;
    }
    __syncthreads();

    // warp-per-cell accumulation (8 cells per warp, serial over entries)
    for (int l = wid; l < 64; l += 8) {
        float acc[PF];
#pragma unroll
        for (int i = 0; i < PF; i++) acc[i] = 0.f;
        int k1 = cellStart[l + 1];
        for (int k = cellStart[l]; k < k1; k++) {
            float2 we = ent[k];           // broadcast (same addr all lanes)
            float w = we.x;
            const float* hr = &H[__float_as_int(we.y) * SC];
#pragma unroll
            for (int i = 0; i < PF; i++) acc[i] += w * hr[i * 32 + lane];
        }
#pragma unroll
        for (int i = 0; i < PF; i++) {
            int ch = i * 32 + lane;
            int s = ch / C, c = ch - s * C;
            Aout[(size_t)(n * 3 + s) * (64 * C) + l * C + c] = acc[i];
        }
    }
}

// -------------------- kernel 5: TF32 tensor-core GEMM -------------------------
#define AS_STRIDE 36
#define BS_STRIDE 72
__global__ void __launch_bounds__(128) gemm_tf32_kernel(
    const float* __restrict__ A, const float* __restrict__ Bk,
    const float* __restrict__ prev, const float* __restrict__ wd,
    const float* __restrict__ bc, const float* __restrict__ bd,
    float* __restrict__ Out, int M, int K, int C, int res)
{
    __shared__ uint32_t As[64 * AS_STRIDE];
    __shared__ uint32_t Bs[32 * BS_STRIDE];

    int tid = threadIdx.x;
    int warp = tid >> 5, lane = tid & 31;
    int warp_m = warp >> 1, warp_n = warp & 1;
    int g = lane >> 2, tg = lane & 3;
    int rowBase = blockIdx.x * 64;

    float acc[2][4][4];
#pragma unroll
    for (int i = 0; i < 2; i++)
#pragma unroll
        for (int j = 0; j < 4; j++)
#pragma unroll
            for (int q = 0; q < 4; q++) acc[i][j][q] = 0.f;

    const int stages0 = K / 32, stages1 = C / 32;
    const int S = stages0 + stages1;

    float4 pa[4], pb[4];

    auto load_stage = [&](int s) {
        int seg = (s >= stages0);
        const float* Ag = seg ? prev : A;
        const float* Bg = seg ? wd : Bk;
        int Ks = seg ? C : K;
        int k0 = seg ? (s - stages0) * 32 : s * 32;
#pragma unroll
        for (int q = 0; q < 4; q++) {
            int f = tid + q * 128;
            int r = rowBase + (f >> 3);
            if (r >= M) r = M - 1;
            int kc = k0 + ((f & 7) << 2);
            pa[q] = *(const float4*)(Ag + (size_t)r * Ks + kc);
            if (seg) {
                pa[q].x = fmaxf(pa[q].x, 0.f); pa[q].y = fmaxf(pa[q].y, 0.f);
                pa[q].z = fmaxf(pa[q].z, 0.f); pa[q].w = fmaxf(pa[q].w, 0.f);
            }
            int kr = k0 + (f >> 4);
            int cc = (f & 15) << 2;
            pb[q] = *(const float4*)(Bg + (size_t)kr * 64 + cc);
        }
    };

    auto store_stage = [&]() {
#pragma unroll
        for (int q = 0; q < 4; q++) {
            int f = tid + q * 128;
            uint32_t* ad = &As[(f >> 3) * AS_STRIDE + ((f & 7) << 2)];
            ad[0] = f2tf32(pa[q].x); ad[1] = f2tf32(pa[q].y);
            ad[2] = f2tf32(pa[q].z); ad[3] = f2tf32(pa[q].w);
            uint32_t* bdst = &Bs[(f >> 4) * BS_STRIDE + ((f & 15) << 2)];
            bdst[0] = f2tf32(pb[q].x); bdst[1] = f2tf32(pb[q].y);
            bdst[2] = f2tf32(pb[q].z); bdst[3] = f2tf32(pb[q].w);
        }
    };

    load_stage(0);
    for (int s = 0; s < S; s++) {
        store_stage();
        __syncthreads();
        if (s + 1 < S) load_stage(s + 1);

#pragma unroll
        for (int k8 = 0; k8 < 32; k8 += 8) {
            uint32_t af[2][4];
#pragma unroll
            for (int i2 = 0; i2 < 2; i2++) {
                int r0 = warp_m * 32 + i2 * 16 + g;
                af[i2][0] = As[r0 * AS_STRIDE + k8 + tg];
                af[i2][1] = As[(r0 + 8) * AS_STRIDE + k8 + tg];
                af[i2][2] = As[r0 * AS_STRIDE + k8 + tg + 4];
                af[i2][3] = As[(r0 + 8) * AS_STRIDE + k8 + tg + 4];
            }
#pragma unroll
            for (int j = 0; j < 4; j++) {
                int n0 = warp_n * 32 + j * 8;
                uint32_t b0 = Bs[(k8 + tg) * BS_STRIDE + n0 + g];
                uint32_t b1 = Bs[(k8 + tg + 4) * BS_STRIDE + n0 + g];
#pragma unroll
                for (int i2 = 0; i2 < 2; i2++) {
                    asm volatile(
                        "mma.sync.aligned.m16n8k8.row.col.f32.tf32.tf32.f32 "
                        "{%0,%1,%2,%3}, {%4,%5,%6,%7}, {%8,%9}, {%0,%1,%2,%3};\n"
                        : "+f"(acc[i2][j][0]), "+f"(acc[i2][j][1]),
                          "+f"(acc[i2][j][2]), "+f"(acc[i2][j][3])
                        : "r"(af[i2][0]), "r"(af[i2][1]), "r"(af[i2][2]), "r"(af[i2][3]),
                          "r"(b0), "r"(b1));
                }
            }
        }
        __syncthreads();
    }

#pragma unroll
    for (int i2 = 0; i2 < 2; i2++) {
#pragma unroll
        for (int j = 0; j < 4; j++) {
            int col = warp_n * 32 + j * 8 + tg * 2;
#pragma unroll
            for (int q = 0; q < 4; q++) {
                int row = rowBase + warp_m * 32 + i2 * 16 + g + ((q >= 2) ? 8 : 0);
                int c = col + (q & 1);
                if (row < M) {
                    float v = acc[i2][j][q] + bc[c] + bd[c];
                    if (res) v += prev[(size_t)row * C + c];
                    Out[(size_t)row * 64 + c] = v;
                }
            }
        }
    }
}

// -------------------- kernel 6: last layer (64C -> 3) -------------------------
__global__ void out4_kernel(const float* __restrict__ A, const float* __restrict__ kern,
                            const float* __restrict__ prev, const float* __restrict__ wd,
                            const float* __restrict__ bc, const float* __restrict__ bd,
                            float* __restrict__ out4, int M, int K)
{
    int warp = (blockIdx.x * blockDim.x + threadIdx.x) >> 5;
    int lane = threadIdx.x & 31;
    if (warp >= M) return;
    float a0 = 0.f, a1 = 0.f, a2 = 0.f;
    const float* Ar = A + (size_t)warp * K;
    for (int k = lane; k < K; k += 32) {
        float av = Ar[k];
        a0 += av * kern[k * 3 + 0];
        a1 += av * kern[k * 3 + 1];
        a2 += av * kern[k * 3 + 2];
    }
    const float* pr = prev + (size_t)warp * 64;
    for (int c = lane; c < 64; c += 32) {
        float h = fmaxf(pr[c], 0.f);
        a0 += h * wd[c * 3 + 0];
        a1 += h * wd[c * 3 + 1];
        a2 += h * wd[c * 3 + 2];
    }
#pragma unroll
    for (int off = 16; off > 0; off >>= 1) {
        a0 += __shfl_down_sync(0xffffffffu, a0, off);
        a1 += __shfl_down_sync(0xffffffffu, a1, off);
        a2 += __shfl_down_sync(0xffffffffu, a2, off);
    }
    if (lane == 0) {
        out4[warp * 3 + 0] = a0 + bc[0] + bd[0];
        out4[warp * 3 + 1] = a1 + bc[1] + bd[1];
        out4[warp * 3 + 2] = a2 + bc[2] + bd[2];
    }
}

// -------------------- kernel 7: final outputs ---------------------------------
__global__ void final_kernel(const float* __restrict__ p0, const float* __restrict__ v0e,
                             float* __restrict__ outp)
{
    int n = blockIdx.x * blockDim.x + threadIdx.x;
    if (n >= NF) return;
#pragma unroll
    for (int j = 0; j < 3; j++) {
        float o0 = g_out4[n * 9 + j];                 // s=0 row
        float corr = o0 * 0.25f * (1.f / 16.f);
        float pc = g_p1[n * 3 + j] + corr;
        outp[n * 3 + j] = pc;                          // p_c
        outp[9000 + n * 3 + j] = (pc - p0[n * 3 + j]) / 0.1f;  // v_c
        outp[18000 + n * 6 + 0 + j] = g_out4[n * 9 + 3 + j] * 0.25f;  // m_matrix s=1
        outp[18000 + n * 6 + 3 + j] = g_out4[n * 9 + 6 + j] * 0.25f;  // m_matrix s=2
        outp[36000 + n * 3 + j] = v0e[n * 3 + j];      // state_feats
    }
}

// -------------------- launch --------------------------------------------------
template <typename T>
static T* sym_addr(const void* sym)
{
    void* p = nullptr;
    cudaGetSymbolAddress(&p, sym);
    return (T*)p;
}

extern "C" void kernel_launch(void* const* d_in, const int* in_sizes, int n_in,
                              void* d_out, int out_size)
{
    (void)n_in; (void)out_size;
    const float* v0e       = (const float*)d_in[1];
    const float* p0        = (const float*)d_in[2];
    const float* v0        = (const float*)d_in[3];
    const float* a         = (const float*)d_in[4];
    const float* other     = (const float*)d_in[5];
    const float* box       = (const float*)d_in[6];
    const float* box_feats = (const float*)d_in[7];
    const float* box_mask  = (const float*)d_in[9];
    const float* k0f = (const float*)d_in[10];
    const float* b0f = (const float*)d_in[11];
    const float* k0o = (const float*)d_in[12];
    const float* b0o = (const float*)d_in[13];
    const float* wdf = (const float*)d_in[14];
    const float* bdf = (const float*)d_in[15];

    // Resolve deep-layer weights 16..31 BY SIZE (robust to metadata ordering).
    const float* kcA[5] = {0, 0, 0, 0, 0};
    const float* wdA[5] = {0, 0, 0, 0, 0};
    const float* b64[6] = {0, 0, 0, 0, 0, 0};
    const float* b3[2]  = {0, 0};
    int n262 = 0, n4096 = 0, nb64 = 0, nb3 = 0;
    for (int i = 16; i < 32; i++) {
        const float* p = (const float*)d_in[i];
        switch (in_sizes[i]) {
            case 393216: kcA[1] = p; break;
            case 262144: if (n262++ == 0) kcA[2] = p; else kcA[3] = p; break;
            case 12288:  kcA[4] = p; break;
            case 6144:   wdA[1] = p; break;
            case 4096:   if (n4096++ == 0) wdA[2] = p; else wdA[3] = p; break;
            case 192:    wdA[4] = p; break;
            case 64:     if (nb64 < 6) b64[nb64++] = p; break;
            case 3:      if (nb3 < 2) b3[nb3++] = p; break;
            default: break;
        }
    }
    const float* bc1 = b64[0]; const float* bd1 = b64[1];
    const float* bc2 = b64[2]; const float* bd2 = b64[3];
    const float* bc3 = b64[4]; const float* bd3 = b64[5];
    const float* bc4 = b3[0];  const float* bd4 = b3[1];

    float* outp = (float*)d_out;

    float* pp1   = sym_addr<float>(g_p1);
    int*   pidxF = sym_addr<int>(g_idxF);
    int*   pcbF  = sym_addr<int>(g_cbF);
    float* pw8F  = sym_addr<float>(g_w8F);
    int*   pcntF = sym_addr<int>(g_cntF);
    int*   pidxB = sym_addr<int>(g_idxB);
    int*   pcbB  = sym_addr<int>(g_cbB);
    float* pw8B  = sym_addr<float>(g_w8B);
    int*   pcntB = sym_addr<int>(g_cntB);
    float* pout0 = sym_addr<float>(g_out0);
    float* pout1 = sym_addr<float>(g_out1);
    float* pout2 = sym_addr<float>(g_out2);
    float* pout3 = sym_addr<float>(g_out3);
    float* pout4 = sym_addr<float>(g_out4);
    float* pA    = sym_addr<float>(g_A);

    const int smem96 = 64 * (3 * 96) * (int)sizeof(float);  // 73728
    const int smem64 = 64 * (3 * 64) * (int)sizeof(float);  // 49152
    cudaFuncSetAttribute(scatter_warp_kernel<96>, cudaFuncAttributeMaxDynamicSharedMemorySize, smem96);
    cudaFuncSetAttribute(scatter_warp_kernel<64>, cudaFuncAttributeMaxDynamicSharedMemorySize, smem64);

    prep_kernel<<<(NF + 127) / 128, 128>>>(p0, v0, a, other, v0e);
    nbr_kernel<<<NF, 256>>>(pp1, NF, nullptr, 1, pidxF, pcbF, pw8F, pcntF);
    nbr_kernel<<<NF, 256>>>(box, NB, box_mask, 0, pidxB, pcbB, pw8B, pcntB);
    phase2_kernel<<<NF, 128>>>(box_feats, k0f, b0f, k0o, b0o, wdf, bdf);

    const int Mrows = NF * 3;  // 9000
    const int gemmGrid = (Mrows + 63) / 64;   // 141 CTAs

    // layer 1: C=96, K=6144, no residual
    scatter_warp_kernel<96><<<NF, 256, smem96>>>(pout0, pA);
    gemm_tf32_kernel<<<gemmGrid, 128>>>(pA, kcA[1], pout0, wdA[1], bc1, bd1, pout1, Mrows, 6144, 96, 0);

    // layer 2: C=64, K=4096, residual
    scatter_warp_kernel<64><<<NF, 256, smem64>>>(pout1, pA);
    gemm_tf32_kernel<<<gemmGrid, 128>>>(pA, kcA[2], pout1, wdA[2], bc2, bd2, pout2, Mrows, 4096, 64, 1);

    // layer 3: C=64, K=4096, residual
    scatter_warp_kernel<64><<<NF, 256, smem64>>>(pout2, pA);
    gemm_tf32_kernel<<<gemmGrid, 128>>>(pA, kcA[3], pout2, wdA[3], bc3, bd3, pout3, Mrows, 4096, 64, 1);

    // layer 4: C=64 -> 3 outputs
    scatter_warp_kernel<64><<<NF, 256, smem64>>>(pout3, pA);
    out4_kernel<<<(Mrows * 32 + 255) / 256, 256>>>(pA, kcA[4], pout3, wdA[4], bc4, bd4, pout4, Mrows, 4096);

    final_kernel<<<(NF + 127) / 128, 128>>>(p0, v0e, outp);
}

// round 11
// speedup vs baseline: 2.0495x; 1.2706x over previous
#include <cuda_runtime.h>
#include <math.h>
#include <stdint.h>

#define NF 3000
#define NB 1500
#define KNB 64

#define GD 9
#define GD3 729
#define GORG (-3.0f)
#define GINV (1.0f/3.0f)

// -------------------- global scratch (no runtime allocation allowed) ----------
__device__ float g_p1[NF * 3];
__device__ float g_ff[NF * 9];

__device__ int   g_idxF[NF * KNB];
__device__ int   g_cbF [NF * KNB];
__device__ float g_w8F [NF * KNB * 8];
__device__ int   g_cntF[NF];

__device__ int   g_idxB[NF * KNB];
__device__ int   g_cbB [NF * KNB];
__device__ float g_w8B [NF * KNB * 8];
__device__ int   g_cntB[NF];

__device__ int g_gcnt[2 * GD3];
__device__ int g_gstart[2 * (GD3 + 1)];
__device__ int g_gfill[2 * GD3];
__device__ int g_gsortF[NF];
__device__ int g_gsortB[NB];

__device__ float g_out0[NF * 3 * 96];
__device__ float g_out1[NF * 3 * 64];
__device__ float g_out2[NF * 3 * 64];
__device__ float g_out3[NF * 3 * 64];
__device__ float g_out4[NF * 3 * 3];

__device__ float g_A[(size_t)NF * 3 * 64 * 96];   // GEMM input scratch (max layer1)

// -------------------- helpers -------------------------------------------------
__device__ __forceinline__ float sgnf(float v) {
    return (v > 0.f) ? 1.f : ((v < 0.f) ? -1.f : 0.f);
}

__device__ __forceinline__ uint32_t f2tf32(float f) {
    uint32_t r;
    asm("cvt.rna.tf32.f32 %0, %1;" : "=r"(r) : "f"(f));
    return r;
}

__device__ __forceinline__ void cp16(uint32_t dst, const void* src) {
    asm volatile("cp.async.cg.shared.global [%0], [%1], 16;" :: "r"(dst), "l"(src) : "memory");
}

__device__ __forceinline__ int cell_id(float x, float y, float z) {
    int cx = min(max((int)floorf((x - GORG) * GINV), 0), GD - 1);
    int cy = min(max((int)floorf((y - GORG) * GINV), 0), GD - 1);
    int cz = min(max((int)floorf((z - GORG) * GINV), 0), GD - 1);
    return (cx * GD + cy) * GD + cz;
}

// Per-edge weight computation: offset (dx,dy,dz) = p_in[j] - p_out[n]
__device__ void edge_weights(float dx, float dy, float dz, float* w8, int* cbase)
{
    const float inv_r = 1.f / 3.f;     // radius = EXTENT*0.5 = 3.0
    float x = dx * inv_r, y = dy * inv_r, z = dz * inv_r;
    float sq = (x * x + y * y) + z * z;

    float win = 1.f - sq;
    win = win * win * win;
    win = fminf(fmaxf(win, 0.f), 1.f);

    // _ball_to_cube
    float norm  = sqrtf(fmaxf(sq, 1e-8f));
    float xy_sq = x * x + y * y;
    bool  polar = (1.25f * z * z > xy_sq);
    float s_p = sqrtf(3.f * norm / (norm + fabsf(z) + 1e-8f));
    float s_e = norm / sqrtf(fmaxf(xy_sq, 1e-8f));
    float cx = polar ? x * s_p : x * s_e;
    float cy = polar ? y * s_p : y * s_e;
    float cz = polar ? sgnf(z) * norm : 1.5f * z;

    float nxy = sqrtf(fmaxf(cx * cx + cy * cy, 1e-8f));
    bool  xdom = (fabsf(cy) <= fabsf(cx));
    float sx = (fabsf(cx) > 1e-8f) ? cx : 1.f;
    float sy = (fabsf(cy) > 1e-8f) ? cy : 1.f;
    const float FOPI = 1.27323954473516268615f;  // 4/pi
    float bx1 = sgnf(cx) * nxy;
    float by1 = bx1 * FOPI * atanf(cy / sx);
    float by2 = sgnf(cy) * nxy;
    float bx2 = by2 * FOPI * atanf(cx / sy);
    float bx = xdom ? bx1 : bx2;
    float by = xdom ? by1 : by2;
    if (cx * cx + cy * cy < 1e-8f) { bx = 0.f; by = 0.f; }
    float bz = cz;
    if (sq < 1e-8f) { bx = 0.f; by = 0.f; bz = 0.f; }

    float bb[3] = {bx, by, bz};
    float f[3];
    int   c0[3];
#pragma unroll
    for (int ax = 0; ax < 3; ax++) {
        float co = (bb[ax] * 0.5f + 0.5f) * 3.f;       // (KS-1)=3
        co = fminf(fmaxf(co, 0.f), 3.f);
        int ci = (int)floorf(co);
        ci = min(max(ci, 0), 2);
        c0[ax] = ci;
        f[ax] = co - (float)ci;
    }
    *cbase = (c0[0] * 4 + c0[1]) * 4 + c0[2];
#pragma unroll
    for (int r = 0; r < 8; r++) {
        int i = (r >> 2) & 1, j = (r >> 1) & 1, l = r & 1;
        float w = (i ? f[0] : 1.f - f[0]) * (j ? f[1] : 1.f - f[1]) * (l ? f[2] : 1.f - f[2]);
        w8[r] = w * win;
    }
}

__device__ __forceinline__ int corner_cell(int cb, int r) {
    return cb + ((r >> 2) & 1) * 16 + ((r >> 1) & 1) * 4 + (r & 1);
}

// -------------------- kernel 1: prep -----------------------------------------
__global__ void prep_kernel(const float* __restrict__ p0, const float* __restrict__ v0,
                            const float* __restrict__ a, const float* __restrict__ other,
                            const float* __restrict__ v0e)
{
    int n = blockIdx.x * blockDim.x + threadIdx.x;
    if (n >= NF) return;
#pragma unroll
    for (int j = 0; j < 3; j++) {
        float v0v = v0[n * 3 + j], av = a[n * 3 + j];
        float v1 = v0v + 0.1f * av;
        float p1 = p0[n * 3 + j] + 0.1f * (v0v + v1) * 0.5f;
        g_p1[n * 3 + j] = p1;
        g_ff[n * 9 + 0 + j] = v1;                // s=0 : v1
        g_ff[n * 9 + 3 + j] = other[n * 3 + j];  // s=1 : other_feats
        g_ff[n * 9 + 6 + j] = v0e[n * 3 + j];    // s=2 : v0_enc
    }
}

// -------------------- grid build ----------------------------------------------
__global__ void grid_zero_kernel()
{
    int i = blockIdx.x * blockDim.x + threadIdx.x;
    if (i < 2 * GD3) g_gcnt[i] = 0;
}

__global__ void grid_count_kernel(const float* __restrict__ box, const float* __restrict__ mask)
{
    int i = blockIdx.x * blockDim.x + threadIdx.x;
    if (i < NF)
        atomicAdd(&g_gcnt[cell_id(g_p1[i * 3], g_p1[i * 3 + 1], g_p1[i * 3 + 2])], 1);
    if (i < NB && mask[i] > 0.f)
        atomicAdd(&g_gcnt[GD3 + cell_id(box[i * 3], box[i * 3 + 1], box[i * 3 + 2])], 1);
}

__global__ void grid_scan_kernel()
{
    __shared__ int a[1024];
    int t = threadIdx.x;
    for (int part = 0; part < 2; part++) {
        int cnt = (t < GD3) ? g_gcnt[part * GD3 + t] : 0;
        a[t] = cnt;
        __syncthreads();
        for (int d = 1; d < 1024; d <<= 1) {
            int v = (t >= d) ? a[t - d] : 0;
            __syncthreads();
            a[t] += v;
            __syncthreads();
        }
        if (t < GD3) {
            g_gstart[part * (GD3 + 1) + t + 1] = a[t];
            g_gfill[part * GD3 + t] = a[t] - cnt;   // exclusive
        }
        if (t == 0) g_gstart[part * (GD3 + 1)] = 0;
        __syncthreads();
    }
}

__global__ void grid_fill_kernel(const float* __restrict__ box, const float* __restrict__ mask)
{
    int i = blockIdx.x * blockDim.x + threadIdx.x;
    if (i < NF) {
        int c = cell_id(g_p1[i * 3], g_p1[i * 3 + 1], g_p1[i * 3 + 2]);
        int p = atomicAdd(&g_gfill[c], 1);
        g_gsortF[p] = i;
    }
    if (i < NB && mask[i] > 0.f) {
        int c = cell_id(box[i * 3], box[i * 3 + 1], box[i * 3 + 2]);
        int p = atomicAdd(&g_gfill[GD3 + c], 1);
        g_gsortB[p] = i;
    }
}

// -------------------- kernel 2: grid neighbor build ---------------------------
__global__ void nbr_grid_kernel(const float* __restrict__ pts, int part, int self_exclude,
                                int* __restrict__ idx_out, int* __restrict__ cb_out,
                                float* __restrict__ w8_out, int* __restrict__ cnt_out)
{
    int n = blockIdx.x, tid = threadIdx.x;
    __shared__ float sd2[512];
    __shared__ int   sidx[512];
    __shared__ int   scnt;
    __shared__ int   cst[27];
    __shared__ int   ccum[28];

    float qx = g_p1[n * 3], qy = g_p1[n * 3 + 1], qz = g_p1[n * 3 + 2];
    if (tid == 0) scnt = 0;
    if (tid < 27) {
        int cx = min(max((int)floorf((qx - GORG) * GINV), 0), GD - 1);
        int cy = min(max((int)floorf((qy - GORG) * GINV), 0), GD - 1);
        int cz = min(max((int)floorf((qz - GORG) * GINV), 0), GD - 1);
        int nx = cx + tid / 9 - 1;
        int ny = cy + (tid / 3) % 3 - 1;
        int nz = cz + tid % 3 - 1;
        int st = 0, len = 0;
        if (nx >= 0 && nx < GD && ny >= 0 && ny < GD && nz >= 0 && nz < GD) {
            int c = (nx * GD + ny) * GD + nz;
            st = g_gstart[part * (GD3 + 1) + c];
            len = g_gstart[part * (GD3 + 1) + c + 1] - st;
        }
        cst[tid] = st;
        ccum[tid + 1] = len;
    }
    __syncthreads();
    if (tid == 0) {
        ccum[0] = 0;
        for (int k = 1; k <= 27; k++) ccum[k] += ccum[k - 1];
    }
    __syncthreads();
    int T = ccum[27];
    const int* sorted = part ? g_gsortB : g_gsortF;

    for (int t = tid; t < T; t += blockDim.x) {
        int seg = 0;
        while (t >= ccum[seg + 1]) seg++;
        int j = sorted[cst[seg] + t - ccum[seg]];
        if (self_exclude && j == n) continue;
        float dx = pts[j * 3] - qx, dy = pts[j * 3 + 1] - qy, dz = pts[j * 3 + 2] - qz;
        float d2 = (dx * dx + dy * dy) + dz * dz;
        if (d2 < 9.0f) {
            int p = atomicAdd(&scnt, 1);
            if (p < 512) { sd2[p] = d2; sidx[p] = j; }
        }
    }
    __syncthreads();
    int cnt = min(scnt, 512);

    // Sort ONLY if more than KNB candidates (set membership is order-free).
    if (cnt > KNB) {
        int P = 1;
        while (P < cnt) P <<= 1;
        for (int i = cnt + tid; i < P; i += blockDim.x) { sd2[i] = 3.0e38f; sidx[i] = 0x7fffffff; }
        __syncthreads();
        for (int k = 2; k <= P; k <<= 1) {
            for (int j2 = k >> 1; j2 > 0; j2 >>= 1) {
                for (int i = tid; i < P; i += blockDim.x) {
                    int ixj = i ^ j2;
                    if (ixj > i) {
                        float a = sd2[i], b = sd2[ixj];
                        int ia = sidx[i], ib = sidx[ixj];
                        bool agtb = (a > b) || ((a == b) && (ia > ib));
                        bool up = ((i & k) == 0);
                        if (agtb == up) { sd2[i] = b; sd2[ixj] = a; sidx[i] = ib; sidx[ixj] = ia; }
                    }
                }
                __syncthreads();
            }
        }
        cnt = KNB;
    }

    if (tid == 0) cnt_out[n] = cnt;
    if (tid < cnt) {
        int j = sidx[tid];
        float dx = pts[j * 3] - qx, dy = pts[j * 3 + 1] - qy, dz = pts[j * 3 + 2] - qz;
        float w8[8];
        int cb;
        edge_weights(dx, dy, dz, w8, &cb);
        int e = n * KNB + tid;
        idx_out[e] = j;
        cb_out[e] = cb;
#pragma unroll
        for (int r = 0; r < 8; r++) w8_out[e * 8 + r] = w8[r];
    }
}

// -------------------- kernel 3: phase-2 (cf + co + df -> out0), CSR gather ----
__global__ void __launch_bounds__(128) phase2_kernel(
    const float* __restrict__ box_feats,
    const float* __restrict__ k0f, const float* __restrict__ b0f,
    const float* __restrict__ k0o, const float* __restrict__ b0o,
    const float* __restrict__ wdf, const float* __restrict__ bdf)
{
    int n = blockIdx.x, tid = threadIdx.x;
    __shared__ float  F[64 * 12];       // fluid neighbor feats, stride 12
    __shared__ float  bfv[64];
    __shared__ float2 entF[512];
    __shared__ float2 entB[512];
    __shared__ int scF[64], scB[64];
    __shared__ int startF[65], startB[65];
    __shared__ int fillF[64], fillB[64];
    __shared__ int ejF[64], ecbF[64];
    __shared__ int ejB[64], ecbB[64];
    __shared__ float ewF[512], ewB[512];
    __shared__ float cF[576];   // 64 cells x 9
    __shared__ float cB[64];

    int cntF = g_cntF[n];
    int cntB = g_cntB[n];

    if (tid < 64) { scF[tid] = 0; scB[tid] = 0; }
    if (tid < cntF) { ejF[tid] = g_idxF[n * KNB + tid]; ecbF[tid] = g_cbF[n * KNB + tid]; }
    {
        int t = tid - 64;
        if (t >= 0 && t < cntB) { ejB[t] = g_idxB[n * KNB + t]; ecbB[t] = g_cbB[n * KNB + t]; }
    }
    for (int i = tid; i < cntF * 8; i += 128) ewF[i] = g_w8F[n * KNB * 8 + i];
    for (int i = tid; i < cntB * 8; i += 128) ewB[i] = g_w8B[n * KNB * 8 + i];
    __syncthreads();

    // count
    if (tid < cntF) {
        int cb = ecbF[tid];
#pragma unroll
        for (int r = 0; r < 8; r++) atomicAdd(&scF[corner_cell(cb, r)], 1);
    } else if (tid >= 64 && tid - 64 < cntB) {
        int cb = ecbB[tid - 64];
#pragma unroll
        for (int r = 0; r < 8; r++) atomicAdd(&scB[corner_cell(cb, r)], 1);
    }
    __syncthreads();
    // inclusive scan of both count arrays
    for (int d = 1; d < 64; d <<= 1) {
        int v = 0;
        if (tid < 64) { if (tid >= d) v = scF[tid - d]; }
        else { int t = tid - 64; if (t >= d) v = scB[t - d]; }
        __syncthreads();
        if (tid < 64) { if (tid >= d) scF[tid] += v; }
        else { int t = tid - 64; if (t >= d) scB[t] += v; }
        __syncthreads();
    }
    if (tid < 64) {
        startF[tid + 1] = scF[tid];
        fillF[tid] = (tid == 0) ? 0 : scF[tid - 1];
        if (tid == 0) startF[0] = 0;
    } else {
        int t = tid - 64;
        startB[t + 1] = scB[t];
        fillB[t] = (t == 0) ? 0 : scB[t - 1];
        if (t == 0) startB[0] = 0;
    }
    __syncthreads();
    // fill
    if (tid < cntF) {
        int cb = ecbF[tid];
#pragma unroll
        for (int r = 0; r < 8; r++) {
            int l = corner_cell(cb, r);
            int pos = atomicAdd(&fillF[l], 1);
            entF[pos] = make_float2(ewF[tid * 8 + r], __int_as_float(tid));
        }
    } else if (tid >= 64 && tid - 64 < cntB) {
        int e = tid - 64;
        int cb = ecbB[e];
#pragma unroll
        for (int r = 0; r < 8; r++) {
            int l = corner_cell(cb, r);
            int pos = atomicAdd(&fillB[l], 1);
            entB[pos] = make_float2(ewB[e * 8 + r], __int_as_float(e));
        }
    }
    // gather features
    for (int i = tid; i < cntF * 9; i += 128) {
        int e = i / 9, c = i % 9;
        F[e * 12 + c] = g_ff[ejF[e] * 9 + c];
    }
    for (int i = tid; i < cntB; i += 128) bfv[i] = box_feats[ejB[i]];
    __syncthreads();

    // accumulate: thread < 64 owns one cell
    if (tid < 64) {
        int l = tid;
        float acc[9];
#pragma unroll
        for (int c = 0; c < 9; c++) acc[c] = 0.f;
        for (int k = startF[l]; k < startF[l + 1]; k++) {
            float2 we = entF[k];
            float w = we.x;
            int e = __float_as_int(we.y);
#pragma unroll
            for (int c = 0; c < 9; c++) acc[c] += w * F[e * 12 + c];
        }
#pragma unroll
        for (int c = 0; c < 9; c++) cF[l * 9 + c] = acc[c];
        float ab = 0.f;
        for (int k = startB[l]; k < startB[l + 1]; k++) {
            float2 we = entB[k];
            ab += we.x * bfv[__float_as_int(we.y)];
        }
        cB[l] = ab;
    }
    __syncthreads();

    if (tid < 96) {
        int s = tid / 32, o = tid % 32;
        float co = b0o[o];
        for (int l = 0; l < 64; l++) co += cB[l] * k0o[l * 32 + o];
        float cf = b0f[o];
        for (int l = 0; l < 64; l++) {
#pragma unroll
            for (int c = 0; c < 3; c++) cf += cF[l * 9 + s * 3 + c] * k0f[(l * 3 + c) * 32 + o];
        }
        float df = bdf[o];
#pragma unroll
        for (int c = 0; c < 3; c++) df += g_ff[n * 9 + s * 3 + c] * wdf[c * 32 + o];
        int base = n * 288 + s * 96;
        g_out0[base + o]      = co;   // concat order: [co, cf, df]
        g_out0[base + 32 + o] = cf;
        g_out0[base + 64 + o] = df;
    }
}

// -------------------- kernel 4: warp-per-cell CSR gather scatter --------------
template <int C>
__global__ void __launch_bounds__(256) scatter_warp_kernel(
    const float* __restrict__ prev, float* __restrict__ Aout)
{
    constexpr int SC = 3 * C;          // 288 or 192
    constexpr int PF = SC / 32;        // floats per lane: 9 or 6
    int n = blockIdx.x;
    int tid = threadIdx.x, lane = tid & 31, wid = tid >> 5;

    extern __shared__ float H[];       // [64][SC]
    __shared__ float2 ent[512];
    __shared__ int   scc[64];
    __shared__ int   cellStart[65];
    __shared__ int   fillPos[64];
    __shared__ int   ej[64];
    __shared__ int   ecb[64];
    __shared__ float ew[512];

    int cnt = g_cntF[n];
    if (tid < 64) scc[tid] = 0;
    if (tid < cnt) { ej[tid] = g_idxF[n * KNB + tid]; ecb[tid] = g_cbF[n * KNB + tid]; }
    for (int i = tid; i < cnt * 8; i += 256) ew[i] = g_w8F[n * KNB * 8 + i];
    __syncthreads();

    if (tid < cnt) {
        int cb = ecb[tid];
#pragma unroll
        for (int r = 0; r < 8; r++) atomicAdd(&scc[corner_cell(cb, r)], 1);
    }
    __syncthreads();
    for (int d = 1; d < 64; d <<= 1) {
        int v = 0;
        if (tid < 64 && tid >= d) v = scc[tid - d];
        __syncthreads();
        if (tid < 64 && tid >= d) scc[tid] += v;
        __syncthreads();
    }
    if (tid < 64) {
        cellStart[tid + 1] = scc[tid];
        fillPos[tid] = (tid == 0) ? 0 : scc[tid - 1];
        if (tid == 0) cellStart[0] = 0;
    }
    __syncthreads();
    if (tid < cnt) {
        int cb = ecb[tid];
#pragma unroll
        for (int r = 0; r < 8; r++) {
            int l = corner_cell(cb, r);
            int pos = atomicAdd(&fillPos[l], 1);
            ent[pos] = make_float2(ew[tid * 8 + r], __int_as_float(tid));
        }
    }
    for (int i = tid; i < cnt * (SC / 4); i += 256) {
        int e = i / (SC / 4), q = i % (SC / 4);
        float4 v = *(const float4*)(prev + (size_t)ej[e] * SC + q * 4);
        v.x = fmaxf(v.x, 0.f); v.y = fmaxf(v.y, 0.f);
        v.z = fmaxf(v.z, 0.f); v.w = fmaxf(v.w, 0.f);
        *(float4*)&H[e * SC + q * 4] = v;
    }
    __syncthreads();

    for (int l = wid; l < 64; l += 8) {
        float acc[PF];
#pragma unroll
        for (int i = 0; i < PF; i++) acc[i] = 0.f;
        int k1 = cellStart[l + 1];
        for (int k = cellStart[l]; k < k1; k++) {
            float2 we = ent[k];
            float w = we.x;
            const float* hr = &H[__float_as_int(we.y) * SC];
#pragma unroll
            for (int i = 0; i < PF; i++) acc[i] += w * hr[i * 32 + lane];
        }
#pragma unroll
        for (int i = 0; i < PF; i++) {
            int ch = i * 32 + lane;
            int s = ch / C, c = ch - s * C;
            Aout[(size_t)(n * 3 + s) * (64 * C) + l * C + c] = acc[i];
        }
    }
}

// -------------------- kernel 5: cp.async pipelined TF32 GEMM ------------------
// Out[row,o] = sum_k A[row,k]*Bk[k,o] + sum_c relu(prev[row,c])*wd[c,o]
//              + bc[o]+bd[o] + (res ? prev[row,o] : 0).  Tile 32x64, 128 thr.
#define PIPE 3
#define GA_STRIDE 36
#define GB_STRIDE 72
#define A_STAGE (32 * GA_STRIDE)   // 1152 floats
#define B_STAGE (32 * GB_STRIDE)   // 2304 floats

__global__ void __launch_bounds__(128) gemm_tf32_async(
    const float* __restrict__ A, const float* __restrict__ Bk,
    const float* __restrict__ prev, const float* __restrict__ wd,
    const float* __restrict__ bc, const float* __restrict__ bd,
    float* __restrict__ Out, int M, int K, int C, int res)
{
    __shared__ float sA[PIPE * A_STAGE];
    __shared__ float sB[PIPE * B_STAGE];

    int tid = threadIdx.x, lane = tid & 31, warp = tid >> 5;
    int wm = warp >> 1, wn = warp & 1;
    int g = lane >> 2, tg = lane & 3;
    int rowBase = blockIdx.x * 32;
    int stages0 = K / 32;
    int S = stages0 + C / 32;

    uint32_t sAu = (uint32_t)__cvta_generic_to_shared(sA);
    uint32_t sBu = (uint32_t)__cvta_generic_to_shared(sB);

    float acc[4][4];
#pragma unroll
    for (int j = 0; j < 4; j++)
#pragma unroll
        for (int q = 0; q < 4; q++) acc[j][q] = 0.f;

    auto issue = [&](int s) {
        int b = s % PIPE;
        bool seg = (s >= stages0);
        const float* Ag = seg ? prev : A;
        const float* Bg = seg ? wd : Bk;
        int Ks = seg ? C : K;
        int k0 = (seg ? s - stages0 : s) * 32;
#pragma unroll
        for (int q = 0; q < 2; q++) {
            int f = tid + q * 128, r = f >> 3, c4 = f & 7;
            int rg = min(rowBase + r, M - 1);
            cp16(sAu + (uint32_t)(b * A_STAGE + r * GA_STRIDE + c4 * 4) * 4,
                 Ag + (size_t)rg * Ks + k0 + c4 * 4);
        }
#pragma unroll
        for (int q = 0; q < 4; q++) {
            int f = tid + q * 128, kr = f >> 4, c4 = f & 15;
            cp16(sBu + (uint32_t)(b * B_STAGE + kr * GB_STRIDE + c4 * 4) * 4,
                 Bg + (size_t)(k0 + kr) * 64 + c4 * 4);
        }
        asm volatile("cp.async.commit_group;" ::: "memory");
    };

    issue(0);
    issue(1);
    for (int s = 0; s < S; s++) {
        if (s + 1 < S) asm volatile("cp.async.wait_group 1;" ::: "memory");
        else           asm volatile("cp.async.wait_group 0;" ::: "memory");
        __syncthreads();
        if (s + 2 < S) issue(s + 2);

        int b = s % PIPE;
        bool seg = (s >= stages0);
        const float* Ab = sA + b * A_STAGE;
        const float* Bb = sB + b * B_STAGE;
#pragma unroll
        for (int k8 = 0; k8 < 32; k8 += 8) {
            float a0 = Ab[(wm * 16 + g) * GA_STRIDE + k8 + tg];
            float a1 = Ab[(wm * 16 + g + 8) * GA_STRIDE + k8 + tg];
            float a2 = Ab[(wm * 16 + g) * GA_STRIDE + k8 + tg + 4];
            float a3 = Ab[(wm * 16 + g + 8) * GA_STRIDE + k8 + tg + 4];
            if (seg) {
                a0 = fmaxf(a0, 0.f); a1 = fmaxf(a1, 0.f);
                a2 = fmaxf(a2, 0.f); a3 = fmaxf(a3, 0.f);
            }
            uint32_t ua0 = f2tf32(a0), ua1 = f2tf32(a1);
            uint32_t ua2 = f2tf32(a2), ua3 = f2tf32(a3);
#pragma unroll
            for (int j = 0; j < 4; j++) {
                int n0 = wn * 32 + j * 8;
                uint32_t ub0 = f2tf32(Bb[(k8 + tg) * GB_STRIDE + n0 + g]);
                uint32_t ub1 = f2tf32(Bb[(k8 + tg + 4) * GB_STRIDE + n0 + g]);
                asm volatile(
                    "mma.sync.aligned.m16n8k8.row.col.f32.tf32.tf32.f32 "
                    "{%0,%1,%2,%3}, {%4,%5,%6,%7}, {%8,%9}, {%0,%1,%2,%3};\n"
                    : "+f"(acc[j][0]), "+f"(acc[j][1]),
                      "+f"(acc[j][2]), "+f"(acc[j][3])
                    : "r"(ua0), "r"(ua1), "r"(ua2), "r"(ua3),
                      "r"(ub0), "r"(ub1));
            }
        }
        __syncthreads();
    }

    // epilogue
#pragma unroll
    for (int j = 0; j < 4; j++) {
        int col = wn * 32 + j * 8 + tg * 2;
#pragma unroll
        for (int q = 0; q < 4; q++) {
            int row = rowBase + wm * 16 + g + ((q >= 2) ? 8 : 0);
            int c = col + (q & 1);
            if (row < M) {
                float v = acc[j][q] + bc[c] + bd[c];
                if (res) v += prev[(size_t)row * C + c];
                Out[(size_t)row * 64 + c] = v;
            }
        }
    }
}

// -------------------- kernel 6: last layer (64C -> 3) -------------------------
__global__ void out4_kernel(const float* __restrict__ A, const float* __restrict__ kern,
                            const float* __restrict__ prev, const float* __restrict__ wd,
                            const float* __restrict__ bc, const float* __restrict__ bd,
                            float* __restrict__ out4, int M, int K)
{
    int warp = (blockIdx.x * blockDim.x + threadIdx.x) >> 5;
    int lane = threadIdx.x & 31;
    if (warp >= M) return;
    float a0 = 0.f, a1 = 0.f, a2 = 0.f;
    const float* Ar = A + (size_t)warp * K;
    for (int k = lane; k < K; k += 32) {
        float av = Ar[k];
        a0 += av * kern[k * 3 + 0];
        a1 += av * kern[k * 3 + 1];
        a2 += av * kern[k * 3 + 2];
    }
    const float* pr = prev + (size_t)warp * 64;
    for (int c = lane; c < 64; c += 32) {
        float h = fmaxf(pr[c], 0.f);
        a0 += h * wd[c * 3 + 0];
        a1 += h * wd[c * 3 + 1];
        a2 += h * wd[c * 3 + 2];
    }
#pragma unroll
    for (int off = 16; off > 0; off >>= 1) {
        a0 += __shfl_down_sync(0xffffffffu, a0, off);
        a1 += __shfl_down_sync(0xffffffffu, a1, off);
        a2 += __shfl_down_sync(0xffffffffu, a2, off);
    }
    if (lane == 0) {
        out4[warp * 3 + 0] = a0 + bc[0] + bd[0];
        out4[warp * 3 + 1] = a1 + bc[1] + bd[1];
        out4[warp * 3 + 2] = a2 + bc[2] + bd[2];
    }
}

// -------------------- kernel 7: final outputs ---------------------------------
__global__ void final_kernel(const float* __restrict__ p0, const float* __restrict__ v0e,
                             float* __restrict__ outp)
{
    int n = blockIdx.x * blockDim.x + threadIdx.x;
    if (n >= NF) return;
#pragma unroll
    for (int j = 0; j < 3; j++) {
        float o0 = g_out4[n * 9 + j];                 // s=0 row
        float corr = o0 * 0.25f * (1.f / 16.f);
        float pc = g_p1[n * 3 + j] + corr;
        outp[n * 3 + j] = pc;                          // p_c
        outp[9000 + n * 3 + j] = (pc - p0[n * 3 + j]) / 0.1f;  // v_c
        outp[18000 + n * 6 + 0 + j] = g_out4[n * 9 + 3 + j] * 0.25f;  // m_matrix s=1
        outp[18000 + n * 6 + 3 + j] = g_out4[n * 9 + 6 + j] * 0.25f;  // m_matrix s=2
        outp[36000 + n * 3 + j] = v0e[n * 3 + j];      // state_feats
    }
}

// -------------------- launch --------------------------------------------------
template <typename T>
static T* sym_addr(const void* sym)
{
    void* p = nullptr;
    cudaGetSymbolAddress(&p, sym);
    return (T*)p;
}

extern "C" void kernel_launch(void* const* d_in, const int* in_sizes, int n_in,
                              void* d_out, int out_size)
{
    (void)n_in; (void)out_size;
    const float* v0e       = (const float*)d_in[1];
    const float* p0        = (const float*)d_in[2];
    const float* v0        = (const float*)d_in[3];
    const float* a         = (const float*)d_in[4];
    const float* other     = (const float*)d_in[5];
    const float* box       = (const float*)d_in[6];
    const float* box_feats = (const float*)d_in[7];
    const float* box_mask  = (const float*)d_in[9];
    const float* k0f = (const float*)d_in[10];
    const float* b0f = (const float*)d_in[11];
    const float* k0o = (const float*)d_in[12];
    const float* b0o = (const float*)d_in[13];
    const float* wdf = (const float*)d_in[14];
    const float* bdf = (const float*)d_in[15];

    // Resolve deep-layer weights 16..31 BY SIZE (robust to metadata ordering).
    const float* kcA[5] = {0, 0, 0, 0, 0};
    const float* wdA[5] = {0, 0, 0, 0, 0};
    const float* b64[6] = {0, 0, 0, 0, 0, 0};
    const float* b3[2]  = {0, 0};
    int n262 = 0, n4096 = 0, nb64 = 0, nb3 = 0;
    for (int i = 16; i < 32; i++) {
        const float* p = (const float*)d_in[i];
        switch (in_sizes[i]) {
            case 393216: kcA[1] = p; break;
            case 262144: if (n262++ == 0) kcA[2] = p; else kcA[3] = p; break;
            case 12288:  kcA[4] = p; break;
            case 6144:   wdA[1] = p; break;
            case 4096:   if (n4096++ == 0) wdA[2] = p; else wdA[3] = p; break;
            case 192:    wdA[4] = p; break;
            case 64:     if (nb64 < 6) b64[nb64++] = p; break;
            case 3:      if (nb3 < 2) b3[nb3++] = p; break;
            default: break;
        }
    }
    const float* bc1 = b64[0]; const float* bd1 = b64[1];
    const float* bc2 = b64[2]; const float* bd2 = b64[3];
    const float* bc3 = b64[4]; const float* bd3 = b64[5];
    const float* bc4 = b3[0];  const float* bd4 = b3[1];

    float* outp = (float*)d_out;

    float* pp1   = sym_addr<float>(g_p1);
    int*   pidxF = sym_addr<int>(g_idxF);
    int*   pcbF  = sym_addr<int>(g_cbF);
    float* pw8F  = sym_addr<float>(g_w8F);
    int*   pcntF = sym_addr<int>(g_cntF);
    int*   pidxB = sym_addr<int>(g_idxB);
    int*   pcbB  = sym_addr<int>(g_cbB);
    float* pw8B  = sym_addr<float>(g_w8B);
    int*   pcntB = sym_addr<int>(g_cntB);
    float* pout0 = sym_addr<float>(g_out0);
    float* pout1 = sym_addr<float>(g_out1);
    float* pout2 = sym_addr<float>(g_out2);
    float* pout3 = sym_addr<float>(g_out3);
    float* pout4 = sym_addr<float>(g_out4);
    float* pA    = sym_addr<float>(g_A);

    const int smem96 = 64 * (3 * 96) * (int)sizeof(float);  // 73728
    const int smem64 = 64 * (3 * 64) * (int)sizeof(float);  // 49152
    cudaFuncSetAttribute(scatter_warp_kernel<96>, cudaFuncAttributeMaxDynamicSharedMemorySize, smem96);
    cudaFuncSetAttribute(scatter_warp_kernel<64>, cudaFuncAttributeMaxDynamicSharedMemorySize, smem64);

    prep_kernel<<<(NF + 127) / 128, 128>>>(p0, v0, a, other, v0e);

    // grid build (fluid on p1, box with mask)
    grid_zero_kernel<<<(2 * GD3 + 255) / 256, 256>>>();
    grid_count_kernel<<<(NF + 255) / 256, 256>>>(box, box_mask);
    grid_scan_kernel<<<1, 1024>>>();
    grid_fill_kernel<<<(NF + 255) / 256, 256>>>(box, box_mask);

    nbr_grid_kernel<<<NF, 128>>>(pp1, 0, 1, pidxF, pcbF, pw8F, pcntF);
    nbr_grid_kernel<<<NF, 128>>>(box, 1, 0, pidxB, pcbB, pw8B, pcntB);
    phase2_kernel<<<NF, 128>>>(box_feats, k0f, b0f, k0o, b0o, wdf, bdf);

    const int Mrows = NF * 3;  // 9000
    const int gemmGrid = (Mrows + 31) / 32;   // 282 CTAs

    // layer 1: C=96, K=6144, no residual
    scatter_warp_kernel<96><<<NF, 256, smem96>>>(pout0, pA);
    gemm_tf32_async<<<gemmGrid, 128>>>(pA, kcA[1], pout0, wdA[1], bc1, bd1, pout1, Mrows, 6144, 96, 0);

    // layer 2: C=64, K=4096, residual
    scatter_warp_kernel<64><<<NF, 256, smem64>>>(pout1, pA);
    gemm_tf32_async<<<gemmGrid, 128>>>(pA, kcA[2], pout1, wdA[2], bc2, bd2, pout2, Mrows, 4096, 64, 1);

    // layer 3: C=64, K=4096, residual
    scatter_warp_kernel<64><<<NF, 256, smem64>>>(pout2, pA);
    gemm_tf32_async<<<gemmGrid, 128>>>(pA, kcA[3], pout2, wdA[3], bc3, bd3, pout3, Mrows, 4096, 64, 1);

    // layer 4: C=64 -> 3 outputs
    scatter_warp_kernel<64><<<NF, 256, smem64>>>(pout3, pA);
    out4_kernel<<<(Mrows * 32 + 255) / 256, 256>>>(pA, kcA[4], pout3, wdA[4], bc4, bd4, pout4, Mrows, 4096);

    final_kernel<<<(NF + 127) / 128, 128>>>(p0, v0e, outp);
}

// round 12
// speedup vs baseline: 2.2476x; 1.0967x over previous
#include <cuda_runtime.h>
#include <cuda_fp16.h>
#include <math.h>
#include <stdint.h>

#define NF 3000
#define NB 1500
#define KNB 64

#define GD 9
#define GD3 729
#define GORG (-3.0f)
#define GINV (1.0f/3.0f)

// -------------------- global scratch (no runtime allocation allowed) ----------
__device__ float g_p1[NF * 3];
__device__ float g_ff[NF * 9];

__device__ int   g_idxF[NF * KNB];
__device__ int   g_cbF [NF * KNB];
__device__ float g_w8F [NF * KNB * 8];
__device__ int   g_cntF[NF];

__device__ int   g_idxB[NF * KNB];
__device__ int   g_cbB [NF * KNB];
__device__ float g_w8B [NF * KNB * 8];
__device__ int   g_cntB[NF];

__device__ int g_gcnt[2 * GD3];
__device__ int g_gstart[2 * (GD3 + 1)];
__device__ int g_gfill[2 * GD3];
__device__ int g_gsortF[NF];
__device__ int g_gsortB[NB];

__device__ float  g_out0 [NF * 3 * 96];
__device__ __half g_out0h[NF * 3 * 96];
__device__ float  g_out1 [NF * 3 * 64];
__device__ __half g_out1h[NF * 3 * 64];
__device__ float  g_out2 [NF * 3 * 64];
__device__ __half g_out2h[NF * 3 * 64];
__device__ float  g_out3 [NF * 3 * 64];
__device__ __half g_out3h[NF * 3 * 64];
__device__ float  g_out4 [NF * 3 * 3];

__device__ __half g_Ah[(size_t)NF * 3 * 64 * 96];   // GEMM input scratch (half)

// transposed fp16 weights [64 out][K]
__device__ __half g_kh1[64 * 6144];
__device__ __half g_kh2[64 * 4096];
__device__ __half g_kh3[64 * 4096];
__device__ __half g_wh1[64 * 96];
__device__ __half g_wh2[64 * 64];
__device__ __half g_wh3[64 * 64];

// -------------------- helpers -------------------------------------------------
__device__ __forceinline__ float sgnf(float v) {
    return (v > 0.f) ? 1.f : ((v < 0.f) ? -1.f : 0.f);
}

__device__ __forceinline__ void cp16(uint32_t dst, const void* src) {
    asm volatile("cp.async.cg.shared.global [%0], [%1], 16;" :: "r"(dst), "l"(src) : "memory");
}

__device__ __forceinline__ int cell_id(float x, float y, float z) {
    int cx = min(max((int)floorf((x - GORG) * GINV), 0), GD - 1);
    int cy = min(max((int)floorf((y - GORG) * GINV), 0), GD - 1);
    int cz = min(max((int)floorf((z - GORG) * GINV), 0), GD - 1);
    return (cx * GD + cy) * GD + cz;
}

// Per-edge weight computation: offset (dx,dy,dz) = p_in[j] - p_out[n]
__device__ void edge_weights(float dx, float dy, float dz, float* w8, int* cbase)
{
    const float inv_r = 1.f / 3.f;     // radius = EXTENT*0.5 = 3.0
    float x = dx * inv_r, y = dy * inv_r, z = dz * inv_r;
    float sq = (x * x + y * y) + z * z;

    float win = 1.f - sq;
    win = win * win * win;
    win = fminf(fmaxf(win, 0.f), 1.f);

    float norm  = sqrtf(fmaxf(sq, 1e-8f));
    float xy_sq = x * x + y * y;
    bool  polar = (1.25f * z * z > xy_sq);
    float s_p = sqrtf(3.f * norm / (norm + fabsf(z) + 1e-8f));
    float s_e = norm / sqrtf(fmaxf(xy_sq, 1e-8f));
    float cx = polar ? x * s_p : x * s_e;
    float cy = polar ? y * s_p : y * s_e;
    float cz = polar ? sgnf(z) * norm : 1.5f * z;

    float nxy = sqrtf(fmaxf(cx * cx + cy * cy, 1e-8f));
    bool  xdom = (fabsf(cy) <= fabsf(cx));
    float sx = (fabsf(cx) > 1e-8f) ? cx : 1.f;
    float sy = (fabsf(cy) > 1e-8f) ? cy : 1.f;
    const float FOPI = 1.27323954473516268615f;  // 4/pi
    float bx1 = sgnf(cx) * nxy;
    float by1 = bx1 * FOPI * atanf(cy / sx);
    float by2 = sgnf(cy) * nxy;
    float bx2 = by2 * FOPI * atanf(cx / sy);
    float bx = xdom ? bx1 : bx2;
    float by = xdom ? by1 : by2;
    if (cx * cx + cy * cy < 1e-8f) { bx = 0.f; by = 0.f; }
    float bz = cz;
    if (sq < 1e-8f) { bx = 0.f; by = 0.f; bz = 0.f; }

    float bb[3] = {bx, by, bz};
    float f[3];
    int   c0[3];
#pragma unroll
    for (int ax = 0; ax < 3; ax++) {
        float co = (bb[ax] * 0.5f + 0.5f) * 3.f;       // (KS-1)=3
        co = fminf(fmaxf(co, 0.f), 3.f);
        int ci = (int)floorf(co);
        ci = min(max(ci, 0), 2);
        c0[ax] = ci;
        f[ax] = co - (float)ci;
    }
    *cbase = (c0[0] * 4 + c0[1]) * 4 + c0[2];
#pragma unroll
    for (int r = 0; r < 8; r++) {
        int i = (r >> 2) & 1, j = (r >> 1) & 1, l = r & 1;
        float w = (i ? f[0] : 1.f - f[0]) * (j ? f[1] : 1.f - f[1]) * (l ? f[2] : 1.f - f[2]);
        w8[r] = w * win;
    }
}

__device__ __forceinline__ int corner_cell(int cb, int r) {
    return cb + ((r >> 2) & 1) * 16 + ((r >> 1) & 1) * 4 + (r & 1);
}

// -------------------- kernel 1: prep -----------------------------------------
__global__ void prep_kernel(const float* __restrict__ p0, const float* __restrict__ v0,
                            const float* __restrict__ a, const float* __restrict__ other,
                            const float* __restrict__ v0e)
{
    int n = blockIdx.x * blockDim.x + threadIdx.x;
    if (n >= NF) return;
#pragma unroll
    for (int j = 0; j < 3; j++) {
        float v0v = v0[n * 3 + j], av = a[n * 3 + j];
        float v1 = v0v + 0.1f * av;
        float p1 = p0[n * 3 + j] + 0.1f * (v0v + v1) * 0.5f;
        g_p1[n * 3 + j] = p1;
        g_ff[n * 9 + 0 + j] = v1;
        g_ff[n * 9 + 3 + j] = other[n * 3 + j];
        g_ff[n * 9 + 6 + j] = v0e[n * 3 + j];
    }
}

// -------------------- weight convert+transpose (fp32 -> fp16) -----------------
__global__ void wconv_kernel(const float* __restrict__ kc1, const float* __restrict__ kc2,
                             const float* __restrict__ kc3, const float* __restrict__ wd1,
                             const float* __restrict__ wd2, const float* __restrict__ wd3)
{
    const int R1 = 64 * 6144, R2 = 64 * 4096, R3 = 64 * 4096;
    const int W1 = 64 * 96, W2 = 64 * 64;
    int i = blockIdx.x * blockDim.x + threadIdx.x;
    int total = R1 + R2 + R3 + W1 + W2 + W2;
    for (; i < total; i += gridDim.x * blockDim.x) {
        int t = i;
        if (t < R1) { int n = t / 6144, k = t % 6144; g_kh1[t] = __float2half_rn(kc1[k * 64 + n]); continue; }
        t -= R1;
        if (t < R2) { int n = t / 4096, k = t % 4096; g_kh2[t] = __float2half_rn(kc2[k * 64 + n]); continue; }
        t -= R2;
        if (t < R3) { int n = t / 4096, k = t % 4096; g_kh3[t] = __float2half_rn(kc3[k * 64 + n]); continue; }
        t -= R3;
        if (t < W1) { int n = t / 96, c = t % 96; g_wh1[t] = __float2half_rn(wd1[c * 64 + n]); continue; }
        t -= W1;
        if (t < W2) { int n = t / 64, c = t % 64; g_wh2[t] = __float2half_rn(wd2[c * 64 + n]); continue; }
        t -= W2;
        { int n = t / 64, c = t % 64; g_wh3[t] = __float2half_rn(wd3[c * 64 + n]); }
    }
}

// -------------------- grid build ----------------------------------------------
__global__ void grid_zero_kernel()
{
    int i = blockIdx.x * blockDim.x + threadIdx.x;
    if (i < 2 * GD3) g_gcnt[i] = 0;
}

__global__ void grid_count_kernel(const float* __restrict__ box, const float* __restrict__ mask)
{
    int i = blockIdx.x * blockDim.x + threadIdx.x;
    if (i < NF)
        atomicAdd(&g_gcnt[cell_id(g_p1[i * 3], g_p1[i * 3 + 1], g_p1[i * 3 + 2])], 1);
    if (i < NB && mask[i] > 0.f)
        atomicAdd(&g_gcnt[GD3 + cell_id(box[i * 3], box[i * 3 + 1], box[i * 3 + 2])], 1);
}

__global__ void grid_scan_kernel()
{
    __shared__ int a[1024];
    int t = threadIdx.x;
    for (int part = 0; part < 2; part++) {
        int cnt = (t < GD3) ? g_gcnt[part * GD3 + t] : 0;
        a[t] = cnt;
        __syncthreads();
        for (int d = 1; d < 1024; d <<= 1) {
            int v = (t >= d) ? a[t - d] : 0;
            __syncthreads();
            a[t] += v;
            __syncthreads();
        }
        if (t < GD3) {
            g_gstart[part * (GD3 + 1) + t + 1] = a[t];
            g_gfill[part * GD3 + t] = a[t] - cnt;
        }
        if (t == 0) g_gstart[part * (GD3 + 1)] = 0;
        __syncthreads();
    }
}

__global__ void grid_fill_kernel(const float* __restrict__ box, const float* __restrict__ mask)
{
    int i = blockIdx.x * blockDim.x + threadIdx.x;
    if (i < NF) {
        int c = cell_id(g_p1[i * 3], g_p1[i * 3 + 1], g_p1[i * 3 + 2]);
        int p = atomicAdd(&g_gfill[c], 1);
        g_gsortF[p] = i;
    }
    if (i < NB && mask[i] > 0.f) {
        int c = cell_id(box[i * 3], box[i * 3 + 1], box[i * 3 + 2]);
        int p = atomicAdd(&g_gfill[GD3 + c], 1);
        g_gsortB[p] = i;
    }
}

// -------------------- kernel 2: grid neighbor build ---------------------------
__global__ void nbr_grid_kernel(const float* __restrict__ pts, int part, int self_exclude,
                                int* __restrict__ idx_out, int* __restrict__ cb_out,
                                float* __restrict__ w8_out, int* __restrict__ cnt_out)
{
    int n = blockIdx.x, tid = threadIdx.x;
    __shared__ float sd2[512];
    __shared__ int   sidx[512];
    __shared__ int   scnt;
    __shared__ int   cst[27];
    __shared__ int   ccum[28];

    float qx = g_p1[n * 3], qy = g_p1[n * 3 + 1], qz = g_p1[n * 3 + 2];
    if (tid == 0) scnt = 0;
    if (tid < 27) {
        int cx = min(max((int)floorf((qx - GORG) * GINV), 0), GD - 1);
        int cy = min(max((int)floorf((qy - GORG) * GINV), 0), GD - 1);
        int cz = min(max((int)floorf((qz - GORG) * GINV), 0), GD - 1);
        int nx = cx + tid / 9 - 1;
        int ny = cy + (tid / 3) % 3 - 1;
        int nz = cz + tid % 3 - 1;
        int st = 0, len = 0;
        if (nx >= 0 && nx < GD && ny >= 0 && ny < GD && nz >= 0 && nz < GD) {
            int c = (nx * GD + ny) * GD + nz;
            st = g_gstart[part * (GD3 + 1) + c];
            len = g_gstart[part * (GD3 + 1) + c + 1] - st;
        }
        cst[tid] = st;
        ccum[tid + 1] = len;
    }
    __syncthreads();
    if (tid == 0) {
        ccum[0] = 0;
        for (int k = 1; k <= 27; k++) ccum[k] += ccum[k - 1];
    }
    __syncthreads();
    int T = ccum[27];
    const int* sorted = part ? g_gsortB : g_gsortF;

    for (int t = tid; t < T; t += blockDim.x) {
        int seg = 0;
        while (t >= ccum[seg + 1]) seg++;
        int j = sorted[cst[seg] + t - ccum[seg]];
        if (self_exclude && j == n) continue;
        float dx = pts[j * 3] - qx, dy = pts[j * 3 + 1] - qy, dz = pts[j * 3 + 2] - qz;
        float d2 = (dx * dx + dy * dy) + dz * dz;
        if (d2 < 9.0f) {
            int p = atomicAdd(&scnt, 1);
            if (p < 512) { sd2[p] = d2; sidx[p] = j; }
        }
    }
    __syncthreads();
    int cnt = min(scnt, 512);

    if (cnt > KNB) {
        int P = 1;
        while (P < cnt) P <<= 1;
        for (int i = cnt + tid; i < P; i += blockDim.x) { sd2[i] = 3.0e38f; sidx[i] = 0x7fffffff; }
        __syncthreads();
        for (int k = 2; k <= P; k <<= 1) {
            for (int j2 = k >> 1; j2 > 0; j2 >>= 1) {
                for (int i = tid; i < P; i += blockDim.x) {
                    int ixj = i ^ j2;
                    if (ixj > i) {
                        float a = sd2[i], b = sd2[ixj];
                        int ia = sidx[i], ib = sidx[ixj];
                        bool agtb = (a > b) || ((a == b) && (ia > ib));
                        bool up = ((i & k) == 0);
                        if (agtb == up) { sd2[i] = b; sd2[ixj] = a; sidx[i] = ib; sidx[ixj] = ia; }
                    }
                }
                __syncthreads();
            }
        }
        cnt = KNB;
    }

    if (tid == 0) cnt_out[n] = cnt;
    if (tid < cnt) {
        int j = sidx[tid];
        float dx = pts[j * 3] - qx, dy = pts[j * 3 + 1] - qy, dz = pts[j * 3 + 2] - qz;
        float w8[8];
        int cb;
        edge_weights(dx, dy, dz, w8, &cb);
        int e = n * KNB + tid;
        idx_out[e] = j;
        cb_out[e] = cb;
#pragma unroll
        for (int r = 0; r < 8; r++) w8_out[e * 8 + r] = w8[r];
    }
}

// -------------------- kernel 3: phase-2 (cf + co + df -> out0), CSR gather ----
__global__ void __launch_bounds__(128) phase2_kernel(
    const float* __restrict__ box_feats,
    const float* __restrict__ k0f, const float* __restrict__ b0f,
    const float* __restrict__ k0o, const float* __restrict__ b0o,
    const float* __restrict__ wdf, const float* __restrict__ bdf)
{
    int n = blockIdx.x, tid = threadIdx.x;
    __shared__ float  F[64 * 12];
    __shared__ float  bfv[64];
    __shared__ float2 entF[512];
    __shared__ float2 entB[512];
    __shared__ int scF[64], scB[64];
    __shared__ int startF[65], startB[65];
    __shared__ int fillF[64], fillB[64];
    __shared__ int ejF[64], ecbF[64];
    __shared__ int ejB[64], ecbB[64];
    __shared__ float ewF[512], ewB[512];
    __shared__ float cF[576];
    __shared__ float cB[64];

    int cntF = g_cntF[n];
    int cntB = g_cntB[n];

    if (tid < 64) { scF[tid] = 0; scB[tid] = 0; }
    if (tid < cntF) { ejF[tid] = g_idxF[n * KNB + tid]; ecbF[tid] = g_cbF[n * KNB + tid]; }
    {
        int t = tid - 64;
        if (t >= 0 && t < cntB) { ejB[t] = g_idxB[n * KNB + t]; ecbB[t] = g_cbB[n * KNB + t]; }
    }
    for (int i = tid; i < cntF * 8; i += 128) ewF[i] = g_w8F[n * KNB * 8 + i];
    for (int i = tid; i < cntB * 8; i += 128) ewB[i] = g_w8B[n * KNB * 8 + i];
    __syncthreads();

    if (tid < cntF) {
        int cb = ecbF[tid];
#pragma unroll
        for (int r = 0; r < 8; r++) atomicAdd(&scF[corner_cell(cb, r)], 1);
    } else if (tid >= 64 && tid - 64 < cntB) {
        int cb = ecbB[tid - 64];
#pragma unroll
        for (int r = 0; r < 8; r++) atomicAdd(&scB[corner_cell(cb, r)], 1);
    }
    __syncthreads();
    for (int d = 1; d < 64; d <<= 1) {
        int v = 0;
        if (tid < 64) { if (tid >= d) v = scF[tid - d]; }
        else { int t = tid - 64; if (t >= d) v = scB[t - d]; }
        __syncthreads();
        if (tid < 64) { if (tid >= d) scF[tid] += v; }
        else { int t = tid - 64; if (t >= d) scB[t] += v; }
        __syncthreads();
    }
    if (tid < 64) {
        startF[tid + 1] = scF[tid];
        fillF[tid] = (tid == 0) ? 0 : scF[tid - 1];
        if (tid == 0) startF[0] = 0;
    } else {
        int t = tid - 64;
        startB[t + 1] = scB[t];
        fillB[t] = (t == 0) ? 0 : scB[t - 1];
        if (t == 0) startB[0] = 0;
    }
    __syncthreads();
    if (tid < cntF) {
        int cb = ecbF[tid];
#pragma unroll
        for (int r = 0; r < 8; r++) {
            int l = corner_cell(cb, r);
            int pos = atomicAdd(&fillF[l], 1);
            entF[pos] = make_float2(ewF[tid * 8 + r], __int_as_float(tid));
        }
    } else if (tid >= 64 && tid - 64 < cntB) {
        int e = tid - 64;
        int cb = ecbB[e];
#pragma unroll
        for (int r = 0; r < 8; r++) {
            int l = corner_cell(cb, r);
            int pos = atomicAdd(&fillB[l], 1);
            entB[pos] = make_float2(ewB[e * 8 + r], __int_as_float(e));
        }
    }
    for (int i = tid; i < cntF * 9; i += 128) {
        int e = i / 9, c = i % 9;
        F[e * 12 + c] = g_ff[ejF[e] * 9 + c];
    }
    for (int i = tid; i < cntB; i += 128) bfv[i] = box_feats[ejB[i]];
    __syncthreads();

    if (tid < 64) {
        int l = tid;
        float acc[9];
#pragma unroll
        for (int c = 0; c < 9; c++) acc[c] = 0.f;
        for (int k = startF[l]; k < startF[l + 1]; k++) {
            float2 we = entF[k];
            float w = we.x;
            int e = __float_as_int(we.y);
#pragma unroll
            for (int c = 0; c < 9; c++) acc[c] += w * F[e * 12 + c];
        }
#pragma unroll
        for (int c = 0; c < 9; c++) cF[l * 9 + c] = acc[c];
        float ab = 0.f;
        for (int k = startB[l]; k < startB[l + 1]; k++) {
            float2 we = entB[k];
            ab += we.x * bfv[__float_as_int(we.y)];
        }
        cB[l] = ab;
    }
    __syncthreads();

    if (tid < 96) {
        int s = tid / 32, o = tid % 32;
        float co = b0o[o];
        for (int l = 0; l < 64; l++) co += cB[l] * k0o[l * 32 + o];
        float cf = b0f[o];
        for (int l = 0; l < 64; l++) {
#pragma unroll
            for (int c = 0; c < 3; c++) cf += cF[l * 9 + s * 3 + c] * k0f[(l * 3 + c) * 32 + o];
        }
        float df = bdf[o];
#pragma unroll
        for (int c = 0; c < 3; c++) df += g_ff[n * 9 + s * 3 + c] * wdf[c * 32 + o];
        int base = n * 288 + s * 96;
        g_out0[base + o]      = co;
        g_out0[base + 32 + o] = cf;
        g_out0[base + 64 + o] = df;
        g_out0h[base + o]      = __float2half_rn(fmaxf(co, 0.f));
        g_out0h[base + 32 + o] = __float2half_rn(fmaxf(cf, 0.f));
        g_out0h[base + 64 + o] = __float2half_rn(fmaxf(df, 0.f));
    }
}

// -------------------- kernel 4: warp-per-cell CSR gather scatter (half I/O) ---
// prevh: 3000 rows of (3*C) RELU'D half features. Writes Ah (9000 x 64C) half.
template <int C>
__global__ void __launch_bounds__(256) scatter_warp_kernel(
    const __half* __restrict__ prevh, __half* __restrict__ Aout)
{
    constexpr int SC = 3 * C;          // 288 or 192
    constexpr int PF = SC / 32;        // floats per lane: 9 or 6
    int n = blockIdx.x;
    int tid = threadIdx.x, lane = tid & 31, wid = tid >> 5;

    extern __shared__ float H[];       // [64][SC]
    __shared__ float2 ent[512];
    __shared__ int   scc[64];
    __shared__ int   cellStart[65];
    __shared__ int   fillPos[64];
    __shared__ int   ej[64];
    __shared__ int   ecb[64];
    __shared__ float ew[512];

    int cnt = g_cntF[n];
    if (tid < 64) scc[tid] = 0;
    if (tid < cnt) { ej[tid] = g_idxF[n * KNB + tid]; ecb[tid] = g_cbF[n * KNB + tid]; }
    for (int i = tid; i < cnt * 8; i += 256) ew[i] = g_w8F[n * KNB * 8 + i];
    __syncthreads();

    if (tid < cnt) {
        int cb = ecb[tid];
#pragma unroll
        for (int r = 0; r < 8; r++) atomicAdd(&scc[corner_cell(cb, r)], 1);
    }
    __syncthreads();
    for (int d = 1; d < 64; d <<= 1) {
        int v = 0;
        if (tid < 64 && tid >= d) v = scc[tid - d];
        __syncthreads();
        if (tid < 64 && tid >= d) scc[tid] += v;
        __syncthreads();
    }
    if (tid < 64) {
        cellStart[tid + 1] = scc[tid];
        fillPos[tid] = (tid == 0) ? 0 : scc[tid - 1];
        if (tid == 0) cellStart[0] = 0;
    }
    __syncthreads();
    if (tid < cnt) {
        int cb = ecb[tid];
#pragma unroll
        for (int r = 0; r < 8; r++) {
            int l = corner_cell(cb, r);
            int pos = atomicAdd(&fillPos[l], 1);
            ent[pos] = make_float2(ew[tid * 8 + r], __int_as_float(tid));
        }
    }
    // gather H rows (already relu'd half -> float), 8 halfs per iteration
    for (int i = tid; i < cnt * (SC / 8); i += 256) {
        int e = i / (SC / 8), q = i % (SC / 8);
        const __half2* src = (const __half2*)(prevh + (size_t)ej[e] * SC + q * 8);
        float* dst = &H[e * SC + q * 8];
#pragma unroll
        for (int h2 = 0; h2 < 4; h2++) {
            float2 f = __half22float2(src[h2]);
            dst[h2 * 2 + 0] = f.x;
            dst[h2 * 2 + 1] = f.y;
        }
    }
    __syncthreads();

    for (int l = wid; l < 64; l += 8) {
        float acc[PF];
#pragma unroll
        for (int i = 0; i < PF; i++) acc[i] = 0.f;
        int k1 = cellStart[l + 1];
        for (int k = cellStart[l]; k < k1; k++) {
            float2 we = ent[k];
            float w = we.x;
            const float* hr = &H[__float_as_int(we.y) * SC];
#pragma unroll
            for (int i = 0; i < PF; i++) acc[i] += w * hr[i * 32 + lane];
        }
#pragma unroll
        for (int i = 0; i < PF; i++) {
            int ch = i * 32 + lane;
            int s = ch / C, c = ch - s * C;
            Aout[(size_t)(n * 3 + s) * (64 * C) + l * C + c] = __float2half_rn(acc[i]);
        }
    }
}

// -------------------- kernel 5: cp.async pipelined FP16 GEMM ------------------
// Out[row,o] = sum_k Ah[row,k]*BhT[o,k] + sum_c prevh[row,c]*wdhT[o,c]
//              + bc[o]+bd[o] + (res ? prevf[row,o] : 0).   Tile 32x64, 128 thr.
// Also writes Outh = half(relu(Out)).
#define PIPE 3
#define HA_ST 40                      // half stride per A row
#define A_STAGE (32 * HA_ST)          // halfs
#define B_STAGE (64 * HA_ST)          // halfs

__global__ void __launch_bounds__(128) gemm_fp16_async(
    const __half* __restrict__ Ah, const __half* __restrict__ BhT,
    const __half* __restrict__ prevh, const __half* __restrict__ wdhT,
    const float* __restrict__ prevf,
    const float* __restrict__ bc, const float* __restrict__ bd,
    float* __restrict__ Out, __half* __restrict__ Outh,
    int M, int K, int C, int res)
{
    __shared__ __half sA[PIPE * A_STAGE];
    __shared__ __half sB[PIPE * B_STAGE];

    int tid = threadIdx.x, lane = tid & 31, warp = tid >> 5;
    int wm = warp >> 1, wn = warp & 1;
    int g = lane >> 2, tg = lane & 3;
    int rowBase = blockIdx.x * 32;
    int stages0 = K / 32;
    int S = stages0 + C / 32;

    uint32_t sAu = (uint32_t)__cvta_generic_to_shared(sA);
    uint32_t sBu = (uint32_t)__cvta_generic_to_shared(sB);

    float acc[4][4];
#pragma unroll
    for (int j = 0; j < 4; j++)
#pragma unroll
        for (int q = 0; q < 4; q++) acc[j][q] = 0.f;

    auto issue = [&](int s) {
        int b = s % PIPE;
        bool seg = (s >= stages0);
        const __half* Ag = seg ? prevh : Ah;
        const __half* Bg = seg ? wdhT : BhT;
        int Ks = seg ? C : K;
        int k0 = (seg ? s - stages0 : s) * 32;
        // A: 32 rows x 32 halfs = 128 x 16B
        {
            int r = tid >> 2, sg = tid & 3;
            int rg = min(rowBase + r, M - 1);
            cp16(sAu + (uint32_t)(b * A_STAGE + r * HA_ST + sg * 8) * 2,
                 Ag + (size_t)rg * Ks + k0 + sg * 8);
        }
        // B: 64 rows x 32 halfs = 256 x 16B
#pragma unroll
        for (int q = 0; q < 2; q++) {
            int f = tid + q * 128;
            int nr = f >> 2, sg = f & 3;
            cp16(sBu + (uint32_t)(b * B_STAGE + nr * HA_ST + sg * 8) * 2,
                 Bg + (size_t)nr * Ks + k0 + sg * 8);
        }
        asm volatile("cp.async.commit_group;" ::: "memory");
    };

    issue(0);
    issue(1);
    for (int s = 0; s < S; s++) {
        if (s + 1 < S) asm volatile("cp.async.wait_group 1;" ::: "memory");
        else           asm volatile("cp.async.wait_group 0;" ::: "memory");
        __syncthreads();
        if (s + 2 < S) issue(s + 2);

        int b = s % PIPE;
        const __half* Ab = sA + b * A_STAGE;
        const __half* Bb = sB + b * B_STAGE;
#pragma unroll
        for (int k16 = 0; k16 < 32; k16 += 16) {
            uint32_t ua0 = *(const uint32_t*)&Ab[(wm * 16 + g) * HA_ST + k16 + 2 * tg];
            uint32_t ua1 = *(const uint32_t*)&Ab[(wm * 16 + g + 8) * HA_ST + k16 + 2 * tg];
            uint32_t ua2 = *(const uint32_t*)&Ab[(wm * 16 + g) * HA_ST + k16 + 2 * tg + 8];
            uint32_t ua3 = *(const uint32_t*)&Ab[(wm * 16 + g + 8) * HA_ST + k16 + 2 * tg + 8];
#pragma unroll
            for (int j = 0; j < 4; j++) {
                int n0 = wn * 32 + j * 8;
                uint32_t ub0 = *(const uint32_t*)&Bb[(n0 + g) * HA_ST + k16 + 2 * tg];
                uint32_t ub1 = *(const uint32_t*)&Bb[(n0 + g) * HA_ST + k16 + 2 * tg + 8];
                asm volatile(
                    "mma.sync.aligned.m16n8k16.row.col.f32.f16.f16.f32 "
                    "{%0,%1,%2,%3}, {%4,%5,%6,%7}, {%8,%9}, {%0,%1,%2,%3};\n"
                    : "+f"(acc[j][0]), "+f"(acc[j][1]),
                      "+f"(acc[j][2]), "+f"(acc[j][3])
                    : "r"(ua0), "r"(ua1), "r"(ua2), "r"(ua3),
                      "r"(ub0), "r"(ub1));
            }
        }
        __syncthreads();
    }

    // epilogue
#pragma unroll
    for (int j = 0; j < 4; j++) {
        int col = wn * 32 + j * 8 + tg * 2;
#pragma unroll
        for (int q = 0; q < 4; q++) {
            int row = rowBase + wm * 16 + g + ((q >= 2) ? 8 : 0);
            int c = col + (q & 1);
            if (row < M) {
                float v = acc[j][q] + bc[c] + bd[c];
                if (res) v += prevf[(size_t)row * C + c];
                Out[(size_t)row * 64 + c] = v;
                Outh[(size_t)row * 64 + c] = __float2half_rn(fmaxf(v, 0.f));
            }
        }
    }
}

// -------------------- kernel 6: last layer (64C -> 3) -------------------------
__global__ void out4_kernel(const __half* __restrict__ A, const float* __restrict__ kern,
                            const __half* __restrict__ prevh, const float* __restrict__ wd,
                            const float* __restrict__ bc, const float* __restrict__ bd,
                            float* __restrict__ out4, int M, int K)
{
    int warp = (blockIdx.x * blockDim.x + threadIdx.x) >> 5;
    int lane = threadIdx.x & 31;
    if (warp >= M) return;
    float a0 = 0.f, a1 = 0.f, a2 = 0.f;
    const __half* Ar = A + (size_t)warp * K;
    for (int k = lane; k < K; k += 32) {
        float av = __half2float(Ar[k]);
        a0 += av * kern[k * 3 + 0];
        a1 += av * kern[k * 3 + 1];
        a2 += av * kern[k * 3 + 2];
    }
    const __half* pr = prevh + (size_t)warp * 64;
    for (int c = lane; c < 64; c += 32) {
        float h = __half2float(pr[c]);   // already relu'd
        a0 += h * wd[c * 3 + 0];
        a1 += h * wd[c * 3 + 1];
        a2 += h * wd[c * 3 + 2];
    }
#pragma unroll
    for (int off = 16; off > 0; off >>= 1) {
        a0 += __shfl_down_sync(0xffffffffu, a0, off);
        a1 += __shfl_down_sync(0xffffffffu, a1, off);
        a2 += __shfl_down_sync(0xffffffffu, a2, off);
    }
    if (lane == 0) {
        out4[warp * 3 + 0] = a0 + bc[0] + bd[0];
        out4[warp * 3 + 1] = a1 + bc[1] + bd[1];
        out4[warp * 3 + 2] = a2 + bc[2] + bd[2];
    }
}

// -------------------- kernel 7: final outputs ---------------------------------
__global__ void final_kernel(const float* __restrict__ p0, const float* __restrict__ v0e,
                             float* __restrict__ outp)
{
    int n = blockIdx.x * blockDim.x + threadIdx.x;
    if (n >= NF) return;
#pragma unroll
    for (int j = 0; j < 3; j++) {
        float o0 = g_out4[n * 9 + j];
        float corr = o0 * 0.25f * (1.f / 16.f);
        float pc = g_p1[n * 3 + j] + corr;
        outp[n * 3 + j] = pc;
        outp[9000 + n * 3 + j] = (pc - p0[n * 3 + j]) / 0.1f;
        outp[18000 + n * 6 + 0 + j] = g_out4[n * 9 + 3 + j] * 0.25f;
        outp[18000 + n * 6 + 3 + j] = g_out4[n * 9 + 6 + j] * 0.25f;
        outp[36000 + n * 3 + j] = v0e[n * 3 + j];
    }
}

// -------------------- launch --------------------------------------------------
template <typename T>
static T* sym_addr(const void* sym)
{
    void* p = nullptr;
    cudaGetSymbolAddress(&p, sym);
    return (T*)p;
}

extern "C" void kernel_launch(void* const* d_in, const int* in_sizes, int n_in,
                              void* d_out, int out_size)
{
    (void)n_in; (void)out_size;
    const float* v0e       = (const float*)d_in[1];
    const float* p0        = (const float*)d_in[2];
    const float* v0        = (const float*)d_in[3];
    const float* a         = (const float*)d_in[4];
    const float* other     = (const float*)d_in[5];
    const float* box       = (const float*)d_in[6];
    const float* box_feats = (const float*)d_in[7];
    const float* box_mask  = (const float*)d_in[9];
    const float* k0f = (const float*)d_in[10];
    const float* b0f = (const float*)d_in[11];
    const float* k0o = (const float*)d_in[12];
    const float* b0o = (const float*)d_in[13];
    const float* wdf = (const float*)d_in[14];
    const float* bdf = (const float*)d_in[15];

    // Resolve deep-layer weights 16..31 BY SIZE (robust to metadata ordering).
    const float* kcA[5] = {0, 0, 0, 0, 0};
    const float* wdA[5] = {0, 0, 0, 0, 0};
    const float* b64[6] = {0, 0, 0, 0, 0, 0};
    const float* b3[2]  = {0, 0};
    int n262 = 0, n4096 = 0, nb64 = 0, nb3 = 0;
    for (int i = 16; i < 32; i++) {
        const float* p = (const float*)d_in[i];
        switch (in_sizes[i]) {
            case 393216: kcA[1] = p; break;
            case 262144: if (n262++ == 0) kcA[2] = p; else kcA[3] = p; break;
            case 12288:  kcA[4] = p; break;
            case 6144:   wdA[1] = p; break;
            case 4096:   if (n4096++ == 0) wdA[2] = p; else wdA[3] = p; break;
            case 192:    wdA[4] = p; break;
            case 64:     if (nb64 < 6) b64[nb64++] = p; break;
            case 3:      if (nb3 < 2) b3[nb3++] = p; break;
            default: break;
        }
    }
    const float* bc1 = b64[0]; const float* bd1 = b64[1];
    const float* bc2 = b64[2]; const float* bd2 = b64[3];
    const float* bc3 = b64[4]; const float* bd3 = b64[5];
    const float* bc4 = b3[0];  const float* bd4 = b3[1];

    float* outp = (float*)d_out;

    float*  pp1   = sym_addr<float>(g_p1);
    int*    pidxF = sym_addr<int>(g_idxF);
    int*    pcbF  = sym_addr<int>(g_cbF);
    float*  pw8F  = sym_addr<float>(g_w8F);
    int*    pcntF = sym_addr<int>(g_cntF);
    int*    pidxB = sym_addr<int>(g_idxB);
    int*    pcbB  = sym_addr<int>(g_cbB);
    float*  pw8B  = sym_addr<float>(g_w8B);
    int*    pcntB = sym_addr<int>(g_cntB);
    float*  pout0  = sym_addr<float>(g_out0);
    __half* pout0h = sym_addr<__half>(g_out0h);
    float*  pout1  = sym_addr<float>(g_out1);
    __half* pout1h = sym_addr<__half>(g_out1h);
    float*  pout2  = sym_addr<float>(g_out2);
    __half* pout2h = sym_addr<__half>(g_out2h);
    float*  pout3  = sym_addr<float>(g_out3);
    __half* pout3h = sym_addr<__half>(g_out3h);
    float*  pout4  = sym_addr<float>(g_out4);
    __half* pAh   = sym_addr<__half>(g_Ah);
    __half* pkh1  = sym_addr<__half>(g_kh1);
    __half* pkh2  = sym_addr<__half>(g_kh2);
    __half* pkh3  = sym_addr<__half>(g_kh3);
    __half* pwh1  = sym_addr<__half>(g_wh1);
    __half* pwh2  = sym_addr<__half>(g_wh2);
    __half* pwh3  = sym_addr<__half>(g_wh3);

    const int smem96 = 64 * (3 * 96) * (int)sizeof(float);  // 73728
    const int smem64 = 64 * (3 * 64) * (int)sizeof(float);  // 49152
    cudaFuncSetAttribute(scatter_warp_kernel<96>, cudaFuncAttributeMaxDynamicSharedMemorySize, smem96);
    cudaFuncSetAttribute(scatter_warp_kernel<64>, cudaFuncAttributeMaxDynamicSharedMemorySize, smem64);

    prep_kernel<<<(NF + 127) / 128, 128>>>(p0, v0, a, other, v0e);
    wconv_kernel<<<592, 256>>>(kcA[1], kcA[2], kcA[3], wdA[1], wdA[2], wdA[3]);

    // grid build (fluid on p1, box with mask)
    grid_zero_kernel<<<(2 * GD3 + 255) / 256, 256>>>();
    grid_count_kernel<<<(NF + 255) / 256, 256>>>(box, box_mask);
    grid_scan_kernel<<<1, 1024>>>();
    grid_fill_kernel<<<(NF + 255) / 256, 256>>>(box, box_mask);

    nbr_grid_kernel<<<NF, 128>>>(pp1, 0, 1, pidxF, pcbF, pw8F, pcntF);
    nbr_grid_kernel<<<NF, 128>>>(box, 1, 0, pidxB, pcbB, pw8B, pcntB);
    phase2_kernel<<<NF, 128>>>(box_feats, k0f, b0f, k0o, b0o, wdf, bdf);

    const int Mrows = NF * 3;  // 9000
    const int gemmGrid = (Mrows + 31) / 32;   // 282 CTAs

    // layer 1: C=96, K=6144, no residual
    scatter_warp_kernel<96><<<NF, 256, smem96>>>(pout0h, pAh);
    gemm_fp16_async<<<gemmGrid, 128>>>(pAh, pkh1, pout0h, pwh1, pout0, bc1, bd1,
                                       pout1, pout1h, Mrows, 6144, 96, 0);

    // layer 2: C=64, K=4096, residual
    scatter_warp_kernel<64><<<NF, 256, smem64>>>(pout1h, pAh);
    gemm_fp16_async<<<gemmGrid, 128>>>(pAh, pkh2, pout1h, pwh2, pout1, bc2, bd2,
                                       pout2, pout2h, Mrows, 4096, 64, 1);

    // layer 3: C=64, K=4096, residual
    scatter_warp_kernel<64><<<NF, 256, smem64>>>(pout2h, pAh);
    gemm_fp16_async<<<gemmGrid, 128>>>(pAh, pkh3, pout2h, pwh3, pout2, bc3, bd3,
                                       pout3, pout3h, Mrows, 4096, 64, 1);

    // layer 4: C=64 -> 3 outputs
    scatter_warp_kernel<64><<<NF, 256, smem64>>>(pout3h, pAh);
    out4_kernel<<<(Mrows * 32 + 255) / 256, 256>>>(pAh, kcA[4], pout3h, wdA[4], bc4, bd4,
                                                   pout4, Mrows, 4096);

    final_kernel<<<(NF + 127) / 128, 128>>>(p0, v0e, outp);
}

// round 13
// speedup vs baseline: 2.4168x; 1.0752x over previous
#include <cuda_runtime.h>
#include <cuda_fp16.h>
#include <math.h>
#include <stdint.h>

#define NF 3000
#define NB 1500
#define KNB 64

#define GD 9
#define GD3 729
#define GORG (-3.0f)
#define GINV (1.0f/3.0f)

// -------------------- global scratch (no runtime allocation allowed) ----------
__device__ float g_p1[NF * 3];
__device__ float g_ff[NF * 9];

__device__ int   g_idxF[NF * KNB];
__device__ int   g_cbF [NF * KNB];
__device__ float g_w8F [NF * KNB * 8];
__device__ int   g_cntF[NF];

__device__ int   g_idxB[NF * KNB];
__device__ int   g_cbB [NF * KNB];
__device__ float g_w8B [NF * KNB * 8];
__device__ int   g_cntB[NF];

__device__ int g_gcnt[2 * GD3];
__device__ int g_gstart[2 * (GD3 + 1)];
__device__ int g_gfill[2 * GD3];
__device__ int g_gsortF[NF];
__device__ int g_gsortB[NB];

__device__ float  g_out0 [NF * 3 * 96];
__device__ __half g_out0h[NF * 3 * 96];
__device__ float  g_out1 [NF * 3 * 64];
__device__ __half g_out1h[NF * 3 * 64];
__device__ float  g_out2 [NF * 3 * 64];
__device__ __half g_out2h[NF * 3 * 64];
__device__ float  g_out3 [NF * 3 * 64];
__device__ __half g_out3h[NF * 3 * 64];

__device__ __half g_Ah[(size_t)NF * 3 * 64 * 96];   // GEMM input scratch (half)

// transposed fp16 weights [64 out][K]
__device__ __half g_kh1[64 * 6144];
__device__ __half g_kh2[64 * 4096];
__device__ __half g_kh3[64 * 4096];
__device__ __half g_wh1[64 * 96];
__device__ __half g_wh2[64 * 64];
__device__ __half g_wh3[64 * 64];

// -------------------- helpers -------------------------------------------------
__device__ __forceinline__ float sgnf(float v) {
    return (v > 0.f) ? 1.f : ((v < 0.f) ? -1.f : 0.f);
}

__device__ __forceinline__ void cp16(uint32_t dst, const void* src) {
    asm volatile("cp.async.cg.shared.global [%0], [%1], 16;" :: "r"(dst), "l"(src) : "memory");
}

__device__ __forceinline__ int cell_id(float x, float y, float z) {
    int cx = min(max((int)floorf((x - GORG) * GINV), 0), GD - 1);
    int cy = min(max((int)floorf((y - GORG) * GINV), 0), GD - 1);
    int cz = min(max((int)floorf((z - GORG) * GINV), 0), GD - 1);
    return (cx * GD + cy) * GD + cz;
}

// Per-edge weight computation: offset (dx,dy,dz) = p_in[j] - p_out[n]
__device__ void edge_weights(float dx, float dy, float dz, float* w8, int* cbase)
{
    const float inv_r = 1.f / 3.f;     // radius = EXTENT*0.5 = 3.0
    float x = dx * inv_r, y = dy * inv_r, z = dz * inv_r;
    float sq = (x * x + y * y) + z * z;

    float win = 1.f - sq;
    win = win * win * win;
    win = fminf(fmaxf(win, 0.f), 1.f);

    float norm  = sqrtf(fmaxf(sq, 1e-8f));
    float xy_sq = x * x + y * y;
    bool  polar = (1.25f * z * z > xy_sq);
    float s_p = sqrtf(3.f * norm / (norm + fabsf(z) + 1e-8f));
    float s_e = norm / sqrtf(fmaxf(xy_sq, 1e-8f));
    float cx = polar ? x * s_p : x * s_e;
    float cy = polar ? y * s_p : y * s_e;
    float cz = polar ? sgnf(z) * norm : 1.5f * z;

    float nxy = sqrtf(fmaxf(cx * cx + cy * cy, 1e-8f));
    bool  xdom = (fabsf(cy) <= fabsf(cx));
    float sx = (fabsf(cx) > 1e-8f) ? cx : 1.f;
    float sy = (fabsf(cy) > 1e-8f) ? cy : 1.f;
    const float FOPI = 1.27323954473516268615f;  // 4/pi
    float bx1 = sgnf(cx) * nxy;
    float by1 = bx1 * FOPI * atanf(cy / sx);
    float by2 = sgnf(cy) * nxy;
    float bx2 = by2 * FOPI * atanf(cx / sy);
    float bx = xdom ? bx1 : bx2;
    float by = xdom ? by1 : by2;
    if (cx * cx + cy * cy < 1e-8f) { bx = 0.f; by = 0.f; }
    float bz = cz;
    if (sq < 1e-8f) { bx = 0.f; by = 0.f; bz = 0.f; }

    float bb[3] = {bx, by, bz};
    float f[3];
    int   c0[3];
#pragma unroll
    for (int ax = 0; ax < 3; ax++) {
        float co = (bb[ax] * 0.5f + 0.5f) * 3.f;       // (KS-1)=3
        co = fminf(fmaxf(co, 0.f), 3.f);
        int ci = (int)floorf(co);
        ci = min(max(ci, 0), 2);
        c0[ax] = ci;
        f[ax] = co - (float)ci;
    }
    *cbase = (c0[0] * 4 + c0[1]) * 4 + c0[2];
#pragma unroll
    for (int r = 0; r < 8; r++) {
        int i = (r >> 2) & 1, j = (r >> 1) & 1, l = r & 1;
        float w = (i ? f[0] : 1.f - f[0]) * (j ? f[1] : 1.f - f[1]) * (l ? f[2] : 1.f - f[2]);
        w8[r] = w * win;
    }
}

__device__ __forceinline__ int corner_cell(int cb, int r) {
    return cb + ((r >> 2) & 1) * 16 + ((r >> 1) & 1) * 4 + (r & 1);
}

// -------------------- kernel 1: prep -----------------------------------------
__global__ void prep_kernel(const float* __restrict__ p0, const float* __restrict__ v0,
                            const float* __restrict__ a, const float* __restrict__ other,
                            const float* __restrict__ v0e)
{
    int n = blockIdx.x * blockDim.x + threadIdx.x;
    if (n >= NF) return;
#pragma unroll
    for (int j = 0; j < 3; j++) {
        float v0v = v0[n * 3 + j], av = a[n * 3 + j];
        float v1 = v0v + 0.1f * av;
        float p1 = p0[n * 3 + j] + 0.1f * (v0v + v1) * 0.5f;
        g_p1[n * 3 + j] = p1;
        g_ff[n * 9 + 0 + j] = v1;
        g_ff[n * 9 + 3 + j] = other[n * 3 + j];
        g_ff[n * 9 + 6 + j] = v0e[n * 3 + j];
    }
}

// -------------------- weight convert+transpose (fp32 -> fp16) -----------------
__global__ void wconv_kernel(const float* __restrict__ kc1, const float* __restrict__ kc2,
                             const float* __restrict__ kc3, const float* __restrict__ wd1,
                             const float* __restrict__ wd2, const float* __restrict__ wd3)
{
    const int R1 = 64 * 6144, R2 = 64 * 4096, R3 = 64 * 4096;
    const int W1 = 64 * 96, W2 = 64 * 64;
    int i = blockIdx.x * blockDim.x + threadIdx.x;
    int total = R1 + R2 + R3 + W1 + W2 + W2;
    for (; i < total; i += gridDim.x * blockDim.x) {
        int t = i;
        if (t < R1) { int n = t / 6144, k = t % 6144; g_kh1[t] = __float2half_rn(kc1[k * 64 + n]); continue; }
        t -= R1;
        if (t < R2) { int n = t / 4096, k = t % 4096; g_kh2[t] = __float2half_rn(kc2[k * 64 + n]); continue; }
        t -= R2;
        if (t < R3) { int n = t / 4096, k = t % 4096; g_kh3[t] = __float2half_rn(kc3[k * 64 + n]); continue; }
        t -= R3;
        if (t < W1) { int n = t / 96, c = t % 96; g_wh1[t] = __float2half_rn(wd1[c * 64 + n]); continue; }
        t -= W1;
        if (t < W2) { int n = t / 64, c = t % 64; g_wh2[t] = __float2half_rn(wd2[c * 64 + n]); continue; }
        t -= W2;
        { int n = t / 64, c = t % 64; g_wh3[t] = __float2half_rn(wd3[c * 64 + n]); }
    }
}

// -------------------- grid build ----------------------------------------------
__global__ void grid_zero_kernel()
{
    int i = blockIdx.x * blockDim.x + threadIdx.x;
    if (i < 2 * GD3) g_gcnt[i] = 0;
}

__global__ void grid_count_kernel(const float* __restrict__ box, const float* __restrict__ mask)
{
    int i = blockIdx.x * blockDim.x + threadIdx.x;
    if (i < NF)
        atomicAdd(&g_gcnt[cell_id(g_p1[i * 3], g_p1[i * 3 + 1], g_p1[i * 3 + 2])], 1);
    if (i < NB && mask[i] > 0.f)
        atomicAdd(&g_gcnt[GD3 + cell_id(box[i * 3], box[i * 3 + 1], box[i * 3 + 2])], 1);
}

__global__ void grid_scan_kernel()
{
    __shared__ int a[1024];
    int t = threadIdx.x;
    for (int part = 0; part < 2; part++) {
        int cnt = (t < GD3) ? g_gcnt[part * GD3 + t] : 0;
        a[t] = cnt;
        __syncthreads();
        for (int d = 1; d < 1024; d <<= 1) {
            int v = (t >= d) ? a[t - d] : 0;
            __syncthreads();
            a[t] += v;
            __syncthreads();
        }
        if (t < GD3) {
            g_gstart[part * (GD3 + 1) + t + 1] = a[t];
            g_gfill[part * GD3 + t] = a[t] - cnt;
        }
        if (t == 0) g_gstart[part * (GD3 + 1)] = 0;
        __syncthreads();
    }
}

__global__ void grid_fill_kernel(const float* __restrict__ box, const float* __restrict__ mask)
{
    int i = blockIdx.x * blockDim.x + threadIdx.x;
    if (i < NF) {
        int c = cell_id(g_p1[i * 3], g_p1[i * 3 + 1], g_p1[i * 3 + 2]);
        int p = atomicAdd(&g_gfill[c], 1);
        g_gsortF[p] = i;
    }
    if (i < NB && mask[i] > 0.f) {
        int c = cell_id(box[i * 3], box[i * 3 + 1], box[i * 3 + 2]);
        int p = atomicAdd(&g_gfill[GD3 + c], 1);
        g_gsortB[p] = i;
    }
}

// -------------------- kernel 2: grid neighbor build ---------------------------
__global__ void nbr_grid_kernel(const float* __restrict__ pts, int part, int self_exclude,
                                int* __restrict__ idx_out, int* __restrict__ cb_out,
                                float* __restrict__ w8_out, int* __restrict__ cnt_out)
{
    int n = blockIdx.x, tid = threadIdx.x;
    __shared__ float sd2[512];
    __shared__ int   sidx[512];
    __shared__ int   scnt;
    __shared__ int   cst[27];
    __shared__ int   ccum[28];

    float qx = g_p1[n * 3], qy = g_p1[n * 3 + 1], qz = g_p1[n * 3 + 2];
    if (tid == 0) scnt = 0;
    if (tid < 27) {
        int cx = min(max((int)floorf((qx - GORG) * GINV), 0), GD - 1);
        int cy = min(max((int)floorf((qy - GORG) * GINV), 0), GD - 1);
        int cz = min(max((int)floorf((qz - GORG) * GINV), 0), GD - 1);
        int nx = cx + tid / 9 - 1;
        int ny = cy + (tid / 3) % 3 - 1;
        int nz = cz + tid % 3 - 1;
        int st = 0, len = 0;
        if (nx >= 0 && nx < GD && ny >= 0 && ny < GD && nz >= 0 && nz < GD) {
            int c = (nx * GD + ny) * GD + nz;
            st = g_gstart[part * (GD3 + 1) + c];
            len = g_gstart[part * (GD3 + 1) + c + 1] - st;
        }
        cst[tid] = st;
        ccum[tid + 1] = len;
    }
    __syncthreads();
    if (tid == 0) {
        ccum[0] = 0;
        for (int k = 1; k <= 27; k++) ccum[k] += ccum[k - 1];
    }
    __syncthreads();
    int T = ccum[27];
    const int* sorted = part ? g_gsortB : g_gsortF;

    for (int t = tid; t < T; t += blockDim.x) {
        int seg = 0;
        while (t >= ccum[seg + 1]) seg++;
        int j = sorted[cst[seg] + t - ccum[seg]];
        if (self_exclude && j == n) continue;
        float dx = pts[j * 3] - qx, dy = pts[j * 3 + 1] - qy, dz = pts[j * 3 + 2] - qz;
        float d2 = (dx * dx + dy * dy) + dz * dz;
        if (d2 < 9.0f) {
            int p = atomicAdd(&scnt, 1);
            if (p < 512) { sd2[p] = d2; sidx[p] = j; }
        }
    }
    __syncthreads();
    int cnt = min(scnt, 512);

    if (cnt > KNB) {
        int P = 1;
        while (P < cnt) P <<= 1;
        for (int i = cnt + tid; i < P; i += blockDim.x) { sd2[i] = 3.0e38f; sidx[i] = 0x7fffffff; }
        __syncthreads();
        for (int k = 2; k <= P; k <<= 1) {
            for (int j2 = k >> 1; j2 > 0; j2 >>= 1) {
                for (int i = tid; i < P; i += blockDim.x) {
                    int ixj = i ^ j2;
                    if (ixj > i) {
                        float a = sd2[i], b = sd2[ixj];
                        int ia = sidx[i], ib = sidx[ixj];
                        bool agtb = (a > b) || ((a == b) && (ia > ib));
                        bool up = ((i & k) == 0);
                        if (agtb == up) { sd2[i] = b; sd2[ixj] = a; sidx[i] = ib; sidx[ixj] = ia; }
                    }
                }
                __syncthreads();
            }
        }
        cnt = KNB;
    }

    if (tid == 0) cnt_out[n] = cnt;
    if (tid < cnt) {
        int j = sidx[tid];
        float dx = pts[j * 3] - qx, dy = pts[j * 3 + 1] - qy, dz = pts[j * 3 + 2] - qz;
        float w8[8];
        int cb;
        edge_weights(dx, dy, dz, w8, &cb);
        int e = n * KNB + tid;
        idx_out[e] = j;
        cb_out[e] = cb;
#pragma unroll
        for (int r = 0; r < 8; r++) w8_out[e * 8 + r] = w8[r];
    }
}

// -------------------- kernel 3: phase-2 (cf + co + df -> out0), CSR gather ----
__global__ void __launch_bounds__(128) phase2_kernel(
    const float* __restrict__ box_feats,
    const float* __restrict__ k0f, const float* __restrict__ b0f,
    const float* __restrict__ k0o, const float* __restrict__ b0o,
    const float* __restrict__ wdf, const float* __restrict__ bdf)
{
    int n = blockIdx.x, tid = threadIdx.x;
    __shared__ float  F[64 * 12];
    __shared__ float  bfv[64];
    __shared__ float2 entF[512];
    __shared__ float2 entB[512];
    __shared__ int scF[64], scB[64];
    __shared__ int startF[65], startB[65];
    __shared__ int fillF[64], fillB[64];
    __shared__ int ejF[64], ecbF[64];
    __shared__ int ejB[64], ecbB[64];
    __shared__ float ewF[512], ewB[512];
    __shared__ float cF[576];
    __shared__ float cB[64];

    int cntF = g_cntF[n];
    int cntB = g_cntB[n];

    if (tid < 64) { scF[tid] = 0; scB[tid] = 0; }
    if (tid < cntF) { ejF[tid] = g_idxF[n * KNB + tid]; ecbF[tid] = g_cbF[n * KNB + tid]; }
    {
        int t = tid - 64;
        if (t >= 0 && t < cntB) { ejB[t] = g_idxB[n * KNB + t]; ecbB[t] = g_cbB[n * KNB + t]; }
    }
    for (int i = tid; i < cntF * 8; i += 128) ewF[i] = g_w8F[n * KNB * 8 + i];
    for (int i = tid; i < cntB * 8; i += 128) ewB[i] = g_w8B[n * KNB * 8 + i];
    __syncthreads();

    if (tid < cntF) {
        int cb = ecbF[tid];
#pragma unroll
        for (int r = 0; r < 8; r++) atomicAdd(&scF[corner_cell(cb, r)], 1);
    } else if (tid >= 64 && tid - 64 < cntB) {
        int cb = ecbB[tid - 64];
#pragma unroll
        for (int r = 0; r < 8; r++) atomicAdd(&scB[corner_cell(cb, r)], 1);
    }
    __syncthreads();
    for (int d = 1; d < 64; d <<= 1) {
        int v = 0;
        if (tid < 64) { if (tid >= d) v = scF[tid - d]; }
        else { int t = tid - 64; if (t >= d) v = scB[t - d]; }
        __syncthreads();
        if (tid < 64) { if (tid >= d) scF[tid] += v; }
        else { int t = tid - 64; if (t >= d) scB[t] += v; }
        __syncthreads();
    }
    if (tid < 64) {
        startF[tid + 1] = scF[tid];
        fillF[tid] = (tid == 0) ? 0 : scF[tid - 1];
        if (tid == 0) startF[0] = 0;
    } else {
        int t = tid - 64;
        startB[t + 1] = scB[t];
        fillB[t] = (t == 0) ? 0 : scB[t - 1];
        if (t == 0) startB[0] = 0;
    }
    __syncthreads();
    if (tid < cntF) {
        int cb = ecbF[tid];
#pragma unroll
        for (int r = 0; r < 8; r++) {
            int l = corner_cell(cb, r);
            int pos = atomicAdd(&fillF[l], 1);
            entF[pos] = make_float2(ewF[tid * 8 + r], __int_as_float(tid));
        }
    } else if (tid >= 64 && tid - 64 < cntB) {
        int e = tid - 64;
        int cb = ecbB[e];
#pragma unroll
        for (int r = 0; r < 8; r++) {
            int l = corner_cell(cb, r);
            int pos = atomicAdd(&fillB[l], 1);
            entB[pos] = make_float2(ewB[e * 8 + r], __int_as_float(e));
        }
    }
    for (int i = tid; i < cntF * 9; i += 128) {
        int e = i / 9, c = i % 9;
        F[e * 12 + c] = g_ff[ejF[e] * 9 + c];
    }
    for (int i = tid; i < cntB; i += 128) bfv[i] = box_feats[ejB[i]];
    __syncthreads();

    if (tid < 64) {
        int l = tid;
        float acc[9];
#pragma unroll
        for (int c = 0; c < 9; c++) acc[c] = 0.f;
        for (int k = startF[l]; k < startF[l + 1]; k++) {
            float2 we = entF[k];
            float w = we.x;
            int e = __float_as_int(we.y);
#pragma unroll
            for (int c = 0; c < 9; c++) acc[c] += w * F[e * 12 + c];
        }
#pragma unroll
        for (int c = 0; c < 9; c++) cF[l * 9 + c] = acc[c];
        float ab = 0.f;
        for (int k = startB[l]; k < startB[l + 1]; k++) {
            float2 we = entB[k];
            ab += we.x * bfv[__float_as_int(we.y)];
        }
        cB[l] = ab;
    }
    __syncthreads();

    if (tid < 96) {
        int s = tid / 32, o = tid % 32;
        float co = b0o[o];
        for (int l = 0; l < 64; l++) co += cB[l] * k0o[l * 32 + o];
        float cf = b0f[o];
        for (int l = 0; l < 64; l++) {
#pragma unroll
            for (int c = 0; c < 3; c++) cf += cF[l * 9 + s * 3 + c] * k0f[(l * 3 + c) * 32 + o];
        }
        float df = bdf[o];
#pragma unroll
        for (int c = 0; c < 3; c++) df += g_ff[n * 9 + s * 3 + c] * wdf[c * 32 + o];
        int base = n * 288 + s * 96;
        g_out0[base + o]      = co;
        g_out0[base + 32 + o] = cf;
        g_out0[base + 64 + o] = df;
        g_out0h[base + o]      = __float2half_rn(fmaxf(co, 0.f));
        g_out0h[base + 32 + o] = __float2half_rn(fmaxf(cf, 0.f));
        g_out0h[base + 64 + o] = __float2half_rn(fmaxf(df, 0.f));
    }
}

// -------------------- kernel 4: warp-per-cell CSR gather scatter (half2) ------
// prevh: 3000 rows of (3*C) RELU'D half features. Writes Ah (9000 x 64C) half.
// H kept as half2 in smem: halves LDS traffic and smem footprint.
template <int C>
__global__ void __launch_bounds__(256) scatter_warp_kernel(
    const __half* __restrict__ prevh, __half* __restrict__ Aout)
{
    constexpr int SC  = 3 * C;             // 288 or 192
    constexpr int H2N = SC / 2;            // half2 per row: 144 or 96
    constexpr int PF2 = (H2N + 31) / 32;   // 5 or 3
    int n = blockIdx.x;
    int tid = threadIdx.x, lane = tid & 31, wid = tid >> 5;

    extern __shared__ __half2 H2[];        // [64][H2N]
    __shared__ float2 ent[512];
    __shared__ int   scc[64];
    __shared__ int   cellStart[65];
    __shared__ int   fillPos[64];
    __shared__ int   ej[64];
    __shared__ int   ecb[64];
    __shared__ float ew[512];

    int cnt = g_cntF[n];
    if (tid < 64) scc[tid] = 0;
    if (tid < cnt) { ej[tid] = g_idxF[n * KNB + tid]; ecb[tid] = g_cbF[n * KNB + tid]; }
    for (int i = tid; i < cnt * 8; i += 256) ew[i] = g_w8F[n * KNB * 8 + i];
    __syncthreads();

    if (tid < cnt) {
        int cb = ecb[tid];
#pragma unroll
        for (int r = 0; r < 8; r++) atomicAdd(&scc[corner_cell(cb, r)], 1);
    }
    __syncthreads();
    for (int d = 1; d < 64; d <<= 1) {
        int v = 0;
        if (tid < 64 && tid >= d) v = scc[tid - d];
        __syncthreads();
        if (tid < 64 && tid >= d) scc[tid] += v;
        __syncthreads();
    }
    if (tid < 64) {
        cellStart[tid + 1] = scc[tid];
        fillPos[tid] = (tid == 0) ? 0 : scc[tid - 1];
        if (tid == 0) cellStart[0] = 0;
    }
    __syncthreads();
    if (tid < cnt) {
        int cb = ecb[tid];
#pragma unroll
        for (int r = 0; r < 8; r++) {
            int l = corner_cell(cb, r);
            int pos = atomicAdd(&fillPos[l], 1);
            ent[pos] = make_float2(ew[tid * 8 + r], __int_as_float(tid));
        }
    }
    // raw 16B copy of relu'd half rows
    for (int i = tid; i < cnt * (SC / 8); i += 256) {
        int e = i / (SC / 8), q = i % (SC / 8);
        *(uint4*)&H2[e * H2N + q * 4] = *(const uint4*)(prevh + (size_t)ej[e] * SC + q * 8);
    }
    __syncthreads();

    for (int l = wid; l < 64; l += 8) {
        float2 acc[PF2];
#pragma unroll
        for (int i = 0; i < PF2; i++) acc[i] = make_float2(0.f, 0.f);
        int k1 = cellStart[l + 1];
        for (int k = cellStart[l]; k < k1; k++) {
            float2 we = ent[k];
            float w = we.x;
            const __half2* hr = &H2[__float_as_int(we.y) * H2N];
#pragma unroll
            for (int i = 0; i < PF2; i++) {
                int j2 = i * 32 + lane;
                if ((H2N % 32 == 0) || j2 < H2N) {
                    float2 f = __half22float2(hr[j2]);
                    acc[i].x += w * f.x;
                    acc[i].y += w * f.y;
                }
            }
        }
#pragma unroll
        for (int i = 0; i < PF2; i++) {
            int j2 = i * 32 + lane;
            if ((H2N % 32 == 0) || j2 < H2N) {
                int ch = 2 * j2;
                int s = ch / C, c = ch - s * C;
                __half2 hv = __floats2half2_rn(acc[i].x, acc[i].y);
                *(__half2*)&Aout[(size_t)(n * 3 + s) * (64 * C) + l * C + c] = hv;
            }
        }
    }
}

// -------------------- kernel 5: cp.async pipelined FP16 GEMM ------------------
#define PIPE 3
#define HA_ST 40                      // half stride per A row
#define A_STAGE (32 * HA_ST)          // halfs
#define B_STAGE (64 * HA_ST)          // halfs

__global__ void __launch_bounds__(128) gemm_fp16_async(
    const __half* __restrict__ Ah, const __half* __restrict__ BhT,
    const __half* __restrict__ prevh, const __half* __restrict__ wdhT,
    const float* __restrict__ prevf,
    const float* __restrict__ bc, const float* __restrict__ bd,
    float* __restrict__ Out, __half* __restrict__ Outh,
    int M, int K, int C, int res)
{
    __shared__ __half sA[PIPE * A_STAGE];
    __shared__ __half sB[PIPE * B_STAGE];

    int tid = threadIdx.x, lane = tid & 31, warp = tid >> 5;
    int wm = warp >> 1, wn = warp & 1;
    int g = lane >> 2, tg = lane & 3;
    int rowBase = blockIdx.x * 32;
    int stages0 = K / 32;
    int S = stages0 + C / 32;

    uint32_t sAu = (uint32_t)__cvta_generic_to_shared(sA);
    uint32_t sBu = (uint32_t)__cvta_generic_to_shared(sB);

    float acc[4][4];
#pragma unroll
    for (int j = 0; j < 4; j++)
#pragma unroll
        for (int q = 0; q < 4; q++) acc[j][q] = 0.f;

    auto issue = [&](int s) {
        int b = s % PIPE;
        bool seg = (s >= stages0);
        const __half* Ag = seg ? prevh : Ah;
        const __half* Bg = seg ? wdhT : BhT;
        int Ks = seg ? C : K;
        int k0 = (seg ? s - stages0 : s) * 32;
        {
            int r = tid >> 2, sg = tid & 3;
            int rg = min(rowBase + r, M - 1);
            cp16(sAu + (uint32_t)(b * A_STAGE + r * HA_ST + sg * 8) * 2,
                 Ag + (size_t)rg * Ks + k0 + sg * 8);
        }
#pragma unroll
        for (int q = 0; q < 2; q++) {
            int f = tid + q * 128;
            int nr = f >> 2, sg = f & 3;
            cp16(sBu + (uint32_t)(b * B_STAGE + nr * HA_ST + sg * 8) * 2,
                 Bg + (size_t)nr * Ks + k0 + sg * 8);
        }
        asm volatile("cp.async.commit_group;" ::: "memory");
    };

    issue(0);
    issue(1);
    for (int s = 0; s < S; s++) {
        if (s + 1 < S) asm volatile("cp.async.wait_group 1;" ::: "memory");
        else           asm volatile("cp.async.wait_group 0;" ::: "memory");
        __syncthreads();
        if (s + 2 < S) issue(s + 2);

        int b = s % PIPE;
        const __half* Ab = sA + b * A_STAGE;
        const __half* Bb = sB + b * B_STAGE;
#pragma unroll
        for (int k16 = 0; k16 < 32; k16 += 16) {
            uint32_t ua0 = *(const uint32_t*)&Ab[(wm * 16 + g) * HA_ST + k16 + 2 * tg];
            uint32_t ua1 = *(const uint32_t*)&Ab[(wm * 16 + g + 8) * HA_ST + k16 + 2 * tg];
            uint32_t ua2 = *(const uint32_t*)&Ab[(wm * 16 + g) * HA_ST + k16 + 2 * tg + 8];
            uint32_t ua3 = *(const uint32_t*)&Ab[(wm * 16 + g + 8) * HA_ST + k16 + 2 * tg + 8];
#pragma unroll
            for (int j = 0; j < 4; j++) {
                int n0 = wn * 32 + j * 8;
                uint32_t ub0 = *(const uint32_t*)&Bb[(n0 + g) * HA_ST + k16 + 2 * tg];
                uint32_t ub1 = *(const uint32_t*)&Bb[(n0 + g) * HA_ST + k16 + 2 * tg + 8];
                asm volatile(
                    "mma.sync.aligned.m16n8k16.row.col.f32.f16.f16.f32 "
                    "{%0,%1,%2,%3}, {%4,%5,%6,%7}, {%8,%9}, {%0,%1,%2,%3};\n"
                    : "+f"(acc[j][0]), "+f"(acc[j][1]),
                      "+f"(acc[j][2]), "+f"(acc[j][3])
                    : "r"(ua0), "r"(ua1), "r"(ua2), "r"(ua3),
                      "r"(ub0), "r"(ub1));
            }
        }
        __syncthreads();
    }

#pragma unroll
    for (int j = 0; j < 4; j++) {
        int col = wn * 32 + j * 8 + tg * 2;
#pragma unroll
        for (int q = 0; q < 4; q++) {
            int row = rowBase + wm * 16 + g + ((q >= 2) ? 8 : 0);
            int c = col + (q & 1);
            if (row < M) {
                float v = acc[j][q] + bc[c] + bd[c];
                if (res) v += prevf[(size_t)row * C + c];
                Out[(size_t)row * 64 + c] = v;
                Outh[(size_t)row * 64 + c] = __float2half_rn(fmaxf(v, 0.f));
            }
        }
    }
}

// -------------------- kernel 6: fused layer-4 + final outputs -----------------
// Per point: build cellacc via CSR, contract against kc4 (smem) + dense wd4,
// reduce 9 scalars, write p_c, v_c, m_matrix, state_feats directly.
__global__ void __launch_bounds__(256) out4_fused_kernel(
    const __half* __restrict__ prevh,   // pout3h (relu'd)
    const float* __restrict__ kc4,       // [4096][3]
    const float* __restrict__ wd4,       // [64][3]
    const float* __restrict__ bc, const float* __restrict__ bd,
    const float* __restrict__ p0, const float* __restrict__ v0e,
    float* __restrict__ outp)
{
    constexpr int C = 64, SC = 192, H2N = 96;
    int n = blockIdx.x;
    int tid = threadIdx.x, lane = tid & 31, wid = tid >> 5;

    extern __shared__ char dynsm[];
    float*   K4 = (float*)dynsm;                        // 12288 floats = 48KB
    __half2* H2 = (__half2*)(dynsm + 49152);            // 64*96 half2 = 24KB
    __shared__ float2 ent[512];
    __shared__ int   scc[64];
    __shared__ int   cellStart[65];
    __shared__ int   fillPos[64];
    __shared__ int   ej[64];
    __shared__ int   ecb[64];
    __shared__ float ew[512];
    __shared__ float racc[9];

    // stage kc4 into smem
    for (int i = tid; i < 3072; i += 256)
        *(float4*)&K4[i * 4] = *(const float4*)(kc4 + i * 4);
    if (tid < 9) racc[tid] = 0.f;

    int cnt = g_cntF[n];
    if (tid < 64) scc[tid] = 0;
    if (tid < cnt) { ej[tid] = g_idxF[n * KNB + tid]; ecb[tid] = g_cbF[n * KNB + tid]; }
    for (int i = tid; i < cnt * 8; i += 256) ew[i] = g_w8F[n * KNB * 8 + i];
    __syncthreads();

    if (tid < cnt) {
        int cb = ecb[tid];
#pragma unroll
        for (int r = 0; r < 8; r++) atomicAdd(&scc[corner_cell(cb, r)], 1);
    }
    __syncthreads();
    for (int d = 1; d < 64; d <<= 1) {
        int v = 0;
        if (tid < 64 && tid >= d) v = scc[tid - d];
        __syncthreads();
        if (tid < 64 && tid >= d) scc[tid] += v;
        __syncthreads();
    }
    if (tid < 64) {
        cellStart[tid + 1] = scc[tid];
        fillPos[tid] = (tid == 0) ? 0 : scc[tid - 1];
        if (tid == 0) cellStart[0] = 0;
    }
    __syncthreads();
    if (tid < cnt) {
        int cb = ecb[tid];
#pragma unroll
        for (int r = 0; r < 8; r++) {
            int l = corner_cell(cb, r);
            int pos = atomicAdd(&fillPos[l], 1);
            ent[pos] = make_float2(ew[tid * 8 + r], __int_as_float(tid));
        }
    }
    for (int i = tid; i < cnt * (SC / 8); i += 256) {
        int e = i / (SC / 8), q = i % (SC / 8);
        *(uint4*)&H2[e * H2N + q * 4] = *(const uint4*)(prevh + (size_t)ej[e] * SC + q * 8);
    }
    __syncthreads();

    // lane owns channel pair c0=2*lane (same for all s); i index == s.
    float res[3][3];
#pragma unroll
    for (int s = 0; s < 3; s++)
#pragma unroll
        for (int o = 0; o < 3; o++) res[s][o] = 0.f;

    int c0 = 2 * lane;
    for (int l = wid; l < 64; l += 8) {
        float2 acc[3];
#pragma unroll
        for (int i = 0; i < 3; i++) acc[i] = make_float2(0.f, 0.f);
        int k1 = cellStart[l + 1];
        for (int k = cellStart[l]; k < k1; k++) {
            float2 we = ent[k];
            float w = we.x;
            const __half2* hr = &H2[__float_as_int(we.y) * H2N];
#pragma unroll
            for (int i = 0; i < 3; i++) {
                float2 f = __half22float2(hr[i * 32 + lane]);
                acc[i].x += w * f.x;
                acc[i].y += w * f.y;
            }
        }
        const float* kx = &K4[(l * 64 + c0) * 3];
        const float* ky = &K4[(l * 64 + c0 + 1) * 3];
#pragma unroll
        for (int i = 0; i < 3; i++)
#pragma unroll
            for (int o = 0; o < 3; o++)
                res[i][o] += acc[i].x * kx[o] + acc[i].y * ky[o];
    }
    // dense branch (warp 0 only): prevh already relu'd
    if (wid == 0) {
#pragma unroll
        for (int s = 0; s < 3; s++) {
            float2 f = __half22float2(*(const __half2*)&prevh[(size_t)(n * 3 + s) * 64 + c0]);
#pragma unroll
            for (int o = 0; o < 3; o++)
                res[s][o] += f.x * wd4[c0 * 3 + o] + f.y * wd4[(c0 + 1) * 3 + o];
        }
    }
    // reduce within warp, then across warps via smem atomics
#pragma unroll
    for (int s = 0; s < 3; s++)
#pragma unroll
        for (int o = 0; o < 3; o++) {
            float v = res[s][o];
#pragma unroll
            for (int off = 16; off > 0; off >>= 1)
                v += __shfl_down_sync(0xffffffffu, v, off);
            if (lane == 0) atomicAdd(&racc[s * 3 + o], v);
        }
    __syncthreads();

    if (tid < 3) {
        int j = tid;
        float bias = bc[j] + bd[j];
        float o0 = racc[j] + bias;             // s=0
        float corr = o0 * 0.25f * (1.f / 16.f);
        float pc = g_p1[n * 3 + j] + corr;
        outp[n * 3 + j] = pc;
        outp[9000 + n * 3 + j] = (pc - p0[n * 3 + j]) / 0.1f;
        outp[18000 + n * 6 + j]     = (racc[3 + j] + bias) * 0.25f;   // s=1
        outp[18000 + n * 6 + 3 + j] = (racc[6 + j] + bias) * 0.25f;   // s=2
        outp[36000 + n * 3 + j] = v0e[n * 3 + j];
    }
}

// -------------------- launch --------------------------------------------------
template <typename T>
static T* sym_addr(const void* sym)
{
    void* p = nullptr;
    cudaGetSymbolAddress(&p, sym);
    return (T*)p;
}

extern "C" void kernel_launch(void* const* d_in, const int* in_sizes, int n_in,
                              void* d_out, int out_size)
{
    (void)n_in; (void)out_size;
    const float* v0e       = (const float*)d_in[1];
    const float* p0        = (const float*)d_in[2];
    const float* v0        = (const float*)d_in[3];
    const float* a         = (const float*)d_in[4];
    const float* other     = (const float*)d_in[5];
    const float* box       = (const float*)d_in[6];
    const float* box_feats = (const float*)d_in[7];
    const float* box_mask  = (const float*)d_in[9];
    const float* k0f = (const float*)d_in[10];
    const float* b0f = (const float*)d_in[11];
    const float* k0o = (const float*)d_in[12];
    const float* b0o = (const float*)d_in[13];
    const float* wdf = (const float*)d_in[14];
    const float* bdf = (const float*)d_in[15];

    // Resolve deep-layer weights 16..31 BY SIZE (robust to metadata ordering).
    const float* kcA[5] = {0, 0, 0, 0, 0};
    const float* wdA[5] = {0, 0, 0, 0, 0};
    const float* b64[6] = {0, 0, 0, 0, 0, 0};
    const float* b3[2]  = {0, 0};
    int n262 = 0, n4096 = 0, nb64 = 0, nb3 = 0;
    for (int i = 16; i < 32; i++) {
        const float* p = (const float*)d_in[i];
        switch (in_sizes[i]) {
            case 393216: kcA[1] = p; break;
            case 262144: if (n262++ == 0) kcA[2] = p; else kcA[3] = p; break;
            case 12288:  kcA[4] = p; break;
            case 6144:   wdA[1] = p; break;
            case 4096:   if (n4096++ == 0) wdA[2] = p; else wdA[3] = p; break;
            case 192:    wdA[4] = p; break;
            case 64:     if (nb64 < 6) b64[nb64++] = p; break;
            case 3:      if (nb3 < 2) b3[nb3++] = p; break;
            default: break;
        }
    }
    const float* bc1 = b64[0]; const float* bd1 = b64[1];
    const float* bc2 = b64[2]; const float* bd2 = b64[3];
    const float* bc3 = b64[4]; const float* bd3 = b64[5];
    const float* bc4 = b3[0];  const float* bd4 = b3[1];

    float* outp = (float*)d_out;

    float*  pp1   = sym_addr<float>(g_p1);
    int*    pidxF = sym_addr<int>(g_idxF);
    int*    pcbF  = sym_addr<int>(g_cbF);
    float*  pw8F  = sym_addr<float>(g_w8F);
    int*    pcntF = sym_addr<int>(g_cntF);
    int*    pidxB = sym_addr<int>(g_idxB);
    int*    pcbB  = sym_addr<int>(g_cbB);
    float*  pw8B  = sym_addr<float>(g_w8B);
    int*    pcntB = sym_addr<int>(g_cntB);
    float*  pout0  = sym_addr<float>(g_out0);
    __half* pout0h = sym_addr<__half>(g_out0h);
    float*  pout1  = sym_addr<float>(g_out1);
    __half* pout1h = sym_addr<__half>(g_out1h);
    float*  pout2  = sym_addr<float>(g_out2);
    __half* pout2h = sym_addr<__half>(g_out2h);
    float*  pout3  = sym_addr<float>(g_out3);
    __half* pout3h = sym_addr<__half>(g_out3h);
    __half* pAh   = sym_addr<__half>(g_Ah);
    __half* pkh1  = sym_addr<__half>(g_kh1);
    __half* pkh2  = sym_addr<__half>(g_kh2);
    __half* pkh3  = sym_addr<__half>(g_kh3);
    __half* pwh1  = sym_addr<__half>(g_wh1);
    __half* pwh2  = sym_addr<__half>(g_wh2);
    __half* pwh3  = sym_addr<__half>(g_wh3);

    const int smem96 = 64 * 144 * (int)sizeof(__half2);   // 36864
    const int smem64 = 64 * 96  * (int)sizeof(__half2);   // 24576
    const int smemO4 = 49152 + 24576;                      // 73728
    cudaFuncSetAttribute(scatter_warp_kernel<96>, cudaFuncAttributeMaxDynamicSharedMemorySize, smem96);
    cudaFuncSetAttribute(scatter_warp_kernel<64>, cudaFuncAttributeMaxDynamicSharedMemorySize, smem64);
    cudaFuncSetAttribute(out4_fused_kernel, cudaFuncAttributeMaxDynamicSharedMemorySize, smemO4);

    prep_kernel<<<(NF + 127) / 128, 128>>>(p0, v0, a, other, v0e);
    wconv_kernel<<<592, 256>>>(kcA[1], kcA[2], kcA[3], wdA[1], wdA[2], wdA[3]);

    // grid build (fluid on p1, box with mask)
    grid_zero_kernel<<<(2 * GD3 + 255) / 256, 256>>>();
    grid_count_kernel<<<(NF + 255) / 256, 256>>>(box, box_mask);
    grid_scan_kernel<<<1, 1024>>>();
    grid_fill_kernel<<<(NF + 255) / 256, 256>>>(box, box_mask);

    nbr_grid_kernel<<<NF, 128>>>(pp1, 0, 1, pidxF, pcbF, pw8F, pcntF);
    nbr_grid_kernel<<<NF, 128>>>(box, 1, 0, pidxB, pcbB, pw8B, pcntB);
    phase2_kernel<<<NF, 128>>>(box_feats, k0f, b0f, k0o, b0o, wdf, bdf);

    const int Mrows = NF * 3;  // 9000
    const int gemmGrid = (Mrows + 31) / 32;   // 282 CTAs

    // layer 1: C=96, K=6144, no residual
    scatter_warp_kernel<96><<<NF, 256, smem96>>>(pout0h, pAh);
    gemm_fp16_async<<<gemmGrid, 128>>>(pAh, pkh1, pout0h, pwh1, pout0, bc1, bd1,
                                       pout1, pout1h, Mrows, 6144, 96, 0);

    // layer 2: C=64, K=4096, residual
    scatter_warp_kernel<64><<<NF, 256, smem64>>>(pout1h, pAh);
    gemm_fp16_async<<<gemmGrid, 128>>>(pAh, pkh2, pout1h, pwh2, pout1, bc2, bd2,
                                       pout2, pout2h, Mrows, 4096, 64, 1);

    // layer 3: C=64, K=4096, residual
    scatter_warp_kernel<64><<<NF, 256, smem64>>>(pout2h, pAh);
    gemm_fp16_async<<<gemmGrid, 128>>>(pAh, pkh3, pout2h, pwh3, pout2, bc3, bd3,
                                       pout3, pout3h, Mrows, 4096, 64, 1);

    // layer 4 fused: cellacc -> kc4/wd4 contraction -> final outputs
    out4_fused_kernel<<<NF, 256, smemO4>>>(pout3h, kcA[4], wdA[4], bc4, bd4,
                                           p0, v0e, outp);
}

// round 15
// speedup vs baseline: 2.4772x; 1.0250x over previous
#include <cuda_runtime.h>
#include <cuda_fp16.h>
#include <math.h>
#include <stdint.h>

#define NF 3000
#define NB 1500
#define KNB 64

#define GD 9
#define GD3 729
#define GORG (-3.0f)
#define GINV (1.0f/3.0f)

// -------------------- global scratch (no runtime allocation allowed) ----------
__device__ float g_p1[NF * 3];
__device__ float g_ff[NF * 9];

__device__ int    g_idxF[NF * KNB];
__device__ int    g_cntF[NF];
__device__ float2 g_entF[NF * 512];
__device__ int    g_csF [NF * 65];

__device__ int    g_idxB[NF * KNB];
__device__ int    g_cntB[NF];
__device__ float2 g_entB[NF * 512];
__device__ int    g_csB [NF * 65];

__device__ int g_gcnt[2 * GD3];
__device__ int g_gstart[2 * (GD3 + 1)];
__device__ int g_gfill[2 * GD3];
__device__ int g_gsortF[NF];
__device__ int g_gsortB[NB];

__device__ float  g_out0 [NF * 3 * 96];
__device__ __half g_out0h[NF * 3 * 96];
__device__ float  g_out1 [NF * 3 * 64];
__device__ __half g_out1h[NF * 3 * 64];
__device__ float  g_out2 [NF * 3 * 64];
__device__ __half g_out2h[NF * 3 * 64];
__device__ float  g_out3 [NF * 3 * 64];
__device__ __half g_out3h[NF * 3 * 64];

__device__ __half g_Ah[(size_t)NF * 3 * 64 * 96];   // GEMM input scratch (half)

// transposed fp16 weights [64 out][K]
__device__ __half g_kh1[64 * 6144];
__device__ __half g_kh2[64 * 4096];
__device__ __half g_kh3[64 * 4096];
__device__ __half g_wh1[64 * 96];
__device__ __half g_wh2[64 * 64];
__device__ __half g_wh3[64 * 64];

// -------------------- helpers -------------------------------------------------
__device__ __forceinline__ float sgnf(float v) {
    return (v > 0.f) ? 1.f : ((v < 0.f) ? -1.f : 0.f);
}

__device__ __forceinline__ void cp16(uint32_t dst, const void* src) {
    asm volatile("cp.async.cg.shared.global [%0], [%1], 16;" :: "r"(dst), "l"(src) : "memory");
}

__device__ __forceinline__ int cell_id(float x, float y, float z) {
    int cx = min(max((int)floorf((x - GORG) * GINV), 0), GD - 1);
    int cy = min(max((int)floorf((y - GORG) * GINV), 0), GD - 1);
    int cz = min(max((int)floorf((z - GORG) * GINV), 0), GD - 1);
    return (cx * GD + cy) * GD + cz;
}

// Per-edge weight computation: offset (dx,dy,dz) = p_in[j] - p_out[n]
__device__ void edge_weights(float dx, float dy, float dz, float* w8, int* cbase)
{
    const float inv_r = 1.f / 3.f;     // radius = EXTENT*0.5 = 3.0
    float x = dx * inv_r, y = dy * inv_r, z = dz * inv_r;
    float sq = (x * x + y * y) + z * z;

    float win = 1.f - sq;
    win = win * win * win;
    win = fminf(fmaxf(win, 0.f), 1.f);

    float norm  = sqrtf(fmaxf(sq, 1e-8f));
    float xy_sq = x * x + y * y;
    bool  polar = (1.25f * z * z > xy_sq);
    float s_p = sqrtf(3.f * norm / (norm + fabsf(z) + 1e-8f));
    float s_e = norm / sqrtf(fmaxf(xy_sq, 1e-8f));
    float cx = polar ? x * s_p : x * s_e;
    float cy = polar ? y * s_p : y * s_e;
    float cz = polar ? sgnf(z) * norm : 1.5f * z;

    float nxy = sqrtf(fmaxf(cx * cx + cy * cy, 1e-8f));
    bool  xdom = (fabsf(cy) <= fabsf(cx));
    float sx = (fabsf(cx) > 1e-8f) ? cx : 1.f;
    float sy = (fabsf(cy) > 1e-8f) ? cy : 1.f;
    const float FOPI = 1.27323954473516268615f;  // 4/pi
    float bx1 = sgnf(cx) * nxy;
    float by1 = bx1 * FOPI * atanf(cy / sx);
    float by2 = sgnf(cy) * nxy;
    float bx2 = by2 * FOPI * atanf(cx / sy);
    float bx = xdom ? bx1 : bx2;
    float by = xdom ? by1 : by2;
    if (cx * cx + cy * cy < 1e-8f) { bx = 0.f; by = 0.f; }
    float bz = cz;
    if (sq < 1e-8f) { bx = 0.f; by = 0.f; bz = 0.f; }

    float bb[3] = {bx, by, bz};
    float f[3];
    int   c0[3];
#pragma unroll
    for (int ax = 0; ax < 3; ax++) {
        float co = (bb[ax] * 0.5f + 0.5f) * 3.f;       // (KS-1)=3
        co = fminf(fmaxf(co, 0.f), 3.f);
        int ci = (int)floorf(co);
        ci = min(max(ci, 0), 2);
        c0[ax] = ci;
        f[ax] = co - (float)ci;
    }
    *cbase = (c0[0] * 4 + c0[1]) * 4 + c0[2];
#pragma unroll
    for (int r = 0; r < 8; r++) {
        int i = (r >> 2) & 1, j = (r >> 1) & 1, l = r & 1;
        float w = (i ? f[0] : 1.f - f[0]) * (j ? f[1] : 1.f - f[1]) * (l ? f[2] : 1.f - f[2]);
        w8[r] = w * win;
    }
}

__device__ __forceinline__ int corner_cell(int cb, int r) {
    return cb + ((r >> 2) & 1) * 16 + ((r >> 1) & 1) * 4 + (r & 1);
}

// -------------------- weight convert+transpose + grid zero --------------------
__global__ void wconv_kernel(const float* __restrict__ kc1, const float* __restrict__ kc2,
                             const float* __restrict__ kc3, const float* __restrict__ wd1,
                             const float* __restrict__ wd2, const float* __restrict__ wd3)
{
    const int R1 = 64 * 6144, R2 = 64 * 4096, R3 = 64 * 4096;
    const int W1 = 64 * 96, W2 = 64 * 64;
    int i0 = blockIdx.x * blockDim.x + threadIdx.x;
    if (i0 < 2 * GD3) g_gcnt[i0] = 0;                  // fold grid_zero here
    int total = R1 + R2 + R3 + W1 + W2 + W2;
    for (int i = i0; i < total; i += gridDim.x * blockDim.x) {
        int t = i;
        if (t < R1) { int n = t / 6144, k = t % 6144; g_kh1[t] = __float2half_rn(kc1[k * 64 + n]); continue; }
        t -= R1;
        if (t < R2) { int n = t / 4096, k = t % 4096; g_kh2[t] = __float2half_rn(kc2[k * 64 + n]); continue; }
        t -= R2;
        if (t < R3) { int n = t / 4096, k = t % 4096; g_kh3[t] = __float2half_rn(kc3[k * 64 + n]); continue; }
        t -= R3;
        if (t < W1) { int n = t / 96, c = t % 96; g_wh1[t] = __float2half_rn(wd1[c * 64 + n]); continue; }
        t -= W1;
        if (t < W2) { int n = t / 64, c = t % 64; g_wh2[t] = __float2half_rn(wd2[c * 64 + n]); continue; }
        t -= W2;
        { int n = t / 64, c = t % 64; g_wh3[t] = __float2half_rn(wd3[c * 64 + n]); }
    }
}

// -------------------- fused prep + grid count ---------------------------------
__global__ void prep_count_kernel(const float* __restrict__ p0, const float* __restrict__ v0,
                                  const float* __restrict__ a, const float* __restrict__ other,
                                  const float* __restrict__ v0e,
                                  const float* __restrict__ box, const float* __restrict__ mask)
{
    int n = blockIdx.x * blockDim.x + threadIdx.x;
    if (n < NF) {
        float p1v[3];
#pragma unroll
        for (int j = 0; j < 3; j++) {
            float v0v = v0[n * 3 + j], av = a[n * 3 + j];
            float v1 = v0v + 0.1f * av;
            float p1 = p0[n * 3 + j] + 0.1f * (v0v + v1) * 0.5f;
            p1v[j] = p1;
            g_p1[n * 3 + j] = p1;
            g_ff[n * 9 + 0 + j] = v1;
            g_ff[n * 9 + 3 + j] = other[n * 3 + j];
            g_ff[n * 9 + 6 + j] = v0e[n * 3 + j];
        }
        atomicAdd(&g_gcnt[cell_id(p1v[0], p1v[1], p1v[2])], 1);
    }
    if (n < NB && mask[n] > 0.f)
        atomicAdd(&g_gcnt[GD3 + cell_id(box[n * 3], box[n * 3 + 1], box[n * 3 + 2])], 1);
}

__global__ void grid_scan_kernel()
{
    __shared__ int a[1024];
    int t = threadIdx.x;
    for (int part = 0; part < 2; part++) {
        int cnt = (t < GD3) ? g_gcnt[part * GD3 + t] : 0;
        a[t] = cnt;
        __syncthreads();
        for (int d = 1; d < 1024; d <<= 1) {
            int v = (t >= d) ? a[t - d] : 0;
            __syncthreads();
            a[t] += v;
            __syncthreads();
        }
        if (t < GD3) {
            g_gstart[part * (GD3 + 1) + t + 1] = a[t];
            g_gfill[part * GD3 + t] = a[t] - cnt;
        }
        if (t == 0) g_gstart[part * (GD3 + 1)] = 0;
        __syncthreads();
    }
}

__global__ void grid_fill_kernel(const float* __restrict__ box, const float* __restrict__ mask)
{
    int i = blockIdx.x * blockDim.x + threadIdx.x;
    if (i < NF) {
        int c = cell_id(g_p1[i * 3], g_p1[i * 3 + 1], g_p1[i * 3 + 2]);
        int p = atomicAdd(&g_gfill[c], 1);
        g_gsortF[p] = i;
    }
    if (i < NB && mask[i] > 0.f) {
        int c = cell_id(box[i * 3], box[i * 3 + 1], box[i * 3 + 2]);
        int p = atomicAdd(&g_gfill[GD3 + c], 1);
        g_gsortB[p] = i;
    }
}

// -------------------- kernel 2: grid neighbor build + CSR ---------------------
__global__ void nbr_grid_kernel(const float* __restrict__ pts, int part, int self_exclude,
                                int* __restrict__ idx_out, int* __restrict__ cnt_out,
                                float2* __restrict__ ent_out, int* __restrict__ cs_out)
{
    int n = blockIdx.x, tid = threadIdx.x;
    __shared__ float sd2[512];
    __shared__ int   sidx[512];
    __shared__ int   scnt;
    __shared__ int   cst[27];
    __shared__ int   ccum[28];
    __shared__ int   scc[64];
    __shared__ int   cellStart[65];
    __shared__ int   fillPos[64];

    float qx = g_p1[n * 3], qy = g_p1[n * 3 + 1], qz = g_p1[n * 3 + 2];
    if (tid == 0) scnt = 0;
    if (tid < 64) scc[tid] = 0;
    if (tid < 27) {
        int cx = min(max((int)floorf((qx - GORG) * GINV), 0), GD - 1);
        int cy = min(max((int)floorf((qy - GORG) * GINV), 0), GD - 1);
        int cz = min(max((int)floorf((qz - GORG) * GINV), 0), GD - 1);
        int nx = cx + tid / 9 - 1;
        int ny = cy + (tid / 3) % 3 - 1;
        int nz = cz + tid % 3 - 1;
        int st = 0, len = 0;
        if (nx >= 0 && nx < GD && ny >= 0 && ny < GD && nz >= 0 && nz < GD) {
            int c = (nx * GD + ny) * GD + nz;
            st = g_gstart[part * (GD3 + 1) + c];
            len = g_gstart[part * (GD3 + 1) + c + 1] - st;
        }
        cst[tid] = st;
        ccum[tid + 1] = len;
    }
    __syncthreads();
    if (tid == 0) {
        ccum[0] = 0;
        for (int k = 1; k <= 27; k++) ccum[k] += ccum[k - 1];
    }
    __syncthreads();
    int T = ccum[27];
    const int* sorted = part ? g_gsortB : g_gsortF;

    for (int t = tid; t < T; t += blockDim.x) {
        int seg = 0;
        while (t >= ccum[seg + 1]) seg++;
        int j = sorted[cst[seg] + t - ccum[seg]];
        if (self_exclude && j == n) continue;
        float dx = pts[j * 3] - qx, dy = pts[j * 3 + 1] - qy, dz = pts[j * 3 + 2] - qz;
        float d2 = (dx * dx + dy * dy) + dz * dz;
        if (d2 < 9.0f) {
            int p = atomicAdd(&scnt, 1);
            if (p < 512) { sd2[p] = d2; sidx[p] = j; }
        }
    }
    __syncthreads();
    int cnt = min(scnt, 512);

    if (cnt > KNB) {
        int P = 1;
        while (P < cnt) P <<= 1;
        for (int i = cnt + tid; i < P; i += blockDim.x) { sd2[i] = 3.0e38f; sidx[i] = 0x7fffffff; }
        __syncthreads();
        for (int k = 2; k <= P; k <<= 1) {
            for (int j2 = k >> 1; j2 > 0; j2 >>= 1) {
                for (int i = tid; i < P; i += blockDim.x) {
                    int ixj = i ^ j2;
                    if (ixj > i) {
                        float a = sd2[i], b = sd2[ixj];
                        int ia = sidx[i], ib = sidx[ixj];
                        bool agtb = (a > b) || ((a == b) && (ia > ib));
                        bool up = ((i & k) == 0);
                        if (agtb == up) { sd2[i] = b; sd2[ixj] = a; sidx[i] = ib; sidx[ixj] = ia; }
                    }
                }
                __syncthreads();
            }
        }
        cnt = KNB;
    }

    // per-edge weights (registers)
    float w8[8];
    int cb = 0;
    if (tid < cnt) {
        int j = sidx[tid];
        float dx = pts[j * 3] - qx, dy = pts[j * 3 + 1] - qy, dz = pts[j * 3 + 2] - qz;
        edge_weights(dx, dy, dz, w8, &cb);
        idx_out[n * KNB + tid] = j;
    }
    if (tid == 0) cnt_out[n] = cnt;

    // CSR build (once per point, stored to global)
    __syncthreads();
    if (tid < cnt) {
#pragma unroll
        for (int r = 0; r < 8; r++) atomicAdd(&scc[corner_cell(cb, r)], 1);
    }
    __syncthreads();
    for (int d = 1; d < 64; d <<= 1) {
        int v = 0;
        if (tid < 64 && tid >= d) v = scc[tid - d];
        __syncthreads();
        if (tid < 64 && tid >= d) scc[tid] += v;
        __syncthreads();
    }
    if (tid < 64) {
        cellStart[tid + 1] = scc[tid];
        fillPos[tid] = (tid == 0) ? 0 : scc[tid - 1];
        if (tid == 0) cellStart[0] = 0;
    }
    __syncthreads();
    if (tid < cnt) {
#pragma unroll
        for (int r = 0; r < 8; r++) {
            int l = corner_cell(cb, r);
            int pos = atomicAdd(&fillPos[l], 1);
            ent_out[n * 512 + pos] = make_float2(w8[r], __int_as_float(tid));
        }
    }
    if (tid < 65) cs_out[n * 65 + tid] = cellStart[tid];
}

// -------------------- kernel 3: phase-2 (cf + co + df -> out0) ----------------
__global__ void __launch_bounds__(128) phase2_kernel(
    const float* __restrict__ box_feats,
    const float* __restrict__ k0f, const float* __restrict__ b0f,
    const float* __restrict__ k0o, const float* __restrict__ b0o,
    const float* __restrict__ wdf, const float* __restrict__ bdf)
{
    int n = blockIdx.x, tid = threadIdx.x;
    __shared__ float  F[64 * 12];
    __shared__ float  bfv[64];
    __shared__ float2 entF[512];
    __shared__ float2 entB[512];
    __shared__ int startF[65], startB[65];
    __shared__ int ejF[64];
    __shared__ float cF[576];
    __shared__ float cB[64];

    int cntF = g_cntF[n];
    int cntB = g_cntB[n];

    if (tid < cntF) ejF[tid] = g_idxF[n * KNB + tid];
    // FIX: full strided loads covering all 65 entries of both start arrays
    for (int i = tid; i < 65; i += 128) startF[i] = g_csF[n * 65 + i];
    for (int i = tid; i < 65; i += 128) startB[i] = g_csB[n * 65 + i];
    __syncthreads();
    int cnt8F = startF[64], cnt8B = startB[64];
    for (int i = tid; i < cnt8F; i += 128) entF[i] = g_entF[n * 512 + i];
    for (int i = tid; i < cnt8B; i += 128) entB[i] = g_entB[n * 512 + i];
    for (int i = tid; i < cntF * 9; i += 128) {
        int e = i / 9, c = i % 9;
        F[e * 12 + c] = g_ff[ejF[e] * 9 + c];
    }
    for (int i = tid; i < cntB; i += 128) bfv[i] = box_feats[g_idxB[n * KNB + i]];
    __syncthreads();

    if (tid < 64) {
        int l = tid;
        float acc[9];
#pragma unroll
        for (int c = 0; c < 9; c++) acc[c] = 0.f;
        for (int k = startF[l]; k < startF[l + 1]; k++) {
            float2 we = entF[k];
            float w = we.x;
            int e = __float_as_int(we.y);
#pragma unroll
            for (int c = 0; c < 9; c++) acc[c] += w * F[e * 12 + c];
        }
#pragma unroll
        for (int c = 0; c < 9; c++) cF[l * 9 + c] = acc[c];
        float ab = 0.f;
        for (int k = startB[l]; k < startB[l + 1]; k++) {
            float2 we = entB[k];
            ab += we.x * bfv[__float_as_int(we.y)];
        }
        cB[l] = ab;
    }
    __syncthreads();

    if (tid < 96) {
        int s = tid / 32, o = tid % 32;
        float co = b0o[o];
        for (int l = 0; l < 64; l++) co += cB[l] * k0o[l * 32 + o];
        float cf = b0f[o];
        for (int l = 0; l < 64; l++) {
#pragma unroll
            for (int c = 0; c < 3; c++) cf += cF[l * 9 + s * 3 + c] * k0f[(l * 3 + c) * 32 + o];
        }
        float df = bdf[o];
#pragma unroll
        for (int c = 0; c < 3; c++) df += g_ff[n * 9 + s * 3 + c] * wdf[c * 32 + o];
        int base = n * 288 + s * 96;
        g_out0[base + o]      = co;
        g_out0[base + 32 + o] = cf;
        g_out0[base + 64 + o] = df;
        g_out0h[base + o]      = __float2half_rn(fmaxf(co, 0.f));
        g_out0h[base + 32 + o] = __float2half_rn(fmaxf(cf, 0.f));
        g_out0h[base + 64 + o] = __float2half_rn(fmaxf(df, 0.f));
    }
}

// -------------------- kernel 4: warp-per-cell CSR gather scatter (half2) ------
template <int C>
__global__ void __launch_bounds__(256) scatter_warp_kernel(
    const __half* __restrict__ prevh, __half* __restrict__ Aout)
{
    constexpr int SC  = 3 * C;             // 288 or 192
    constexpr int H2N = SC / 2;            // half2 per row: 144 or 96
    constexpr int PF2 = (H2N + 31) / 32;   // 5 or 3
    int n = blockIdx.x;
    int tid = threadIdx.x, lane = tid & 31, wid = tid >> 5;

    extern __shared__ __half2 H2[];        // [64][H2N]
    __shared__ float2 ent[512];
    __shared__ int   cellStart[65];
    __shared__ int   ej[64];

    int cnt = g_cntF[n];
    if (tid < cnt) ej[tid] = g_idxF[n * KNB + tid];
    if (tid < 65) cellStart[tid] = g_csF[n * 65 + tid];
    __syncthreads();
    int cnt8 = cellStart[64];
    for (int i = tid; i < cnt8; i += 256) ent[i] = g_entF[n * 512 + i];
    for (int i = tid; i < cnt * (SC / 8); i += 256) {
        int e = i / (SC / 8), q = i % (SC / 8);
        *(uint4*)&H2[e * H2N + q * 4] = *(const uint4*)(prevh + (size_t)ej[e] * SC + q * 8);
    }
    __syncthreads();

    for (int l = wid; l < 64; l += 8) {
        float2 acc[PF2];
#pragma unroll
        for (int i = 0; i < PF2; i++) acc[i] = make_float2(0.f, 0.f);
        int k1 = cellStart[l + 1];
        for (int k = cellStart[l]; k < k1; k++) {
            float2 we = ent[k];
            float w = we.x;
            const __half2* hr = &H2[__float_as_int(we.y) * H2N];
#pragma unroll
            for (int i = 0; i < PF2; i++) {
                int j2 = i * 32 + lane;
                if ((H2N % 32 == 0) || j2 < H2N) {
                    float2 f = __half22float2(hr[j2]);
                    acc[i].x += w * f.x;
                    acc[i].y += w * f.y;
                }
            }
        }
#pragma unroll
        for (int i = 0; i < PF2; i++) {
            int j2 = i * 32 + lane;
            if ((H2N % 32 == 0) || j2 < H2N) {
                int ch = 2 * j2;
                int s = ch / C, c = ch - s * C;
                __half2 hv = __floats2half2_rn(acc[i].x, acc[i].y);
                *(__half2*)&Aout[(size_t)(n * 3 + s) * (64 * C) + l * C + c] = hv;
            }
        }
    }
}

// -------------------- kernel 5: cp.async pipelined FP16 GEMM ------------------
#define PIPE 3
#define HA_ST 40                      // half stride per A row
#define A_STAGE (32 * HA_ST)          // halfs
#define B_STAGE (64 * HA_ST)          // halfs

__global__ void __launch_bounds__(128) gemm_fp16_async(
    const __half* __restrict__ Ah, const __half* __restrict__ BhT,
    const __half* __restrict__ prevh, const __half* __restrict__ wdhT,
    const float* __restrict__ prevf,
    const float* __restrict__ bc, const float* __restrict__ bd,
    float* __restrict__ Out, __half* __restrict__ Outh,
    int M, int K, int C, int res)
{
    __shared__ __half sA[PIPE * A_STAGE];
    __shared__ __half sB[PIPE * B_STAGE];

    int tid = threadIdx.x, lane = tid & 31, warp = tid >> 5;
    int wm = warp >> 1, wn = warp & 1;
    int g = lane >> 2, tg = lane & 3;
    int rowBase = blockIdx.x * 32;
    int stages0 = K / 32;
    int S = stages0 + C / 32;

    uint32_t sAu = (uint32_t)__cvta_generic_to_shared(sA);
    uint32_t sBu = (uint32_t)__cvta_generic_to_shared(sB);

    float acc[4][4];
#pragma unroll
    for (int j = 0; j < 4; j++)
#pragma unroll
        for (int q = 0; q < 4; q++) acc[j][q] = 0.f;

    auto issue = [&](int s) {
        int b = s % PIPE;
        bool seg = (s >= stages0);
        const __half* Ag = seg ? prevh : Ah;
        const __half* Bg = seg ? wdhT : BhT;
        int Ks = seg ? C : K;
        int k0 = (seg ? s - stages0 : s) * 32;
        {
            int r = tid >> 2, sg = tid & 3;
            int rg = min(rowBase + r, M - 1);
            cp16(sAu + (uint32_t)(b * A_STAGE + r * HA_ST + sg * 8) * 2,
                 Ag + (size_t)rg * Ks + k0 + sg * 8);
        }
#pragma unroll
        for (int q = 0; q < 2; q++) {
            int f = tid + q * 128;
            int nr = f >> 2, sg = f & 3;
            cp16(sBu + (uint32_t)(b * B_STAGE + nr * HA_ST + sg * 8) * 2,
                 Bg + (size_t)nr * Ks + k0 + sg * 8);
        }
        asm volatile("cp.async.commit_group;" ::: "memory");
    };

    issue(0);
    issue(1);
    for (int s = 0; s < S; s++) {
        if (s + 1 < S) asm volatile("cp.async.wait_group 1;" ::: "memory");
        else           asm volatile("cp.async.wait_group 0;" ::: "memory");
        __syncthreads();
        if (s + 2 < S) issue(s + 2);

        int b = s % PIPE;
        const __half* Ab = sA + b * A_STAGE;
        const __half* Bb = sB + b * B_STAGE;
#pragma unroll
        for (int k16 = 0; k16 < 32; k16 += 16) {
            uint32_t ua0 = *(const uint32_t*)&Ab[(wm * 16 + g) * HA_ST + k16 + 2 * tg];
            uint32_t ua1 = *(const uint32_t*)&Ab[(wm * 16 + g + 8) * HA_ST + k16 + 2 * tg];
            uint32_t ua2 = *(const uint32_t*)&Ab[(wm * 16 + g) * HA_ST + k16 + 2 * tg + 8];
            uint32_t ua3 = *(const uint32_t*)&Ab[(wm * 16 + g + 8) * HA_ST + k16 + 2 * tg + 8];
#pragma unroll
            for (int j = 0; j < 4; j++) {
                int n0 = wn * 32 + j * 8;
                uint32_t ub0 = *(const uint32_t*)&Bb[(n0 + g) * HA_ST + k16 + 2 * tg];
                uint32_t ub1 = *(const uint32_t*)&Bb[(n0 + g) * HA_ST + k16 + 2 * tg + 8];
                asm volatile(
                    "mma.sync.aligned.m16n8k16.row.col.f32.f16.f16.f32 "
                    "{%0,%1,%2,%3}, {%4,%5,%6,%7}, {%8,%9}, {%0,%1,%2,%3};\n"
                    : "+f"(acc[j][0]), "+f"(acc[j][1]),
                      "+f"(acc[j][2]), "+f"(acc[j][3])
                    : "r"(ua0), "r"(ua1), "r"(ua2), "r"(ua3),
                      "r"(ub0), "r"(ub1));
            }
        }
        __syncthreads();
    }

#pragma unroll
    for (int j = 0; j < 4; j++) {
        int col = wn * 32 + j * 8 + tg * 2;
#pragma unroll
        for (int q = 0; q < 4; q++) {
            int row = rowBase + wm * 16 + g + ((q >= 2) ? 8 : 0);
            int c = col + (q & 1);
            if (row < M) {
                float v = acc[j][q] + bc[c] + bd[c];
                if (res) v += prevf[(size_t)row * C + c];
                Out[(size_t)row * 64 + c] = v;
                Outh[(size_t)row * 64 + c] = __float2half_rn(fmaxf(v, 0.f));
            }
        }
    }
}

// -------------------- kernel 6: fused layer-4 + final outputs -----------------
__global__ void __launch_bounds__(256) out4_fused_kernel(
    const __half* __restrict__ prevh,   // pout3h (relu'd)
    const float* __restrict__ kc4,       // [4096][3]
    const float* __restrict__ wd4,       // [64][3]
    const float* __restrict__ bc, const float* __restrict__ bd,
    const float* __restrict__ p0, const float* __restrict__ v0e,
    float* __restrict__ outp)
{
    constexpr int SC = 192, H2N = 96;
    int n = blockIdx.x;
    int tid = threadIdx.x, lane = tid & 31, wid = tid >> 5;

    extern __shared__ char dynsm[];
    float*   K4 = (float*)dynsm;                        // 12288 floats = 48KB
    __half2* H2 = (__half2*)(dynsm + 49152);            // 64*96 half2 = 24KB
    __shared__ float2 ent[512];
    __shared__ int   cellStart[65];
    __shared__ int   ej[64];
    __shared__ float racc[9];

    // stage kc4 into smem
    for (int i = tid; i < 3072; i += 256)
        *(float4*)&K4[i * 4] = *(const float4*)(kc4 + i * 4);
    if (tid < 9) racc[tid] = 0.f;

    int cnt = g_cntF[n];
    if (tid < cnt) ej[tid] = g_idxF[n * KNB + tid];
    if (tid < 65) cellStart[tid] = g_csF[n * 65 + tid];
    __syncthreads();
    int cnt8 = cellStart[64];
    for (int i = tid; i < cnt8; i += 256) ent[i] = g_entF[n * 512 + i];
    for (int i = tid; i < cnt * (SC / 8); i += 256) {
        int e = i / (SC / 8), q = i % (SC / 8);
        *(uint4*)&H2[e * H2N + q * 4] = *(const uint4*)(prevh + (size_t)ej[e] * SC + q * 8);
    }
    __syncthreads();

    float res[3][3];
#pragma unroll
    for (int s = 0; s < 3; s++)
#pragma unroll
        for (int o = 0; o < 3; o++) res[s][o] = 0.f;

    int c0 = 2 * lane;
    for (int l = wid; l < 64; l += 8) {
        float2 acc[3];
#pragma unroll
        for (int i = 0; i < 3; i++) acc[i] = make_float2(0.f, 0.f);
        int k1 = cellStart[l + 1];
        for (int k = cellStart[l]; k < k1; k++) {
            float2 we = ent[k];
            float w = we.x;
            const __half2* hr = &H2[__float_as_int(we.y) * H2N];
#pragma unroll
            for (int i = 0; i < 3; i++) {
                float2 f = __half22float2(hr[i * 32 + lane]);
                acc[i].x += w * f.x;
                acc[i].y += w * f.y;
            }
        }
        const float* kx = &K4[(l * 64 + c0) * 3];
        const float* ky = &K4[(l * 64 + c0 + 1) * 3];
#pragma unroll
        for (int i = 0; i < 3; i++)
#pragma unroll
            for (int o = 0; o < 3; o++)
                res[i][o] += acc[i].x * kx[o] + acc[i].y * ky[o];
    }
    if (wid == 0) {
#pragma unroll
        for (int s = 0; s < 3; s++) {
            float2 f = __half22float2(*(const __half2*)&prevh[(size_t)(n * 3 + s) * 64 + c0]);
#pragma unroll
            for (int o = 0; o < 3; o++)
                res[s][o] += f.x * wd4[c0 * 3 + o] + f.y * wd4[(c0 + 1) * 3 + o];
        }
    }
#pragma unroll
    for (int s = 0; s < 3; s++)
#pragma unroll
        for (int o = 0; o < 3; o++) {
            float v = res[s][o];
#pragma unroll
            for (int off = 16; off > 0; off >>= 1)
                v += __shfl_down_sync(0xffffffffu, v, off);
            if (lane == 0) atomicAdd(&racc[s * 3 + o], v);
        }
    __syncthreads();

    if (tid < 3) {
        int j = tid;
        float bias = bc[j] + bd[j];
        float o0 = racc[j] + bias;             // s=0
        float corr = o0 * 0.25f * (1.f / 16.f);
        float pc = g_p1[n * 3 + j] + corr;
        outp[n * 3 + j] = pc;
        outp[9000 + n * 3 + j] = (pc - p0[n * 3 + j]) / 0.1f;
        outp[18000 + n * 6 + j]     = (racc[3 + j] + bias) * 0.25f;   // s=1
        outp[18000 + n * 6 + 3 + j] = (racc[6 + j] + bias) * 0.25f;   // s=2
        outp[36000 + n * 3 + j] = v0e[n * 3 + j];
    }
}

// -------------------- launch --------------------------------------------------
template <typename T>
static T* sym_addr(const void* sym)
{
    void* p = nullptr;
    cudaGetSymbolAddress(&p, sym);
    return (T*)p;
}

extern "C" void kernel_launch(void* const* d_in, const int* in_sizes, int n_in,
                              void* d_out, int out_size)
{
    (void)n_in; (void)out_size;
    const float* v0e       = (const float*)d_in[1];
    const float* p0        = (const float*)d_in[2];
    const float* v0        = (const float*)d_in[3];
    const float* a         = (const float*)d_in[4];
    const float* other     = (const float*)d_in[5];
    const float* box       = (const float*)d_in[6];
    const float* box_feats = (const float*)d_in[7];
    const float* box_mask  = (const float*)d_in[9];
    const float* k0f = (const float*)d_in[10];
    const float* b0f = (const float*)d_in[11];
    const float* k0o = (const float*)d_in[12];
    const float* b0o = (const float*)d_in[13];
    const float* wdf = (const float*)d_in[14];
    const float* bdf = (const float*)d_in[15];

    // Resolve deep-layer weights 16..31 BY SIZE (robust to metadata ordering).
    const float* kcA[5] = {0, 0, 0, 0, 0};
    const float* wdA[5] = {0, 0, 0, 0, 0};
    const float* b64[6] = {0, 0, 0, 0, 0, 0};
    const float* b3[2]  = {0, 0};
    int n262 = 0, n4096 = 0, nb64 = 0, nb3 = 0;
    for (int i = 16; i < 32; i++) {
        const float* p = (const float*)d_in[i];
        switch (in_sizes[i]) {
            case 393216: kcA[1] = p; break;
            case 262144: if (n262++ == 0) kcA[2] = p; else kcA[3] = p; break;
            case 12288:  kcA[4] = p; break;
            case 6144:   wdA[1] = p; break;
            case 4096:   if (n4096++ == 0) wdA[2] = p; else wdA[3] = p; break;
            case 192:    wdA[4] = p; break;
            case 64:     if (nb64 < 6) b64[nb64++] = p; break;
            case 3:      if (nb3 < 2) b3[nb3++] = p; break;
            default: break;
        }
    }
    const float* bc1 = b64[0]; const float* bd1 = b64[1];
    const float* bc2 = b64[2]; const float* bd2 = b64[3];
    const float* bc3 = b64[4]; const float* bd3 = b64[5];
    const float* bc4 = b3[0];  const float* bd4 = b3[1];

    float* outp = (float*)d_out;

    float*  pp1   = sym_addr<float>(g_p1);
    int*    pidxF = sym_addr<int>(g_idxF);
    int*    pcntF = sym_addr<int>(g_cntF);
    float2* pentF = sym_addr<float2>(g_entF);
    int*    pcsF  = sym_addr<int>(g_csF);
    int*    pidxB = sym_addr<int>(g_idxB);
    int*    pcntB = sym_addr<int>(g_cntB);
    float2* pentB = sym_addr<float2>(g_entB);
    int*    pcsB  = sym_addr<int>(g_csB);
    float*  pout0  = sym_addr<float>(g_out0);
    __half* pout0h = sym_addr<__half>(g_out0h);
    float*  pout1  = sym_addr<float>(g_out1);
    __half* pout1h = sym_addr<__half>(g_out1h);
    float*  pout2  = sym_addr<float>(g_out2);
    __half* pout2h = sym_addr<__half>(g_out2h);
    float*  pout3  = sym_addr<float>(g_out3);
    __half* pout3h = sym_addr<__half>(g_out3h);
    __half* pAh   = sym_addr<__half>(g_Ah);
    __half* pkh1  = sym_addr<__half>(g_kh1);
    __half* pkh2  = sym_addr<__half>(g_kh2);
    __half* pkh3  = sym_addr<__half>(g_kh3);
    __half* pwh1  = sym_addr<__half>(g_wh1);
    __half* pwh2  = sym_addr<__half>(g_wh2);
    __half* pwh3  = sym_addr<__half>(g_wh3);

    const int smem96 = 64 * 144 * (int)sizeof(__half2);   // 36864
    const int smem64 = 64 * 96  * (int)sizeof(__half2);   // 24576
    const int smemO4 = 49152 + 24576;                      // 73728
    cudaFuncSetAttribute(scatter_warp_kernel<96>, cudaFuncAttributeMaxDynamicSharedMemorySize, smem96);
    cudaFuncSetAttribute(scatter_warp_kernel<64>, cudaFuncAttributeMaxDynamicSharedMemorySize, smem64);
    cudaFuncSetAttribute(out4_fused_kernel, cudaFuncAttributeMaxDynamicSharedMemorySize, smemO4);

    // wconv also zeroes the grid counters; prep_count fuses prep + grid count.
    wconv_kernel<<<592, 256>>>(kcA[1], kcA[2], kcA[3], wdA[1], wdA[2], wdA[3]);
    prep_count_kernel<<<(NF + 255) / 256, 256>>>(p0, v0, a, other, v0e, box, box_mask);
    grid_scan_kernel<<<1, 1024>>>();
    grid_fill_kernel<<<(NF + 255) / 256, 256>>>(box, box_mask);

    nbr_grid_kernel<<<NF, 128>>>(pp1, 0, 1, pidxF, pcntF, pentF, pcsF);
    nbr_grid_kernel<<<NF, 128>>>(box, 1, 0, pidxB, pcntB, pentB, pcsB);
    phase2_kernel<<<NF, 128>>>(box_feats, k0f, b0f, k0o, b0o, wdf, bdf);

    const int Mrows = NF * 3;  // 9000
    const int gemmGrid = (Mrows + 31) / 32;   // 282 CTAs

    // layer 1: C=96, K=6144, no residual
    scatter_warp_kernel<96><<<NF, 256, smem96>>>(pout0h, pAh);
    gemm_fp16_async<<<gemmGrid, 128>>>(pAh, pkh1, pout0h, pwh1, pout0, bc1, bd1,
                                       pout1, pout1h, Mrows, 6144, 96, 0);

    // layer 2: C=64, K=4096, residual
    scatter_warp_kernel<64><<<NF, 256, smem64>>>(pout1h, pAh);
    gemm_fp16_async<<<gemmGrid, 128>>>(pAh, pkh2, pout1h, pwh2, pout1, bc2, bd2,
                                       pout2, pout2h, Mrows, 4096, 64, 1);

    // layer 3: C=64, K=4096, residual
    scatter_warp_kernel<64><<<NF, 256, smem64>>>(pout2h, pAh);
    gemm_fp16_async<<<gemmGrid, 128>>>(pAh, pkh3, pout2h, pwh3, pout2, bc3, bd3,
                                       pout3, pout3h, Mrows, 4096, 64, 1);

    // layer 4 fused: cellacc -> kc4/wd4 contraction -> final outputs
    out4_fused_kernel<<<NF, 256, smemO4>>>(pout3h, kcA[4], wdA[4], bc4, bd4,
                                           p0, v0e, outp);
}